// round 7
// baseline (speedup 1.0000x reference)
#include <cuda_runtime.h>
#include <cuda_bf16.h>
#include <mma.h>
#include <math.h>
#include <stdint.h>

using namespace nvcuda;

#define NB 2
#define CH 256
#define SV 32768L
#define NH 4
#define HD 64
#define SCALE_INV 0.0625f
#define EPS 1e-6f

__device__ __forceinline__ unsigned pack2(float a, float b) {
    __nv_bfloat162 t = __floats2bfloat162_rn(a, b);
    return *reinterpret_cast<unsigned*>(&t);
}

// ---------------- scratch ----------------
__device__ __align__(16) float g_attn   [NB * 256L * SV];   // x + local attn (raw)
__device__ __align__(16) float g_praw   [NB * 256 * 512];
__device__ __align__(16) __nv_bfloat16 g_xnB   [NB * 256L * SV];
__device__ __align__(16) __nv_bfloat16 g_qkvB  [NB * 768L * SV];
__device__ __align__(16) __nv_bfloat16 g_attnB [NB * 256L * SV];   // raw bf16
__device__ __align__(16) __nv_bfloat16 g_ghi   [NB * 256L * SV];
__device__ __align__(16) __nv_bfloat16 g_glo   [NB * 256L * SV];
__device__ __align__(16) __nv_bfloat16 g_pooledB[NB * 256 * 512];
__device__ __align__(16) __nv_bfloat16 g_q2T   [NB * 4L * SV * 64];
__device__ __align__(16) __nv_bfloat16 g_kvT   [NB * 8L * 512 * 64];
__device__ __align__(16) __nv_bfloat16 g_WqkvB [768 * 256];
__device__ __align__(16) __nv_bfloat16 g_Wq2B  [NB * 256 * 256];   // per-batch folded
__device__ __align__(16) __nv_bfloat16 g_WkvB  [512 * 256];
__device__ __align__(16) __nv_bfloat16 g_WprojB[256 * 768];
__device__ float g_qb2  [NB * 256];
__device__ float g_part [NB * 2048 * 2];
__device__ float g_aff  [6 * NB * 256];

// ---------------- cp.async ----------------
__device__ __forceinline__ void cp16(void* dst, const void* src) {
    unsigned d = (unsigned)__cvta_generic_to_shared(dst);
    asm volatile("cp.async.cg.shared.global [%0], [%1], 16;\n" :: "r"(d), "l"(src));
}
#define CP_COMMIT asm volatile("cp.async.commit_group;\n" ::: "memory")
#define CP_WAIT1  asm volatile("cp.async.wait_group 1;\n" ::: "memory")
#define CP_WAIT0  asm volatile("cp.async.wait_group 0;\n" ::: "memory")

// =========================================================================
// reductions / affine / conversions
// =========================================================================
__global__ void reduce1_kernel(const float* __restrict__ buf, long per, float* __restrict__ part) {
    int n = blockIdx.y;
    const float* p = buf + (size_t)n * per;
    float s = 0.f, ss = 0.f;
    for (long i = (long)blockIdx.x * blockDim.x + threadIdx.x; i < per;
         i += (long)gridDim.x * blockDim.x) {
        float v = p[i];
        s += v; ss += v * v;
    }
    for (int o = 16; o; o >>= 1) {
        s  += __shfl_down_sync(0xffffffffu, s, o);
        ss += __shfl_down_sync(0xffffffffu, ss, o);
    }
    __shared__ float sh[64];
    int w = threadIdx.x >> 5;
    if ((threadIdx.x & 31) == 0) { sh[w] = s; sh[32 + w] = ss; }
    __syncthreads();
    if (threadIdx.x < 32) {
        int nw = blockDim.x >> 5;
        s  = (threadIdx.x < nw) ? sh[threadIdx.x]      : 0.f;
        ss = (threadIdx.x < nw) ? sh[32 + threadIdx.x] : 0.f;
        for (int o = 16; o; o >>= 1) {
            s  += __shfl_down_sync(0xffffffffu, s, o);
            ss += __shfl_down_sync(0xffffffffu, ss, o);
        }
        if (threadIdx.x == 0) {
            part[((size_t)n * gridDim.x + blockIdx.x) * 2 + 0] = s;
            part[((size_t)n * gridDim.x + blockIdx.x) * 2 + 1] = ss;
        }
    }
}

// merged reduce2 + make_affine: one block per sample, 256 threads
__global__ void stats2affine_kernel(const float* __restrict__ part, int nb,
                                    const float* __restrict__ w, const float* __restrict__ b,
                                    float* __restrict__ a, float* __restrict__ d,
                                    float inv_cnt) {
    int n = blockIdx.x, tid = threadIdx.x;
    float s = 0.f, ss = 0.f;
    for (int i = tid; i < nb; i += 256) {
        s  += part[((size_t)n * nb + i) * 2 + 0];
        ss += part[((size_t)n * nb + i) * 2 + 1];
    }
    for (int o = 16; o; o >>= 1) {
        s  += __shfl_down_sync(0xffffffffu, s, o);
        ss += __shfl_down_sync(0xffffffffu, ss, o);
    }
    __shared__ float sh[16];
    __shared__ float sm_mean, sm_rstd;
    int wp = tid >> 5;
    if ((tid & 31) == 0) { sh[wp] = s; sh[8 + wp] = ss; }
    __syncthreads();
    if (tid < 32) {
        s  = (tid < 8) ? sh[tid]     : 0.f;
        ss = (tid < 8) ? sh[8 + tid] : 0.f;
        for (int o = 4; o; o >>= 1) {
            s  += __shfl_down_sync(0xffffffffu, s, o);
            ss += __shfl_down_sync(0xffffffffu, ss, o);
        }
        if (tid == 0) {
            float mean = s * inv_cnt;
            float var  = ss * inv_cnt - mean * mean;
            sm_mean = mean;
            sm_rstd = rsqrtf(var + EPS);
        }
    }
    __syncthreads();
    float mean = sm_mean, rstd = sm_rstd;
    a[n * CH + tid] = w[tid] * rstd;
    d[n * CH + tid] = b[tid] - mean * rstd * w[tid];
}

__global__ void convert_x_kernel(const float* __restrict__ x,
                                 const float* __restrict__ a, const float* __restrict__ d,
                                 __nv_bfloat16* __restrict__ out) {
    size_t i4 = (size_t)blockIdx.x * blockDim.x + threadIdx.x;
    int c = (int)((i4 >> 13) & 255);
    int n = (int)(i4 >> 21);
    float aa = a[n * CH + c], dd = d[n * CH + c];
    float4 v = reinterpret_cast<const float4*>(x)[i4];
    uint2 r;
    r.x = pack2(fmaf(aa, v.x, dd), fmaf(aa, v.y, dd));
    r.y = pack2(fmaf(aa, v.z, dd), fmaf(aa, v.w, dd));
    reinterpret_cast<uint2*>(out)[i4] = r;
}

// fold anorm affine into q weights: Wq2[n] = Wq * a1[n], qb2[n] = Wq@d1[n] + q_b
__global__ void fold_q_kernel(const float* __restrict__ q_w, const float* __restrict__ q_b,
                              const float* __restrict__ A1, const float* __restrict__ D1,
                              __nv_bfloat16* __restrict__ Wq2, float* __restrict__ qb2) {
    int n = blockIdx.x, m = threadIdx.x;
    const float* wr = q_w + (size_t)m * 256;
    const float* ar = A1 + n * 256;
    const float* dr = D1 + n * 256;
    __nv_bfloat16* o = Wq2 + ((size_t)n * 256 + m) * 256;
    float acc = 0.f;
    #pragma unroll 8
    for (int c = 0; c < 256; c++) {
        float w = wr[c];
        o[c] = __float2bfloat16(w * ar[c]);
        acc = fmaf(w, dr[c], acc);
    }
    qb2[n * 256 + m] = acc + q_b[m];
}

// fused pooled chain: affine(A1,D1) -> stats -> ds affine -> bf16
__global__ void pooled_fuse_kernel(const float* __restrict__ praw,
                                   const float* __restrict__ A1, const float* __restrict__ D1,
                                   const float* __restrict__ dnw, const float* __restrict__ dnb,
                                   __nv_bfloat16* __restrict__ pooledB) {
    int n = blockIdx.x, tid = threadIdx.x;
    const float* base = praw + (size_t)n * 131072;
    const float* ar = A1 + n * 256;
    const float* dr = D1 + n * 256;
    float s = 0.f, ss = 0.f;
    for (int i = tid; i < 131072; i += 256) {
        int c = i >> 9;
        float v = fmaf(ar[c], base[i], dr[c]);
        s += v; ss += v * v;
    }
    for (int o = 16; o; o >>= 1) {
        s  += __shfl_down_sync(0xffffffffu, s, o);
        ss += __shfl_down_sync(0xffffffffu, ss, o);
    }
    __shared__ float sh[16];
    __shared__ float a2s[256], d2s[256];
    __shared__ float sm_mean, sm_rstd;
    int wp = tid >> 5;
    if ((tid & 31) == 0) { sh[wp] = s; sh[8 + wp] = ss; }
    __syncthreads();
    if (tid < 32) {
        s  = (tid < 8) ? sh[tid]     : 0.f;
        ss = (tid < 8) ? sh[8 + tid] : 0.f;
        for (int o = 4; o; o >>= 1) {
            s  += __shfl_down_sync(0xffffffffu, s, o);
            ss += __shfl_down_sync(0xffffffffu, ss, o);
        }
        if (tid == 0) {
            float mean = s * (1.f / 131072.f);
            float var  = ss * (1.f / 131072.f) - mean * mean;
            sm_mean = mean;
            sm_rstd = rsqrtf(var + EPS);
        }
    }
    __syncthreads();
    {
        float mean = sm_mean, rstd = sm_rstd;
        a2s[tid] = dnw[tid] * rstd;
        d2s[tid] = dnb[tid] - mean * rstd * dnw[tid];
    }
    __syncthreads();
    __nv_bfloat16* ob = pooledB + (size_t)n * 131072;
    for (int i = tid; i < 131072; i += 256) {
        int c = i >> 9;
        float v = fmaf(ar[c], base[i], dr[c]);
        ob[i] = __float2bfloat16(fmaf(a2s[c], v, d2s[c]));
    }
}

__global__ void convert_weights_kernel(
    const float* __restrict__ qkv_w, const float* __restrict__ kv_w,
    const float* __restrict__ proj_w,
    __nv_bfloat16* __restrict__ Wqkv, __nv_bfloat16* __restrict__ Wkv,
    __nv_bfloat16* __restrict__ Wproj) {
    int idx = blockIdx.x * blockDim.x + threadIdx.x;
    const int T1 = 768 * 256, T2 = T1 + 512 * 256, T3 = T2 + 256 * 768;
    if (idx < T1) {
        Wqkv[idx] = __float2bfloat16(qkv_w[idx]);
    } else if (idx < T2) {
        int j = idx - T1; Wkv[j] = __float2bfloat16(kv_w[j]);
    } else if (idx < T3) {
        int j = idx - T1 - 512 * 256;
        int m = j / 768, k = j % 768;
        float v = proj_w[m * 256 + (k & 255)];
        __nv_bfloat16 hi = __float2bfloat16(v);
        if (k >= 256 && k < 512) hi = __float2bfloat16(v - __bfloat162float(hi));
        Wproj[j] = hi;
    }
}

// =========================================================================
// wgemm3: BM=128, BN=128, BK=32, 3-stage cp.async, 256 threads.
// aStride/biasStride: per-z offsets (elements) for folded per-batch weights.
// =========================================================================
#define WG_SMEM 69632

template<int MODE>
__global__ void __launch_bounds__(256) wgemm3_kernel(
    const __nv_bfloat16* __restrict__ A,
    const __nv_bfloat16* __restrict__ B0, const __nv_bfloat16* __restrict__ B1,
    const float* __restrict__ bias,
    float* __restrict__ outF, __nv_bfloat16* __restrict__ outB,
    int M, int S, int KT, float qScale, long aStride, int biasStride) {
    extern __shared__ __align__(16) char dsm[];
    __nv_bfloat16* As = (__nv_bfloat16*)dsm;
    __nv_bfloat16* Bs = (__nv_bfloat16*)(dsm + 30720);
    float* Cs = (float*)dsm;

    int tid = threadIdx.x, warp = tid >> 5;
    int wm = warp >> 2, wn = warp & 3;
    int m0 = blockIdx.x * 128;
    int s0 = blockIdx.y * 128;
    int z  = blockIdx.z;

    const __nv_bfloat16* Az = A + (size_t)z * aStride;
    const float* biasz = bias + (size_t)z * biasStride;
    const __nv_bfloat16* Bb0 = B0 + (size_t)z * 256 * S;
    const __nv_bfloat16* Bb1 = B1 + (size_t)z * 256 * S;

    wmma::fragment<wmma::accumulator, 16, 16, 16, float> acc[4][2];
    #pragma unroll
    for (int i = 0; i < 4; i++)
        #pragma unroll
        for (int j = 0; j < 2; j++) wmma::fill_fragment(acc[i][j], 0.f);

    const int NIT = KT >> 5;

    auto prefetch = [&](int it, int buf) {
        int ktL = it * 32;
        #pragma unroll
        for (int i = 0; i < 2; i++) {
            int c = tid + i * 256;
            int r = c >> 2, q = (c & 3) * 8;
            cp16(As + buf * 5120 + r * 40 + q,
                 Az + (size_t)(m0 + r) * KT + ktL + q);
        }
        const __nv_bfloat16* Bp = (ktL < 512) ? Bb0 : Bb1;
        int krow = ktL & 255;
        #pragma unroll
        for (int i = 0; i < 2; i++) {
            int c = tid + i * 256;
            int r = c >> 4, q = (c & 15) * 8;
            cp16(Bs + buf * 4352 + r * 136 + q,
                 Bp + (size_t)(krow + r) * S + s0 + q);
        }
    };

    prefetch(0, 0); CP_COMMIT;
    prefetch(1, 1); CP_COMMIT;

    int buf = 0;
    for (int it = 0; it < NIT; it++) {
        if (it + 1 < NIT) CP_WAIT1; else CP_WAIT0;
        __syncthreads();
        #pragma unroll
        for (int ks = 0; ks < 2; ks++) {
            wmma::fragment<wmma::matrix_a, 16, 16, 16, __nv_bfloat16, wmma::row_major> af[4];
            #pragma unroll
            for (int i = 0; i < 4; i++)
                wmma::load_matrix_sync(af[i], As + buf * 5120 + (wm * 64 + i * 16) * 40 + ks * 16, 40);
            wmma::fragment<wmma::matrix_b, 16, 16, 16, __nv_bfloat16, wmma::row_major> bf[2];
            #pragma unroll
            for (int j = 0; j < 2; j++)
                wmma::load_matrix_sync(bf[j], Bs + buf * 4352 + (ks * 16) * 136 + wn * 32 + j * 16, 136);
            #pragma unroll
            for (int i = 0; i < 4; i++)
                #pragma unroll
                for (int j = 0; j < 2; j++)
                    wmma::mma_sync(acc[i][j], af[i], bf[j], acc[i][j]);
        }
        if (it + 2 < NIT) {
            prefetch(it + 2, (buf + 2) % 3);
            CP_COMMIT;
        }
        buf = (buf + 1) % 3;
    }

    __syncthreads();
    #pragma unroll
    for (int i = 0; i < 4; i++)
        #pragma unroll
        for (int j = 0; j < 2; j++)
            wmma::store_matrix_sync(Cs + (wm * 64 + i * 16) * 132 + wn * 32 + j * 16,
                                    acc[i][j], 132, wmma::mem_row_major);
    __syncthreads();

    if (MODE == 0) {
        float* Ob = outF + ((size_t)z * M + m0) * S;
        #pragma unroll
        for (int it = 0; it < 16; it++) {
            int idx = tid + it * 256;
            int r = idx >> 5, c4 = idx & 31;
            float bv = biasz[m0 + r];
            float4 v = *reinterpret_cast<const float4*>(&Cs[r * 132 + c4 * 4]);
            v.x += bv; v.y += bv; v.z += bv; v.w += bv;
            *reinterpret_cast<float4*>(&Ob[(size_t)r * S + s0 + c4 * 4]) = v;
        }
    } else {
        #pragma unroll
        for (int it = 0; it < 8; it++) {
            int idx = tid + it * 256;
            int sl = idx & 127, dg = idx >> 7;
            int gmb = m0 + dg * 8;
            float sc;
            size_t off;
            __nv_bfloat16* base;
            if (MODE == 1) {
                int hb = gmb >> 6, db = gmb & 63;
                sc = qScale;
                base = outB + ((size_t)(z * (M >> 6) + hb) * S + s0 + sl) * 64;
                off = db;
            } else {
                int sel = gmb >> 8, head = (gmb >> 6) & 3, db = gmb & 63;
                sc = (sel == 0) ? qScale : 1.f;
                int s = s0 + sl;
                int d5 = s & 31, w5 = (s >> 5) & 31, h5 = s >> 10;
                int window = ((h5 >> 2) * 8 + (w5 >> 2)) * 8 + (d5 >> 2);
                int token  = (((h5 & 3) * 4 + (w5 & 3)) * 4 + (d5 & 3));
                base = outB + (((size_t)(z * 3 + sel) * 4 + head) * 512) * 4096;
                off = (size_t)window * 4096 + token * 64 + db;
            }
            float f[8];
            #pragma unroll
            for (int e = 0; e < 8; e++)
                f[e] = (Cs[(dg * 8 + e) * 132 + sl] + biasz[gmb + e]) * sc;
            uint4 u;
            u.x = pack2(f[0], f[1]);
            u.y = pack2(f[2], f[3]);
            u.z = pack2(f[4], f[5]);
            u.w = pack2(f[6], f[7]);
            *reinterpret_cast<uint4*>(base + off) = u;
        }
    }
}

// =========================================================================
// Local windowed attention + raw bf16 out + pool sums + gn partials
// =========================================================================
__global__ void __launch_bounds__(128) local_attn_w_kernel(
    const __nv_bfloat16* __restrict__ qkvB, const float* __restrict__ x,
    float* __restrict__ attn, __nv_bfloat16* __restrict__ attnB,
    float* __restrict__ praw, float* __restrict__ part) {
    __shared__ __align__(16) __nv_bfloat16 QP[64 * 72];
    __shared__ __align__(16) __nv_bfloat16 Ks[64 * 72];
    __shared__ __align__(16) __nv_bfloat16 Vs[64 * 72];
    __shared__ __align__(16) float Sf[64 * 68];
    __shared__ float linv[64];
    __shared__ float rs[4], rss[4];

    int w = blockIdx.x, head = blockIdx.y, n = blockIdx.z;
    int tid = threadIdx.x, warp = tid >> 5;

    size_t base = (((size_t)(n * 3) * 4 + head) * 512 + w) * 4096;
    size_t step = (size_t)4 * 512 * 4096;
    const uint4* Qg = (const uint4*)(qkvB + base);
    const uint4* Kg = (const uint4*)(qkvB + base + step);
    const uint4* Vg = (const uint4*)(qkvB + base + 2 * step);

    #pragma unroll
    for (int i = 0; i < 4; i++) {
        int c = tid + i * 128;
        int r = c >> 3, q = c & 7;
        ((uint4*)(QP + r * 72))[q] = Qg[c];
        ((uint4*)(Ks + r * 72))[q] = Kg[c];
        ((uint4*)(Vs + r * 72))[q] = Vg[c];
    }
    __syncthreads();

    {
        int m = warp * 16;
        wmma::fragment<wmma::accumulator, 16, 16, 16, float> acc[4];
        #pragma unroll
        for (int j = 0; j < 4; j++) wmma::fill_fragment(acc[j], 0.f);
        #pragma unroll
        for (int kd = 0; kd < 4; kd++) {
            wmma::fragment<wmma::matrix_a, 16, 16, 16, __nv_bfloat16, wmma::row_major> af;
            wmma::load_matrix_sync(af, QP + m * 72 + kd * 16, 72);
            #pragma unroll
            for (int j = 0; j < 4; j++) {
                wmma::fragment<wmma::matrix_b, 16, 16, 16, __nv_bfloat16, wmma::col_major> bf;
                wmma::load_matrix_sync(bf, Ks + (j * 16) * 72 + kd * 16, 72);
                wmma::mma_sync(acc[j], af, bf, acc[j]);
            }
        }
        #pragma unroll
        for (int j = 0; j < 4; j++)
            wmma::store_matrix_sync(Sf + m * 68 + j * 16, acc[j], 68, wmma::mem_row_major);
    }
    __syncthreads();

    // softmax without max subtraction (scores tiny; shift-invariant)
    {
        int r = tid >> 1, hf = tid & 1;
        const float* srow = Sf + r * 68 + hf * 32;
        float ls = 0.f;
        __nv_bfloat16* prow = QP + r * 72 + hf * 32;
        #pragma unroll
        for (int j = 0; j < 32; j++) {
            float p = __expf(srow[j]);
            ls += p;
            prow[j] = __float2bfloat16(p);
        }
        ls += __shfl_xor_sync(0xffffffffu, ls, 1);
        if (hf == 0) linv[r] = 1.f / ls;
    }
    __syncthreads();

    {
        int m = warp * 16;
        wmma::fragment<wmma::accumulator, 16, 16, 16, float> acc[4];
        #pragma unroll
        for (int j = 0; j < 4; j++) wmma::fill_fragment(acc[j], 0.f);
        #pragma unroll
        for (int kk = 0; kk < 4; kk++) {
            wmma::fragment<wmma::matrix_a, 16, 16, 16, __nv_bfloat16, wmma::row_major> af;
            wmma::load_matrix_sync(af, QP + m * 72 + kk * 16, 72);
            #pragma unroll
            for (int j = 0; j < 4; j++) {
                wmma::fragment<wmma::matrix_b, 16, 16, 16, __nv_bfloat16, wmma::row_major> bf;
                wmma::load_matrix_sync(bf, Vs + (kk * 16) * 72 + j * 16, 72);
                wmma::mma_sync(acc[j], af, bf, acc[j]);
            }
        }
        #pragma unroll
        for (int j = 0; j < 4; j++)
            wmma::store_matrix_sync(Sf + m * 68 + j * 16, acc[j], 68, wmma::mem_row_major);
    }
    __syncthreads();

    int wh = w >> 6, ww = (w >> 3) & 7, wd = w & 7;
    int base_s = wh * 4096 + ww * 128 + wd * 4;
    int chb = n * 256 + head * 64;
    float s_acc = 0.f, ss_acc = 0.f;
    #pragma unroll
    for (int it = 0; it < 8; it++) {
        int idx = tid + it * 128;
        int d = idx >> 4, tg = idx & 15;
        int i_ = tg >> 2, j_ = tg & 3;
        int s = base_s + i_ * 1024 + j_ * 32;
        int t0 = tg * 4;
        size_t g = ((size_t)(chb + d)) * SV + s;
        float4 xv = *reinterpret_cast<const float4*>(x + g);
        float4 ov;
        ov.x = fmaf(Sf[(t0 + 0) * 68 + d], linv[t0 + 0], xv.x);
        ov.y = fmaf(Sf[(t0 + 1) * 68 + d], linv[t0 + 1], xv.y);
        ov.z = fmaf(Sf[(t0 + 2) * 68 + d], linv[t0 + 2], xv.z);
        ov.w = fmaf(Sf[(t0 + 3) * 68 + d], linv[t0 + 3], xv.w);
        *reinterpret_cast<float4*>(attn + g) = ov;
        uint2 rb;
        rb.x = pack2(ov.x, ov.y);
        rb.y = pack2(ov.z, ov.w);
        *reinterpret_cast<uint2*>(attnB + g) = rb;
        float ps = ov.x + ov.y + ov.z + ov.w;
        s_acc  += ps;
        ss_acc += ov.x*ov.x + ov.y*ov.y + ov.z*ov.z + ov.w*ov.w;
        #pragma unroll
        for (int o = 8; o; o >>= 1) ps += __shfl_down_sync(0xffffffffu, ps, o);
        if ((tid & 15) == 0)
            praw[((size_t)(chb + d)) * 512 + w] = ps * (1.f / 64.f);
    }
    #pragma unroll
    for (int o = 16; o; o >>= 1) {
        s_acc  += __shfl_down_sync(0xffffffffu, s_acc, o);
        ss_acc += __shfl_down_sync(0xffffffffu, ss_acc, o);
    }
    if ((tid & 31) == 0) { rs[warp] = s_acc; rss[warp] = ss_acc; }
    __syncthreads();
    if (tid == 0) {
        size_t pi = (size_t)n * 2048 + head * 512 + w;
        part[pi * 2 + 0] = rs[0] + rs[1] + rs[2] + rs[3];
        part[pi * 2 + 1] = rss[0] + rss[1] + rss[2] + rss[3];
    }
}

// =========================================================================
// Global attention: no-max softmax, O persistent in accumulators
// =========================================================================
#define GA_SMEM 90624

__global__ void __launch_bounds__(256, 2) gattn_kernel(
    const __nv_bfloat16* __restrict__ q2T, const __nv_bfloat16* __restrict__ kvT,
    const float* __restrict__ attn,
    const float* __restrict__ A1, const float* __restrict__ D1,
    __nv_bfloat16* __restrict__ ghi, __nv_bfloat16* __restrict__ glo) {
    extern __shared__ __align__(16) char sm[];
    __nv_bfloat16* Qs = (__nv_bfloat16*)sm;
    __nv_bfloat16* Ks = Qs + 128 * 72;
    __nv_bfloat16* Vs = Ks + 64 * 72;
    __nv_bfloat16* Ps = Vs + 64 * 72;
    float* Sf   = (float*)(Ps + 128 * 72);
    float* lrow = Sf + 128 * 68;

    int tid = threadIdx.x, warp = tid >> 5;
    int h = blockIdx.y, n = blockIdx.z;
    int s0 = blockIdx.x * 128;

    const uint4* Qg = (const uint4*)(q2T + ((size_t)(n * 4 + h) * SV + s0) * 64);
    const uint4* Kg = (const uint4*)(kvT + ((size_t)(n * 8 + h) * 512) * 64);
    const uint4* Vg = (const uint4*)(kvT + ((size_t)(n * 8 + 4 + h) * 512) * 64);

    #pragma unroll
    for (int i = 0; i < 4; i++) {
        int idx = tid + i * 256;
        int r = idx >> 3, c = idx & 7;
        ((uint4*)(Qs + r * 72))[c] = Qg[r * 8 + c];
    }
    if (tid < 128) lrow[tid] = 0.f;

    int pm = warp >> 1, pn = warp & 1;
    wmma::fragment<wmma::accumulator, 16, 16, 16, float> acc_o[2][2];
    #pragma unroll
    for (int i = 0; i < 2; i++)
        #pragma unroll
        for (int j = 0; j < 2; j++) wmma::fill_fragment(acc_o[i][j], 0.f);

    for (int ch = 0; ch < 8; ch++) {
        __syncthreads();
        #pragma unroll
        for (int i = 0; i < 2; i++) {
            int idx = tid + i * 256;
            int r = idx >> 3, c = idx & 7;
            ((uint4*)(Ks + r * 72))[c] = Kg[(ch * 64 + r) * 8 + c];
            ((uint4*)(Vs + r * 72))[c] = Vg[(ch * 64 + r) * 8 + c];
        }
        __syncthreads();

        {
            int m = warp * 16;
            wmma::fragment<wmma::accumulator, 16, 16, 16, float> acc[4];
            #pragma unroll
            for (int j = 0; j < 4; j++) wmma::fill_fragment(acc[j], 0.f);
            #pragma unroll
            for (int kd = 0; kd < 4; kd++) {
                wmma::fragment<wmma::matrix_a, 16, 16, 16, __nv_bfloat16, wmma::row_major> af;
                wmma::load_matrix_sync(af, Qs + m * 72 + kd * 16, 72);
                #pragma unroll
                for (int j = 0; j < 4; j++) {
                    wmma::fragment<wmma::matrix_b, 16, 16, 16, __nv_bfloat16, wmma::col_major> bf;
                    wmma::load_matrix_sync(bf, Ks + (j * 16) * 72 + kd * 16, 72);
                    wmma::mma_sync(acc[j], af, bf, acc[j]);
                }
            }
            #pragma unroll
            for (int j = 0; j < 4; j++)
                wmma::store_matrix_sync(Sf + m * 68 + j * 16, acc[j], 68, wmma::mem_row_major);
        }
        __syncthreads();

        {
            int r = tid >> 1, hf = tid & 1;
            const float* srow = Sf + r * 68 + hf * 32;
            float ls = 0.f;
            __nv_bfloat16* prow = Ps + r * 72 + hf * 32;
            #pragma unroll
            for (int j = 0; j < 32; j++) {
                float p = __expf(srow[j]);
                ls += p;
                prow[j] = __float2bfloat16(p);
            }
            ls += __shfl_xor_sync(0xffffffffu, ls, 1);
            if (hf == 0) lrow[r] += ls;
        }
        __syncthreads();

        {
            #pragma unroll
            for (int kk = 0; kk < 4; kk++) {
                wmma::fragment<wmma::matrix_a, 16, 16, 16, __nv_bfloat16, wmma::row_major> af[2];
                #pragma unroll
                for (int i = 0; i < 2; i++)
                    wmma::load_matrix_sync(af[i], Ps + (pm * 32 + i * 16) * 72 + kk * 16, 72);
                wmma::fragment<wmma::matrix_b, 16, 16, 16, __nv_bfloat16, wmma::row_major> bf[2];
                #pragma unroll
                for (int j = 0; j < 2; j++)
                    wmma::load_matrix_sync(bf[j], Vs + (kk * 16) * 72 + pn * 32 + j * 16, 72);
                #pragma unroll
                for (int i = 0; i < 2; i++)
                    #pragma unroll
                    for (int j = 0; j < 2; j++)
                        wmma::mma_sync(acc_o[i][j], af[i], bf[j], acc_o[i][j]);
            }
        }
    }

    __syncthreads();
    #pragma unroll
    for (int i = 0; i < 2; i++)
        #pragma unroll
        for (int j = 0; j < 2; j++)
            wmma::store_matrix_sync(Sf + (pm * 32 + i * 16) * 68 + pn * 32 + j * 16,
                                    acc_o[i][j], 68, wmma::mem_row_major);
    __syncthreads();

    #pragma unroll
    for (int i = 0; i < 32; i++) {
        int idx = tid + i * 256;
        int r = idx & 127, d = idx >> 7;
        int cch = n * 256 + h * 64 + d;
        float v = Sf[r * 68 + d] / lrow[r];
        size_t gi = ((size_t)cch) * SV + s0 + r;
        float t = v + fmaf(A1[cch], attn[gi], D1[cch]);
        __nv_bfloat16 hi = __float2bfloat16(t);
        ghi[gi] = hi;
        glo[gi] = __float2bfloat16(t - __bfloat162float(hi));
    }
}

// =========================================================================
// host launch
// =========================================================================
extern "C" void kernel_launch(void* const* d_in, const int* in_sizes, int n_in,
                              void* d_out, int out_size) {
    const float* x      = (const float*)d_in[0];
    const float* qkv_w  = (const float*)d_in[1];
    const float* qkv_b  = (const float*)d_in[2];
    const float* norm_w = (const float*)d_in[3];
    const float* norm_b = (const float*)d_in[4];
    const float* anorm_w= (const float*)d_in[5];
    const float* anorm_b= (const float*)d_in[6];
    const float* dnorm_w= (const float*)d_in[7];
    const float* dnorm_b= (const float*)d_in[8];
    const float* q_w    = (const float*)d_in[9];
    const float* q_b    = (const float*)d_in[10];
    const float* kv_w   = (const float*)d_in[11];
    const float* kv_b   = (const float*)d_in[12];
    const float* proj_w = (const float*)d_in[13];
    const float* proj_b = (const float*)d_in[14];
    float* out = (float*)d_out;

    float *attn, *praw, *part, *aff, *qb2;
    __nv_bfloat16 *xnB, *qkvB, *attnB, *ghi, *glo, *pooledB, *q2T, *kvT;
    __nv_bfloat16 *WqkvB, *Wq2B, *WkvB, *WprojB;
    cudaGetSymbolAddress((void**)&attn,    g_attn);
    cudaGetSymbolAddress((void**)&praw,    g_praw);
    cudaGetSymbolAddress((void**)&xnB,     g_xnB);
    cudaGetSymbolAddress((void**)&qkvB,    g_qkvB);
    cudaGetSymbolAddress((void**)&attnB,   g_attnB);
    cudaGetSymbolAddress((void**)&ghi,     g_ghi);
    cudaGetSymbolAddress((void**)&glo,     g_glo);
    cudaGetSymbolAddress((void**)&pooledB, g_pooledB);
    cudaGetSymbolAddress((void**)&q2T,     g_q2T);
    cudaGetSymbolAddress((void**)&kvT,     g_kvT);
    cudaGetSymbolAddress((void**)&WqkvB,   g_WqkvB);
    cudaGetSymbolAddress((void**)&Wq2B,    g_Wq2B);
    cudaGetSymbolAddress((void**)&WkvB,    g_WkvB);
    cudaGetSymbolAddress((void**)&WprojB,  g_WprojB);
    cudaGetSymbolAddress((void**)&qb2,     g_qb2);
    cudaGetSymbolAddress((void**)&part,    g_part);
    cudaGetSymbolAddress((void**)&aff,     g_aff);

    static bool attr_set = false;
    if (!attr_set) {
        cudaFuncSetAttribute(gattn_kernel, cudaFuncAttributeMaxDynamicSharedMemorySize, GA_SMEM);
        cudaFuncSetAttribute(wgemm3_kernel<0>, cudaFuncAttributeMaxDynamicSharedMemorySize, WG_SMEM);
        cudaFuncSetAttribute(wgemm3_kernel<1>, cudaFuncAttributeMaxDynamicSharedMemorySize, WG_SMEM);
        cudaFuncSetAttribute(wgemm3_kernel<2>, cudaFuncAttributeMaxDynamicSharedMemorySize, WG_SMEM);
        attr_set = true;
    }

    float* A0 = aff;        float* D0 = aff + 512;
    float* A1 = aff + 1024; float* D1 = aff + 1536;

    convert_weights_kernel<<<2048, 256>>>(qkv_w, kv_w, proj_w, WqkvB, WkvB, WprojB);

    // GroupNorm(x) -> bf16 normed x
    reduce1_kernel<<<dim3(512, NB), 256>>>(x, 256L * SV, part);
    stats2affine_kernel<<<NB, 256>>>(part, 512, norm_w, norm_b, A0, D0, 1.f / (256.f * 32768.f));
    convert_x_kernel<<<16384, 256>>>(x, A0, D0, xnB);

    // qkv conv -> window-gathered bf16 (q pre-scaled 1/16)
    wgemm3_kernel<2><<<dim3(6, 256, NB), 256, WG_SMEM>>>(
        WqkvB, xnB, xnB, qkv_b, nullptr, qkvB, 768, (int)SV, 256, SCALE_INV, 0, 0);

    // local attention: attn(raw fp32 + bf16) + pooled sums + gn partials
    local_attn_w_kernel<<<dim3(512, NH, NB), 128>>>(qkvB, x, attn, attnB, praw, part);

    // anorm affine from fused partials
    stats2affine_kernel<<<NB, 256>>>(part, 2048, anorm_w, anorm_b, A1, D1, 1.f / (256.f * 32768.f));

    // fold anorm into q weights (per batch)
    fold_q_kernel<<<NB, 256>>>(q_w, q_b, A1, D1, Wq2B, qb2);

    // fused pooled chain -> bf16 pooled
    pooled_fuse_kernel<<<NB, 256>>>(praw, A1, D1, dnorm_w, dnorm_b, pooledB);

    // kv conv -> kvT, q conv (folded weights, raw attnB) -> q2T (scaled 1/16)
    wgemm3_kernel<1><<<dim3(4, 4, NB), 256, WG_SMEM>>>(
        WkvB, pooledB, pooledB, kv_b, nullptr, kvT, 512, 512, 256, 1.f, 0, 0);
    wgemm3_kernel<1><<<dim3(2, 256, NB), 256, WG_SMEM>>>(
        Wq2B, attnB, attnB, qb2, nullptr, q2T, 256, (int)SV, 256, SCALE_INV,
        256L * 256, 256);

    // global attention + affine residual -> bf16 hi/lo
    gattn_kernel<<<dim3(256, NH, NB), 256, GA_SMEM>>>(q2T, kvT, attn, A1, D1, ghi, glo);

    // final projection (3-term bf16 split) -> out
    wgemm3_kernel<0><<<dim3(2, 256, NB), 256, WG_SMEM>>>(
        WprojB, ghi, glo, proj_b, out, nullptr, 256, (int)SV, 768, 1.f, 0, 0);
}

// round 8
// speedup vs baseline: 1.2692x; 1.2692x over previous
#include <cuda_runtime.h>
#include <cuda_bf16.h>
#include <mma.h>
#include <math.h>
#include <stdint.h>

using namespace nvcuda;

#define NB 2
#define CH 256
#define SV 32768L
#define NH 4
#define HD 64
#define SCALE_INV 0.0625f
#define EPS 1e-6f

__device__ __forceinline__ unsigned pack2(float a, float b) {
    __nv_bfloat162 t = __floats2bfloat162_rn(a, b);
    return *reinterpret_cast<unsigned*>(&t);
}

// ---------------- scratch ----------------
__device__ __align__(16) float g_attn   [NB * 256L * SV];   // x + local attn (raw)
__device__ __align__(16) float g_praw   [NB * 256 * 512];
__device__ __align__(16) float g_pnorm  [NB * 256 * 512];
__device__ __align__(16) __nv_bfloat16 g_xnB   [NB * 256L * SV];
__device__ __align__(16) __nv_bfloat16 g_qkvB  [NB * 768L * SV];
__device__ __align__(16) __nv_bfloat16 g_attnB [NB * 256L * SV];
__device__ __align__(16) __nv_bfloat16 g_ghi   [NB * 256L * SV];
__device__ __align__(16) __nv_bfloat16 g_glo   [NB * 256L * SV];
__device__ __align__(16) __nv_bfloat16 g_pooledB[NB * 256 * 512];
__device__ __align__(16) __nv_bfloat16 g_q2T   [NB * 4L * SV * 64];
__device__ __align__(16) __nv_bfloat16 g_kvT   [NB * 8L * 512 * 64];
__device__ __align__(16) __nv_bfloat16 g_WqkvB [768 * 256];
__device__ __align__(16) __nv_bfloat16 g_WqB   [256 * 256];
__device__ __align__(16) __nv_bfloat16 g_WkvB  [512 * 256];
__device__ __align__(16) __nv_bfloat16 g_WprojB[256 * 768];
__device__ float g_part [NB * 2048 * 2];
__device__ float g_aff  [6 * NB * 256];

// ---------------- cp.async ----------------
__device__ __forceinline__ void cp16(void* dst, const void* src) {
    unsigned d = (unsigned)__cvta_generic_to_shared(dst);
    asm volatile("cp.async.cg.shared.global [%0], [%1], 16;\n" :: "r"(d), "l"(src));
}
#define CP_COMMIT asm volatile("cp.async.commit_group;\n" ::: "memory")
#define CP_WAIT1  asm volatile("cp.async.wait_group 1;\n" ::: "memory")
#define CP_WAIT0  asm volatile("cp.async.wait_group 0;\n" ::: "memory")

// =========================================================================
// reductions / affine / conversions
// =========================================================================
__global__ void reduce1_kernel(const float* __restrict__ buf, long per, float* __restrict__ part) {
    int n = blockIdx.y;
    const float* p = buf + (size_t)n * per;
    float s = 0.f, ss = 0.f;
    for (long i = (long)blockIdx.x * blockDim.x + threadIdx.x; i < per;
         i += (long)gridDim.x * blockDim.x) {
        float v = p[i];
        s += v; ss += v * v;
    }
    for (int o = 16; o; o >>= 1) {
        s  += __shfl_down_sync(0xffffffffu, s, o);
        ss += __shfl_down_sync(0xffffffffu, ss, o);
    }
    __shared__ float sh[64];
    int w = threadIdx.x >> 5;
    if ((threadIdx.x & 31) == 0) { sh[w] = s; sh[32 + w] = ss; }
    __syncthreads();
    if (threadIdx.x < 32) {
        int nw = blockDim.x >> 5;
        s  = (threadIdx.x < nw) ? sh[threadIdx.x]      : 0.f;
        ss = (threadIdx.x < nw) ? sh[32 + threadIdx.x] : 0.f;
        for (int o = 16; o; o >>= 1) {
            s  += __shfl_down_sync(0xffffffffu, s, o);
            ss += __shfl_down_sync(0xffffffffu, ss, o);
        }
        if (threadIdx.x == 0) {
            part[((size_t)n * gridDim.x + blockIdx.x) * 2 + 0] = s;
            part[((size_t)n * gridDim.x + blockIdx.x) * 2 + 1] = ss;
        }
    }
}

// merged reduce2 + make_affine: one block per sample, 256 threads
__global__ void stats2affine_kernel(const float* __restrict__ part, int nb,
                                    const float* __restrict__ w, const float* __restrict__ b,
                                    float* __restrict__ a, float* __restrict__ d,
                                    float inv_cnt) {
    int n = blockIdx.x, tid = threadIdx.x;
    float s = 0.f, ss = 0.f;
    for (int i = tid; i < nb; i += 256) {
        s  += part[((size_t)n * nb + i) * 2 + 0];
        ss += part[((size_t)n * nb + i) * 2 + 1];
    }
    for (int o = 16; o; o >>= 1) {
        s  += __shfl_down_sync(0xffffffffu, s, o);
        ss += __shfl_down_sync(0xffffffffu, ss, o);
    }
    __shared__ float sh[16];
    __shared__ float sm_mean, sm_rstd;
    int wp = tid >> 5;
    if ((tid & 31) == 0) { sh[wp] = s; sh[8 + wp] = ss; }
    __syncthreads();
    if (tid < 32) {
        s  = (tid < 8) ? sh[tid]     : 0.f;
        ss = (tid < 8) ? sh[8 + tid] : 0.f;
        for (int o = 4; o; o >>= 1) {
            s  += __shfl_down_sync(0xffffffffu, s, o);
            ss += __shfl_down_sync(0xffffffffu, ss, o);
        }
        if (tid == 0) {
            float mean = s * inv_cnt;
            float var  = ss * inv_cnt - mean * mean;
            sm_mean = mean;
            sm_rstd = rsqrtf(var + EPS);
        }
    }
    __syncthreads();
    float mean = sm_mean, rstd = sm_rstd;
    a[n * CH + tid] = w[tid] * rstd;
    d[n * CH + tid] = b[tid] - mean * rstd * w[tid];
}

__global__ void convert_x_kernel(const float* __restrict__ x,
                                 const float* __restrict__ a, const float* __restrict__ d,
                                 __nv_bfloat16* __restrict__ out) {
    size_t i4 = (size_t)blockIdx.x * blockDim.x + threadIdx.x;
    int c = (int)((i4 >> 13) & 255);
    int n = (int)(i4 >> 21);
    float aa = a[n * CH + c], dd = d[n * CH + c];
    float4 v = reinterpret_cast<const float4*>(x)[i4];
    uint2 r;
    r.x = pack2(fmaf(aa, v.x, dd), fmaf(aa, v.y, dd));
    r.y = pack2(fmaf(aa, v.z, dd), fmaf(aa, v.w, dd));
    reinterpret_cast<uint2*>(out)[i4] = r;
}

__global__ void apply_pool_affine_kernel(const float* __restrict__ praw,
                                         const float* __restrict__ a, const float* __restrict__ d,
                                         float* __restrict__ pnorm) {
    size_t i4 = (size_t)blockIdx.x * blockDim.x + threadIdx.x;
    int c = (int)((i4 >> 7) & 255);
    int n = (int)(i4 >> 15);
    float aa = a[n * CH + c], dd = d[n * CH + c];
    float4 v = reinterpret_cast<const float4*>(praw)[i4];
    v.x = fmaf(aa, v.x, dd); v.y = fmaf(aa, v.y, dd);
    v.z = fmaf(aa, v.z, dd); v.w = fmaf(aa, v.w, dd);
    reinterpret_cast<float4*>(pnorm)[i4] = v;
}

__global__ void convert_pooled_kernel(const float* __restrict__ pooled,
                                      const float* __restrict__ a, const float* __restrict__ d,
                                      __nv_bfloat16* __restrict__ out) {
    size_t i4 = (size_t)blockIdx.x * blockDim.x + threadIdx.x;
    int c = (int)((i4 >> 7) & 255);
    int n = (int)(i4 >> 15);
    float aa = a[n * CH + c], dd = d[n * CH + c];
    float4 v = reinterpret_cast<const float4*>(pooled)[i4];
    uint2 r;
    r.x = pack2(fmaf(aa, v.x, dd), fmaf(aa, v.y, dd));
    r.y = pack2(fmaf(aa, v.z, dd), fmaf(aa, v.w, dd));
    reinterpret_cast<uint2*>(out)[i4] = r;
}

__global__ void convert_weights_kernel(
    const float* __restrict__ qkv_w, const float* __restrict__ q_w,
    const float* __restrict__ kv_w, const float* __restrict__ proj_w,
    __nv_bfloat16* __restrict__ Wqkv, __nv_bfloat16* __restrict__ Wq,
    __nv_bfloat16* __restrict__ Wkv, __nv_bfloat16* __restrict__ Wproj) {
    int idx = blockIdx.x * blockDim.x + threadIdx.x;
    const int T1 = 768 * 256, T2 = T1 + 256 * 256, T3 = T2 + 512 * 256, T4 = T3 + 256 * 768;
    if (idx < T1) {
        Wqkv[idx] = __float2bfloat16(qkv_w[idx]);
    } else if (idx < T2) {
        int j = idx - T1; Wq[j] = __float2bfloat16(q_w[j]);
    } else if (idx < T3) {
        int j = idx - T2; Wkv[j] = __float2bfloat16(kv_w[j]);
    } else if (idx < T4) {
        int j = idx - T3;
        int m = j / 768, k = j % 768;
        float v = proj_w[m * 256 + (k & 255)];
        __nv_bfloat16 hi = __float2bfloat16(v);
        if (k >= 256 && k < 512) hi = __float2bfloat16(v - __bfloat162float(hi));
        Wproj[j] = hi;
    }
}

// =========================================================================
// wgemm3: BM=128, BN=128, BK=32, 3-stage cp.async, 256 threads.
// =========================================================================
#define WG_SMEM 69632

template<int MODE>
__global__ void __launch_bounds__(256) wgemm3_kernel(
    const __nv_bfloat16* __restrict__ A,
    const __nv_bfloat16* __restrict__ B0, const __nv_bfloat16* __restrict__ B1,
    const float* __restrict__ bias,
    float* __restrict__ outF, __nv_bfloat16* __restrict__ outB,
    int M, int S, int KT, float qScale) {
    extern __shared__ __align__(16) char dsm[];
    __nv_bfloat16* As = (__nv_bfloat16*)dsm;
    __nv_bfloat16* Bs = (__nv_bfloat16*)(dsm + 30720);
    float* Cs = (float*)dsm;

    int tid = threadIdx.x, warp = tid >> 5;
    int wm = warp >> 2, wn = warp & 3;
    int m0 = blockIdx.x * 128;
    int s0 = blockIdx.y * 128;
    int z  = blockIdx.z;

    const __nv_bfloat16* Bb0 = B0 + (size_t)z * 256 * S;
    const __nv_bfloat16* Bb1 = B1 + (size_t)z * 256 * S;

    wmma::fragment<wmma::accumulator, 16, 16, 16, float> acc[4][2];
    #pragma unroll
    for (int i = 0; i < 4; i++)
        #pragma unroll
        for (int j = 0; j < 2; j++) wmma::fill_fragment(acc[i][j], 0.f);

    const int NIT = KT >> 5;

    auto prefetch = [&](int it, int buf) {
        int ktL = it * 32;
        #pragma unroll
        for (int i = 0; i < 2; i++) {
            int c = tid + i * 256;
            int r = c >> 2, q = (c & 3) * 8;
            cp16(As + buf * 5120 + r * 40 + q,
                 A + (size_t)(m0 + r) * KT + ktL + q);
        }
        const __nv_bfloat16* Bp = (ktL < 512) ? Bb0 : Bb1;
        int krow = ktL & 255;
        #pragma unroll
        for (int i = 0; i < 2; i++) {
            int c = tid + i * 256;
            int r = c >> 4, q = (c & 15) * 8;
            cp16(Bs + buf * 4352 + r * 136 + q,
                 Bp + (size_t)(krow + r) * S + s0 + q);
        }
    };

    prefetch(0, 0); CP_COMMIT;
    prefetch(1, 1); CP_COMMIT;

    int buf = 0;
    for (int it = 0; it < NIT; it++) {
        if (it + 1 < NIT) CP_WAIT1; else CP_WAIT0;
        __syncthreads();
        #pragma unroll
        for (int ks = 0; ks < 2; ks++) {
            wmma::fragment<wmma::matrix_a, 16, 16, 16, __nv_bfloat16, wmma::row_major> af[4];
            #pragma unroll
            for (int i = 0; i < 4; i++)
                wmma::load_matrix_sync(af[i], As + buf * 5120 + (wm * 64 + i * 16) * 40 + ks * 16, 40);
            wmma::fragment<wmma::matrix_b, 16, 16, 16, __nv_bfloat16, wmma::row_major> bf[2];
            #pragma unroll
            for (int j = 0; j < 2; j++)
                wmma::load_matrix_sync(bf[j], Bs + buf * 4352 + (ks * 16) * 136 + wn * 32 + j * 16, 136);
            #pragma unroll
            for (int i = 0; i < 4; i++)
                #pragma unroll
                for (int j = 0; j < 2; j++)
                    wmma::mma_sync(acc[i][j], af[i], bf[j], acc[i][j]);
        }
        if (it + 2 < NIT) {
            prefetch(it + 2, (buf + 2) % 3);
            CP_COMMIT;
        }
        buf = (buf + 1) % 3;
    }

    __syncthreads();
    #pragma unroll
    for (int i = 0; i < 4; i++)
        #pragma unroll
        for (int j = 0; j < 2; j++)
            wmma::store_matrix_sync(Cs + (wm * 64 + i * 16) * 132 + wn * 32 + j * 16,
                                    acc[i][j], 132, wmma::mem_row_major);
    __syncthreads();

    if (MODE == 0) {
        float* Ob = outF + ((size_t)z * M + m0) * S;
        #pragma unroll
        for (int it = 0; it < 16; it++) {
            int idx = tid + it * 256;
            int r = idx >> 5, c4 = idx & 31;
            float bv = bias[m0 + r];
            float4 v = *reinterpret_cast<const float4*>(&Cs[r * 132 + c4 * 4]);
            v.x += bv; v.y += bv; v.z += bv; v.w += bv;
            *reinterpret_cast<float4*>(&Ob[(size_t)r * S + s0 + c4 * 4]) = v;
        }
    } else {
        #pragma unroll
        for (int it = 0; it < 8; it++) {
            int idx = tid + it * 256;
            int sl = idx & 127, dg = idx >> 7;
            int gmb = m0 + dg * 8;
            float sc;
            size_t off;
            __nv_bfloat16* base;
            if (MODE == 1) {
                int hb = gmb >> 6, db = gmb & 63;
                sc = qScale;
                base = outB + ((size_t)(z * (M >> 6) + hb) * S + s0 + sl) * 64;
                off = db;
            } else {
                int sel = gmb >> 8, head = (gmb >> 6) & 3, db = gmb & 63;
                sc = (sel == 0) ? qScale : 1.f;
                int s = s0 + sl;
                int d5 = s & 31, w5 = (s >> 5) & 31, h5 = s >> 10;
                int window = ((h5 >> 2) * 8 + (w5 >> 2)) * 8 + (d5 >> 2);
                int token  = (((h5 & 3) * 4 + (w5 & 3)) * 4 + (d5 & 3));
                base = outB + (((size_t)(z * 3 + sel) * 4 + head) * 512) * 4096;
                off = (size_t)window * 4096 + token * 64 + db;
            }
            float f[8];
            #pragma unroll
            for (int e = 0; e < 8; e++)
                f[e] = (Cs[(dg * 8 + e) * 132 + sl] + bias[gmb + e]) * sc;
            uint4 u;
            u.x = pack2(f[0], f[1]);
            u.y = pack2(f[2], f[3]);
            u.z = pack2(f[4], f[5]);
            u.w = pack2(f[6], f[7]);
            *reinterpret_cast<uint4*>(base + off) = u;
        }
    }
}

// =========================================================================
// Local windowed attention (wmma, no-max softmax) + pool sums + gn partials
// =========================================================================
__global__ void __launch_bounds__(128) local_attn_w_kernel(
    const __nv_bfloat16* __restrict__ qkvB, const float* __restrict__ x,
    float* __restrict__ attn, float* __restrict__ praw, float* __restrict__ part) {
    __shared__ __align__(16) __nv_bfloat16 QP[64 * 72];
    __shared__ __align__(16) __nv_bfloat16 Ks[64 * 72];
    __shared__ __align__(16) __nv_bfloat16 Vs[64 * 72];
    __shared__ __align__(16) float Sf[64 * 68];
    __shared__ float linv[64];
    __shared__ float rs[4], rss[4];

    int w = blockIdx.x, head = blockIdx.y, n = blockIdx.z;
    int tid = threadIdx.x, warp = tid >> 5;

    size_t base = (((size_t)(n * 3) * 4 + head) * 512 + w) * 4096;
    size_t step = (size_t)4 * 512 * 4096;
    const uint4* Qg = (const uint4*)(qkvB + base);
    const uint4* Kg = (const uint4*)(qkvB + base + step);
    const uint4* Vg = (const uint4*)(qkvB + base + 2 * step);

    #pragma unroll
    for (int i = 0; i < 4; i++) {
        int c = tid + i * 128;
        int r = c >> 3, q = c & 7;
        ((uint4*)(QP + r * 72))[q] = Qg[c];
        ((uint4*)(Ks + r * 72))[q] = Kg[c];
        ((uint4*)(Vs + r * 72))[q] = Vg[c];
    }
    __syncthreads();

    {
        int m = warp * 16;
        wmma::fragment<wmma::accumulator, 16, 16, 16, float> acc[4];
        #pragma unroll
        for (int j = 0; j < 4; j++) wmma::fill_fragment(acc[j], 0.f);
        #pragma unroll
        for (int kd = 0; kd < 4; kd++) {
            wmma::fragment<wmma::matrix_a, 16, 16, 16, __nv_bfloat16, wmma::row_major> af;
            wmma::load_matrix_sync(af, QP + m * 72 + kd * 16, 72);
            #pragma unroll
            for (int j = 0; j < 4; j++) {
                wmma::fragment<wmma::matrix_b, 16, 16, 16, __nv_bfloat16, wmma::col_major> bf;
                wmma::load_matrix_sync(bf, Ks + (j * 16) * 72 + kd * 16, 72);
                wmma::mma_sync(acc[j], af, bf, acc[j]);
            }
        }
        #pragma unroll
        for (int j = 0; j < 4; j++)
            wmma::store_matrix_sync(Sf + m * 68 + j * 16, acc[j], 68, wmma::mem_row_major);
    }
    __syncthreads();

    // softmax without max subtraction (scores tiny; shift-invariant)
    {
        int r = tid >> 1, hf = tid & 1;
        const float* srow = Sf + r * 68 + hf * 32;
        float ls = 0.f;
        __nv_bfloat16* prow = QP + r * 72 + hf * 32;
        #pragma unroll
        for (int j = 0; j < 32; j++) {
            float p = __expf(srow[j]);
            ls += p;
            prow[j] = __float2bfloat16(p);
        }
        ls += __shfl_xor_sync(0xffffffffu, ls, 1);
        if (hf == 0) linv[r] = 1.f / ls;
    }
    __syncthreads();

    {
        int m = warp * 16;
        wmma::fragment<wmma::accumulator, 16, 16, 16, float> acc[4];
        #pragma unroll
        for (int j = 0; j < 4; j++) wmma::fill_fragment(acc[j], 0.f);
        #pragma unroll
        for (int kk = 0; kk < 4; kk++) {
            wmma::fragment<wmma::matrix_a, 16, 16, 16, __nv_bfloat16, wmma::row_major> af;
            wmma::load_matrix_sync(af, QP + m * 72 + kk * 16, 72);
            #pragma unroll
            for (int j = 0; j < 4; j++) {
                wmma::fragment<wmma::matrix_b, 16, 16, 16, __nv_bfloat16, wmma::row_major> bf;
                wmma::load_matrix_sync(bf, Vs + (kk * 16) * 72 + j * 16, 72);
                wmma::mma_sync(acc[j], af, bf, acc[j]);
            }
        }
        #pragma unroll
        for (int j = 0; j < 4; j++)
            wmma::store_matrix_sync(Sf + m * 68 + j * 16, acc[j], 68, wmma::mem_row_major);
    }
    __syncthreads();

    int wh = w >> 6, ww = (w >> 3) & 7, wd = w & 7;
    int base_s = wh * 4096 + ww * 128 + wd * 4;
    int chb = n * 256 + head * 64;
    float s_acc = 0.f, ss_acc = 0.f;
    #pragma unroll
    for (int it = 0; it < 8; it++) {
        int idx = tid + it * 128;
        int d = idx >> 4, tg = idx & 15;
        int i_ = tg >> 2, j_ = tg & 3;
        int s = base_s + i_ * 1024 + j_ * 32;
        int t0 = tg * 4;
        size_t g = ((size_t)(chb + d)) * SV + s;
        float4 xv = *reinterpret_cast<const float4*>(x + g);
        float4 ov;
        ov.x = fmaf(Sf[(t0 + 0) * 68 + d], linv[t0 + 0], xv.x);
        ov.y = fmaf(Sf[(t0 + 1) * 68 + d], linv[t0 + 1], xv.y);
        ov.z = fmaf(Sf[(t0 + 2) * 68 + d], linv[t0 + 2], xv.z);
        ov.w = fmaf(Sf[(t0 + 3) * 68 + d], linv[t0 + 3], xv.w);
        *reinterpret_cast<float4*>(attn + g) = ov;
        float ps = ov.x + ov.y + ov.z + ov.w;
        s_acc  += ps;
        ss_acc += ov.x*ov.x + ov.y*ov.y + ov.z*ov.z + ov.w*ov.w;
        #pragma unroll
        for (int o = 8; o; o >>= 1) ps += __shfl_down_sync(0xffffffffu, ps, o);
        if ((tid & 15) == 0)
            praw[((size_t)(chb + d)) * 512 + w] = ps * (1.f / 64.f);
    }
    #pragma unroll
    for (int o = 16; o; o >>= 1) {
        s_acc  += __shfl_down_sync(0xffffffffu, s_acc, o);
        ss_acc += __shfl_down_sync(0xffffffffu, ss_acc, o);
    }
    if ((tid & 31) == 0) { rs[warp] = s_acc; rss[warp] = ss_acc; }
    __syncthreads();
    if (tid == 0) {
        size_t pi = (size_t)n * 2048 + head * 512 + w;
        part[pi * 2 + 0] = rs[0] + rs[1] + rs[2] + rs[3];
        part[pi * 2 + 1] = rss[0] + rss[1] + rss[2] + rss[3];
    }
}

// =========================================================================
// Global attention: no-max softmax, O persistent in accumulators
// =========================================================================
#define GA_SMEM 90624

__global__ void __launch_bounds__(256, 2) gattn_kernel(
    const __nv_bfloat16* __restrict__ q2T, const __nv_bfloat16* __restrict__ kvT,
    const float* __restrict__ attn,
    const float* __restrict__ A1, const float* __restrict__ D1,
    __nv_bfloat16* __restrict__ ghi, __nv_bfloat16* __restrict__ glo) {
    extern __shared__ __align__(16) char sm[];
    __nv_bfloat16* Qs = (__nv_bfloat16*)sm;
    __nv_bfloat16* Ks = Qs + 128 * 72;
    __nv_bfloat16* Vs = Ks + 64 * 72;
    __nv_bfloat16* Ps = Vs + 64 * 72;
    float* Sf   = (float*)(Ps + 128 * 72);
    float* lrow = Sf + 128 * 68;

    int tid = threadIdx.x, warp = tid >> 5;
    int h = blockIdx.y, n = blockIdx.z;
    int s0 = blockIdx.x * 128;

    const uint4* Qg = (const uint4*)(q2T + ((size_t)(n * 4 + h) * SV + s0) * 64);
    const uint4* Kg = (const uint4*)(kvT + ((size_t)(n * 8 + h) * 512) * 64);
    const uint4* Vg = (const uint4*)(kvT + ((size_t)(n * 8 + 4 + h) * 512) * 64);

    #pragma unroll
    for (int i = 0; i < 4; i++) {
        int idx = tid + i * 256;
        int r = idx >> 3, c = idx & 7;
        ((uint4*)(Qs + r * 72))[c] = Qg[r * 8 + c];
    }
    if (tid < 128) lrow[tid] = 0.f;

    int pm = warp >> 1, pn = warp & 1;
    wmma::fragment<wmma::accumulator, 16, 16, 16, float> acc_o[2][2];
    #pragma unroll
    for (int i = 0; i < 2; i++)
        #pragma unroll
        for (int j = 0; j < 2; j++) wmma::fill_fragment(acc_o[i][j], 0.f);

    for (int ch = 0; ch < 8; ch++) {
        __syncthreads();
        #pragma unroll
        for (int i = 0; i < 2; i++) {
            int idx = tid + i * 256;
            int r = idx >> 3, c = idx & 7;
            ((uint4*)(Ks + r * 72))[c] = Kg[(ch * 64 + r) * 8 + c];
            ((uint4*)(Vs + r * 72))[c] = Vg[(ch * 64 + r) * 8 + c];
        }
        __syncthreads();

        {
            int m = warp * 16;
            wmma::fragment<wmma::accumulator, 16, 16, 16, float> acc[4];
            #pragma unroll
            for (int j = 0; j < 4; j++) wmma::fill_fragment(acc[j], 0.f);
            #pragma unroll
            for (int kd = 0; kd < 4; kd++) {
                wmma::fragment<wmma::matrix_a, 16, 16, 16, __nv_bfloat16, wmma::row_major> af;
                wmma::load_matrix_sync(af, Qs + m * 72 + kd * 16, 72);
                #pragma unroll
                for (int j = 0; j < 4; j++) {
                    wmma::fragment<wmma::matrix_b, 16, 16, 16, __nv_bfloat16, wmma::col_major> bf;
                    wmma::load_matrix_sync(bf, Ks + (j * 16) * 72 + kd * 16, 72);
                    wmma::mma_sync(acc[j], af, bf, acc[j]);
                }
            }
            #pragma unroll
            for (int j = 0; j < 4; j++)
                wmma::store_matrix_sync(Sf + m * 68 + j * 16, acc[j], 68, wmma::mem_row_major);
        }
        __syncthreads();

        {
            int r = tid >> 1, hf = tid & 1;
            const float* srow = Sf + r * 68 + hf * 32;
            float ls = 0.f;
            __nv_bfloat16* prow = Ps + r * 72 + hf * 32;
            #pragma unroll
            for (int j = 0; j < 32; j++) {
                float p = __expf(srow[j]);
                ls += p;
                prow[j] = __float2bfloat16(p);
            }
            ls += __shfl_xor_sync(0xffffffffu, ls, 1);
            if (hf == 0) lrow[r] += ls;
        }
        __syncthreads();

        {
            #pragma unroll
            for (int kk = 0; kk < 4; kk++) {
                wmma::fragment<wmma::matrix_a, 16, 16, 16, __nv_bfloat16, wmma::row_major> af[2];
                #pragma unroll
                for (int i = 0; i < 2; i++)
                    wmma::load_matrix_sync(af[i], Ps + (pm * 32 + i * 16) * 72 + kk * 16, 72);
                wmma::fragment<wmma::matrix_b, 16, 16, 16, __nv_bfloat16, wmma::row_major> bf[2];
                #pragma unroll
                for (int j = 0; j < 2; j++)
                    wmma::load_matrix_sync(bf[j], Vs + (kk * 16) * 72 + pn * 32 + j * 16, 72);
                #pragma unroll
                for (int i = 0; i < 2; i++)
                    #pragma unroll
                    for (int j = 0; j < 2; j++)
                        wmma::mma_sync(acc_o[i][j], af[i], bf[j], acc_o[i][j]);
            }
        }
    }

    __syncthreads();
    #pragma unroll
    for (int i = 0; i < 2; i++)
        #pragma unroll
        for (int j = 0; j < 2; j++)
            wmma::store_matrix_sync(Sf + (pm * 32 + i * 16) * 68 + pn * 32 + j * 16,
                                    acc_o[i][j], 68, wmma::mem_row_major);
    __syncthreads();

    #pragma unroll
    for (int i = 0; i < 32; i++) {
        int idx = tid + i * 256;
        int r = idx & 127, d = idx >> 7;
        int cch = n * 256 + h * 64 + d;
        float v = Sf[r * 68 + d] / lrow[r];
        size_t gi = ((size_t)cch) * SV + s0 + r;
        float t = v + fmaf(A1[cch], attn[gi], D1[cch]);
        __nv_bfloat16 hi = __float2bfloat16(t);
        ghi[gi] = hi;
        glo[gi] = __float2bfloat16(t - __bfloat162float(hi));
    }
}

// =========================================================================
// host launch
// =========================================================================
extern "C" void kernel_launch(void* const* d_in, const int* in_sizes, int n_in,
                              void* d_out, int out_size) {
    const float* x      = (const float*)d_in[0];
    const float* qkv_w  = (const float*)d_in[1];
    const float* qkv_b  = (const float*)d_in[2];
    const float* norm_w = (const float*)d_in[3];
    const float* norm_b = (const float*)d_in[4];
    const float* anorm_w= (const float*)d_in[5];
    const float* anorm_b= (const float*)d_in[6];
    const float* dnorm_w= (const float*)d_in[7];
    const float* dnorm_b= (const float*)d_in[8];
    const float* q_w    = (const float*)d_in[9];
    const float* q_b    = (const float*)d_in[10];
    const float* kv_w   = (const float*)d_in[11];
    const float* kv_b   = (const float*)d_in[12];
    const float* proj_w = (const float*)d_in[13];
    const float* proj_b = (const float*)d_in[14];
    float* out = (float*)d_out;

    float *attn, *praw, *pnorm, *part, *aff;
    __nv_bfloat16 *xnB, *qkvB, *attnB, *ghi, *glo, *pooledB, *q2T, *kvT;
    __nv_bfloat16 *WqkvB, *WqB, *WkvB, *WprojB;
    cudaGetSymbolAddress((void**)&attn,    g_attn);
    cudaGetSymbolAddress((void**)&praw,    g_praw);
    cudaGetSymbolAddress((void**)&pnorm,   g_pnorm);
    cudaGetSymbolAddress((void**)&xnB,     g_xnB);
    cudaGetSymbolAddress((void**)&qkvB,    g_qkvB);
    cudaGetSymbolAddress((void**)&attnB,   g_attnB);
    cudaGetSymbolAddress((void**)&ghi,     g_ghi);
    cudaGetSymbolAddress((void**)&glo,     g_glo);
    cudaGetSymbolAddress((void**)&pooledB, g_pooledB);
    cudaGetSymbolAddress((void**)&q2T,     g_q2T);
    cudaGetSymbolAddress((void**)&kvT,     g_kvT);
    cudaGetSymbolAddress((void**)&WqkvB,   g_WqkvB);
    cudaGetSymbolAddress((void**)&WqB,     g_WqB);
    cudaGetSymbolAddress((void**)&WkvB,    g_WkvB);
    cudaGetSymbolAddress((void**)&WprojB,  g_WprojB);
    cudaGetSymbolAddress((void**)&part,    g_part);
    cudaGetSymbolAddress((void**)&aff,     g_aff);

    static bool attr_set = false;
    if (!attr_set) {
        cudaFuncSetAttribute(gattn_kernel, cudaFuncAttributeMaxDynamicSharedMemorySize, GA_SMEM);
        cudaFuncSetAttribute(wgemm3_kernel<0>, cudaFuncAttributeMaxDynamicSharedMemorySize, WG_SMEM);
        cudaFuncSetAttribute(wgemm3_kernel<1>, cudaFuncAttributeMaxDynamicSharedMemorySize, WG_SMEM);
        cudaFuncSetAttribute(wgemm3_kernel<2>, cudaFuncAttributeMaxDynamicSharedMemorySize, WG_SMEM);
        attr_set = true;
    }

    float* A0 = aff;        float* D0 = aff + 512;
    float* A1 = aff + 1024; float* D1 = aff + 1536;
    float* A2 = aff + 2048; float* D2 = aff + 2560;

    convert_weights_kernel<<<2304, 256>>>(qkv_w, q_w, kv_w, proj_w,
                                          WqkvB, WqB, WkvB, WprojB);

    // GroupNorm(x) -> bf16 normed x
    reduce1_kernel<<<dim3(512, NB), 256>>>(x, 256L * SV, part);
    stats2affine_kernel<<<NB, 256>>>(part, 512, norm_w, norm_b, A0, D0, 1.f / (256.f * 32768.f));
    convert_x_kernel<<<16384, 256>>>(x, A0, D0, xnB);

    // qkv conv -> window-gathered bf16 (q pre-scaled 1/16)
    wgemm3_kernel<2><<<dim3(6, 256, NB), 256, WG_SMEM>>>(
        WqkvB, xnB, xnB, qkv_b, nullptr, qkvB, 768, (int)SV, 256, SCALE_INV);

    // local attention: attn(raw) + pooled sums + gn partials
    local_attn_w_kernel<<<dim3(512, NH, NB), 128>>>(qkvB, x, attn, praw, part);

    // anorm affine from fused partials
    stats2affine_kernel<<<NB, 256>>>(part, 2048, anorm_w, anorm_b, A1, D1, 1.f / (256.f * 32768.f));

    // attnB = bf16(anorm(attn))
    convert_x_kernel<<<16384, 256>>>(attn, A1, D1, attnB);

    // pooled: affine -> ds-norm stats -> bf16
    apply_pool_affine_kernel<<<256, 256>>>(praw, A1, D1, pnorm);
    reduce1_kernel<<<dim3(32, NB), 256>>>(pnorm, 256L * 512, part);
    stats2affine_kernel<<<NB, 256>>>(part, 32, dnorm_w, dnorm_b, A2, D2, 1.f / (256.f * 512.f));
    convert_pooled_kernel<<<256, 256>>>(pnorm, A2, D2, pooledB);

    // kv conv -> kvT, q conv -> q2T (scaled 1/16)
    wgemm3_kernel<1><<<dim3(4, 4, NB), 256, WG_SMEM>>>(
        WkvB, pooledB, pooledB, kv_b, nullptr, kvT, 512, 512, 256, 1.f);
    wgemm3_kernel<1><<<dim3(2, 256, NB), 256, WG_SMEM>>>(
        WqB, attnB, attnB, q_b, nullptr, q2T, 256, (int)SV, 256, SCALE_INV);

    // global attention + affine residual -> bf16 hi/lo
    gattn_kernel<<<dim3(256, NH, NB), 256, GA_SMEM>>>(q2T, kvT, attn, A1, D1, ghi, glo);

    // final projection (3-term bf16 split) -> out
    wgemm3_kernel<0><<<dim3(2, 256, NB), 256, WG_SMEM>>>(
        WprojB, ghi, glo, proj_b, out, nullptr, 256, (int)SV, 768, 1.f);
}

// round 9
// speedup vs baseline: 1.3152x; 1.0363x over previous
#include <cuda_runtime.h>
#include <cuda_bf16.h>
#include <mma.h>
#include <math.h>
#include <stdint.h>

using namespace nvcuda;

#define NB 2
#define CH 256
#define SV 32768L
#define NH 4
#define HD 64
#define SCALE_INV 0.0625f
#define EPS 1e-6f

__device__ __forceinline__ unsigned pack2(float a, float b) {
    __nv_bfloat162 t = __floats2bfloat162_rn(a, b);
    return *reinterpret_cast<unsigned*>(&t);
}

// ---------------- scratch ----------------
__device__ __align__(16) float g_attn   [NB * 256L * SV];   // x + local attn (raw)
__device__ __align__(16) float g_praw   [NB * 256 * 512];
__device__ __align__(16) float g_pnorm  [NB * 256 * 512];
__device__ __align__(16) __nv_bfloat16 g_xnB   [NB * 256L * SV];
__device__ __align__(16) __nv_bfloat16 g_qkvB  [NB * 768L * SV];
__device__ __align__(16) __nv_bfloat16 g_attnB [NB * 256L * SV];
__device__ __align__(16) __nv_bfloat16 g_ghi   [NB * 256L * SV];
__device__ __align__(16) __nv_bfloat16 g_glo   [NB * 256L * SV];
__device__ __align__(16) __nv_bfloat16 g_pooledB[NB * 256 * 512];
__device__ __align__(16) __nv_bfloat16 g_q2T   [NB * 4L * SV * 64];
__device__ __align__(16) __nv_bfloat16 g_kvT   [NB * 8L * 512 * 64];
__device__ __align__(16) __nv_bfloat16 g_WqkvB [768 * 256];
__device__ __align__(16) __nv_bfloat16 g_WqB   [256 * 256];
__device__ __align__(16) __nv_bfloat16 g_WkvB  [512 * 256];
__device__ __align__(16) __nv_bfloat16 g_WprojB[256 * 768];
__device__ float g_part [NB * 2048 * 2];
__device__ float g_aff  [6 * NB * 256];

// ---------------- cp.async ----------------
__device__ __forceinline__ void cp16(void* dst, const void* src) {
    unsigned d = (unsigned)__cvta_generic_to_shared(dst);
    asm volatile("cp.async.cg.shared.global [%0], [%1], 16;\n" :: "r"(d), "l"(src));
}
#define CP_COMMIT asm volatile("cp.async.commit_group;\n" ::: "memory")
#define CP_WAIT1  asm volatile("cp.async.wait_group 1;\n" ::: "memory")
#define CP_WAIT0  asm volatile("cp.async.wait_group 0;\n" ::: "memory")

// =========================================================================
// reductions / affine / conversions
// =========================================================================
__global__ void reduce1_kernel(const float* __restrict__ buf, long per, float* __restrict__ part) {
    int n = blockIdx.y;
    const float* p = buf + (size_t)n * per;
    float s = 0.f, ss = 0.f;
    for (long i = (long)blockIdx.x * blockDim.x + threadIdx.x; i < per;
         i += (long)gridDim.x * blockDim.x) {
        float v = p[i];
        s += v; ss += v * v;
    }
    for (int o = 16; o; o >>= 1) {
        s  += __shfl_down_sync(0xffffffffu, s, o);
        ss += __shfl_down_sync(0xffffffffu, ss, o);
    }
    __shared__ float sh[64];
    int w = threadIdx.x >> 5;
    if ((threadIdx.x & 31) == 0) { sh[w] = s; sh[32 + w] = ss; }
    __syncthreads();
    if (threadIdx.x < 32) {
        int nw = blockDim.x >> 5;
        s  = (threadIdx.x < nw) ? sh[threadIdx.x]      : 0.f;
        ss = (threadIdx.x < nw) ? sh[32 + threadIdx.x] : 0.f;
        for (int o = 16; o; o >>= 1) {
            s  += __shfl_down_sync(0xffffffffu, s, o);
            ss += __shfl_down_sync(0xffffffffu, ss, o);
        }
        if (threadIdx.x == 0) {
            part[((size_t)n * gridDim.x + blockIdx.x) * 2 + 0] = s;
            part[((size_t)n * gridDim.x + blockIdx.x) * 2 + 1] = ss;
        }
    }
}

// merged reduce2 + make_affine: one block per sample, 256 threads
__global__ void stats2affine_kernel(const float* __restrict__ part, int nb,
                                    const float* __restrict__ w, const float* __restrict__ b,
                                    float* __restrict__ a, float* __restrict__ d,
                                    float inv_cnt) {
    int n = blockIdx.x, tid = threadIdx.x;
    float s = 0.f, ss = 0.f;
    for (int i = tid; i < nb; i += 256) {
        s  += part[((size_t)n * nb + i) * 2 + 0];
        ss += part[((size_t)n * nb + i) * 2 + 1];
    }
    for (int o = 16; o; o >>= 1) {
        s  += __shfl_down_sync(0xffffffffu, s, o);
        ss += __shfl_down_sync(0xffffffffu, ss, o);
    }
    __shared__ float sh[16];
    __shared__ float sm_mean, sm_rstd;
    int wp = tid >> 5;
    if ((tid & 31) == 0) { sh[wp] = s; sh[8 + wp] = ss; }
    __syncthreads();
    if (tid < 32) {
        s  = (tid < 8) ? sh[tid]     : 0.f;
        ss = (tid < 8) ? sh[8 + tid] : 0.f;
        for (int o = 4; o; o >>= 1) {
            s  += __shfl_down_sync(0xffffffffu, s, o);
            ss += __shfl_down_sync(0xffffffffu, ss, o);
        }
        if (tid == 0) {
            float mean = s * inv_cnt;
            float var  = ss * inv_cnt - mean * mean;
            sm_mean = mean;
            sm_rstd = rsqrtf(var + EPS);
        }
    }
    __syncthreads();
    float mean = sm_mean, rstd = sm_rstd;
    a[n * CH + tid] = w[tid] * rstd;
    d[n * CH + tid] = b[tid] - mean * rstd * w[tid];
}

__global__ void convert_x_kernel(const float* __restrict__ x,
                                 const float* __restrict__ a, const float* __restrict__ d,
                                 __nv_bfloat16* __restrict__ out) {
    size_t i4 = (size_t)blockIdx.x * blockDim.x + threadIdx.x;
    int c = (int)((i4 >> 13) & 255);
    int n = (int)(i4 >> 21);
    float aa = a[n * CH + c], dd = d[n * CH + c];
    float4 v = reinterpret_cast<const float4*>(x)[i4];
    uint2 r;
    r.x = pack2(fmaf(aa, v.x, dd), fmaf(aa, v.y, dd));
    r.y = pack2(fmaf(aa, v.z, dd), fmaf(aa, v.w, dd));
    reinterpret_cast<uint2*>(out)[i4] = r;
}

__global__ void apply_pool_affine_kernel(const float* __restrict__ praw,
                                         const float* __restrict__ a, const float* __restrict__ d,
                                         float* __restrict__ pnorm) {
    size_t i4 = (size_t)blockIdx.x * blockDim.x + threadIdx.x;
    int c = (int)((i4 >> 7) & 255);
    int n = (int)(i4 >> 15);
    float aa = a[n * CH + c], dd = d[n * CH + c];
    float4 v = reinterpret_cast<const float4*>(praw)[i4];
    v.x = fmaf(aa, v.x, dd); v.y = fmaf(aa, v.y, dd);
    v.z = fmaf(aa, v.z, dd); v.w = fmaf(aa, v.w, dd);
    reinterpret_cast<float4*>(pnorm)[i4] = v;
}

__global__ void convert_pooled_kernel(const float* __restrict__ pooled,
                                      const float* __restrict__ a, const float* __restrict__ d,
                                      __nv_bfloat16* __restrict__ out) {
    size_t i4 = (size_t)blockIdx.x * blockDim.x + threadIdx.x;
    int c = (int)((i4 >> 7) & 255);
    int n = (int)(i4 >> 15);
    float aa = a[n * CH + c], dd = d[n * CH + c];
    float4 v = reinterpret_cast<const float4*>(pooled)[i4];
    uint2 r;
    r.x = pack2(fmaf(aa, v.x, dd), fmaf(aa, v.y, dd));
    r.y = pack2(fmaf(aa, v.z, dd), fmaf(aa, v.w, dd));
    reinterpret_cast<uint2*>(out)[i4] = r;
}

__global__ void convert_weights_kernel(
    const float* __restrict__ qkv_w, const float* __restrict__ q_w,
    const float* __restrict__ kv_w, const float* __restrict__ proj_w,
    __nv_bfloat16* __restrict__ Wqkv, __nv_bfloat16* __restrict__ Wq,
    __nv_bfloat16* __restrict__ Wkv, __nv_bfloat16* __restrict__ Wproj) {
    int idx = blockIdx.x * blockDim.x + threadIdx.x;
    const int T1 = 768 * 256, T2 = T1 + 256 * 256, T3 = T2 + 512 * 256, T4 = T3 + 256 * 768;
    if (idx < T1) {
        Wqkv[idx] = __float2bfloat16(qkv_w[idx]);
    } else if (idx < T2) {
        int j = idx - T1; Wq[j] = __float2bfloat16(q_w[j]);
    } else if (idx < T3) {
        int j = idx - T2; Wkv[j] = __float2bfloat16(kv_w[j]);
    } else if (idx < T4) {
        int j = idx - T3;
        int m = j / 768, k = j % 768;
        float v = proj_w[m * 256 + (k & 255)];
        __nv_bfloat16 hi = __float2bfloat16(v);
        if (k >= 256 && k < 512) hi = __float2bfloat16(v - __bfloat162float(hi));
        Wproj[j] = hi;
    }
}

// =========================================================================
// wgemm3: BM=128, BN=128, BK=32, 3-stage cp.async, 256 threads.
// MODE 1/2 epilogue: col-major Cs staging + dim-major lane mapping for
// fully coalesced bf16 stores.
// =========================================================================
#define WG_SMEM 69632

template<int MODE>
__global__ void __launch_bounds__(256) wgemm3_kernel(
    const __nv_bfloat16* __restrict__ A,
    const __nv_bfloat16* __restrict__ B0, const __nv_bfloat16* __restrict__ B1,
    const float* __restrict__ bias,
    float* __restrict__ outF, __nv_bfloat16* __restrict__ outB,
    int M, int S, int KT, float qScale) {
    extern __shared__ __align__(16) char dsm[];
    __nv_bfloat16* As = (__nv_bfloat16*)dsm;
    __nv_bfloat16* Bs = (__nv_bfloat16*)(dsm + 30720);
    float* Cs = (float*)dsm;

    int tid = threadIdx.x, warp = tid >> 5;
    int wm = warp >> 2, wn = warp & 3;
    int m0 = blockIdx.x * 128;
    int s0 = blockIdx.y * 128;
    int z  = blockIdx.z;

    const __nv_bfloat16* Bb0 = B0 + (size_t)z * 256 * S;
    const __nv_bfloat16* Bb1 = B1 + (size_t)z * 256 * S;

    wmma::fragment<wmma::accumulator, 16, 16, 16, float> acc[4][2];
    #pragma unroll
    for (int i = 0; i < 4; i++)
        #pragma unroll
        for (int j = 0; j < 2; j++) wmma::fill_fragment(acc[i][j], 0.f);

    const int NIT = KT >> 5;

    auto prefetch = [&](int it, int buf) {
        int ktL = it * 32;
        #pragma unroll
        for (int i = 0; i < 2; i++) {
            int c = tid + i * 256;
            int r = c >> 2, q = (c & 3) * 8;
            cp16(As + buf * 5120 + r * 40 + q,
                 A + (size_t)(m0 + r) * KT + ktL + q);
        }
        const __nv_bfloat16* Bp = (ktL < 512) ? Bb0 : Bb1;
        int krow = ktL & 255;
        #pragma unroll
        for (int i = 0; i < 2; i++) {
            int c = tid + i * 256;
            int r = c >> 4, q = (c & 15) * 8;
            cp16(Bs + buf * 4352 + r * 136 + q,
                 Bp + (size_t)(krow + r) * S + s0 + q);
        }
    };

    prefetch(0, 0); CP_COMMIT;
    prefetch(1, 1); CP_COMMIT;

    int buf = 0;
    for (int it = 0; it < NIT; it++) {
        if (it + 1 < NIT) CP_WAIT1; else CP_WAIT0;
        __syncthreads();
        #pragma unroll
        for (int ks = 0; ks < 2; ks++) {
            wmma::fragment<wmma::matrix_a, 16, 16, 16, __nv_bfloat16, wmma::row_major> af[4];
            #pragma unroll
            for (int i = 0; i < 4; i++)
                wmma::load_matrix_sync(af[i], As + buf * 5120 + (wm * 64 + i * 16) * 40 + ks * 16, 40);
            wmma::fragment<wmma::matrix_b, 16, 16, 16, __nv_bfloat16, wmma::row_major> bf[2];
            #pragma unroll
            for (int j = 0; j < 2; j++)
                wmma::load_matrix_sync(bf[j], Bs + buf * 4352 + (ks * 16) * 136 + wn * 32 + j * 16, 136);
            #pragma unroll
            for (int i = 0; i < 4; i++)
                #pragma unroll
                for (int j = 0; j < 2; j++)
                    wmma::mma_sync(acc[i][j], af[i], bf[j], acc[i][j]);
        }
        if (it + 2 < NIT) {
            prefetch(it + 2, (buf + 2) % 3);
            CP_COMMIT;
        }
        buf = (buf + 1) % 3;
    }

    __syncthreads();

    if (MODE == 0) {
        // row-major staging [dim][token], stride 132
        #pragma unroll
        for (int i = 0; i < 4; i++)
            #pragma unroll
            for (int j = 0; j < 2; j++)
                wmma::store_matrix_sync(Cs + (wm * 64 + i * 16) * 132 + wn * 32 + j * 16,
                                        acc[i][j], 132, wmma::mem_row_major);
        __syncthreads();
        float* Ob = outF + ((size_t)z * M + m0) * S;
        #pragma unroll
        for (int it = 0; it < 16; it++) {
            int idx = tid + it * 256;
            int r = idx >> 5, c4 = idx & 31;
            float bv = bias[m0 + r];
            float4 v = *reinterpret_cast<const float4*>(&Cs[r * 132 + c4 * 4]);
            v.x += bv; v.y += bv; v.z += bv; v.w += bv;
            *reinterpret_cast<float4*>(&Ob[(size_t)r * S + s0 + c4 * 4]) = v;
        }
    } else {
        // col-major staging: Cs[token][dim], stride 136
        #pragma unroll
        for (int i = 0; i < 4; i++)
            #pragma unroll
            for (int j = 0; j < 2; j++)
                wmma::store_matrix_sync(Cs + (wn * 32 + j * 16) * 136 + wm * 64 + i * 16,
                                        acc[i][j], 136, wmma::mem_col_major);
        __syncthreads();

        int dg = tid & 15;                 // dim-group: dims m0 + dg*8 .. +7
        int gmb = m0 + dg * 8;
        float bias8[8];
        #pragma unroll
        for (int e = 0; e < 8; e++) bias8[e] = bias[gmb + e];

        float sc;
        int db = gmb & 63;
        __nv_bfloat16* hbase;
        if (MODE == 1) {
            int hb = gmb >> 6;
            sc = qScale;
            hbase = outB + ((size_t)(z * (M >> 6) + hb) * S + s0) * 64 + db;
        } else {
            int sel = gmb >> 8, head = (gmb >> 6) & 3;
            sc = (sel == 0) ? qScale : 1.f;
            hbase = outB + (((size_t)(z * 3 + sel) * 4 + head) * 512) * 4096 + db;
        }

        #pragma unroll
        for (int it = 0; it < 8; it++) {
            int sl = it * 16 + (tid >> 4);
            float4 lo = *reinterpret_cast<const float4*>(&Cs[sl * 136 + dg * 8]);
            float4 hi = *reinterpret_cast<const float4*>(&Cs[sl * 136 + dg * 8 + 4]);
            float f[8] = {lo.x, lo.y, lo.z, lo.w, hi.x, hi.y, hi.z, hi.w};
            #pragma unroll
            for (int e = 0; e < 8; e++) f[e] = (f[e] + bias8[e]) * sc;
            uint4 u;
            u.x = pack2(f[0], f[1]);
            u.y = pack2(f[2], f[3]);
            u.z = pack2(f[4], f[5]);
            u.w = pack2(f[6], f[7]);
            size_t off;
            if (MODE == 1) {
                off = (size_t)sl * 64;
            } else {
                int s = s0 + sl;
                int d5 = s & 31, w5 = (s >> 5) & 31, h5 = s >> 10;
                int window = ((h5 >> 2) * 8 + (w5 >> 2)) * 8 + (d5 >> 2);
                int token  = (((h5 & 3) * 4 + (w5 & 3)) * 4 + (d5 & 3));
                off = (size_t)window * 4096 + token * 64;
            }
            *reinterpret_cast<uint4*>(hbase + off) = u;
        }
    }
}

// =========================================================================
// Local windowed attention (wmma, no-max softmax) + pool sums + gn partials
// =========================================================================
__global__ void __launch_bounds__(128) local_attn_w_kernel(
    const __nv_bfloat16* __restrict__ qkvB, const float* __restrict__ x,
    float* __restrict__ attn, float* __restrict__ praw, float* __restrict__ part) {
    __shared__ __align__(16) __nv_bfloat16 QP[64 * 72];
    __shared__ __align__(16) __nv_bfloat16 Ks[64 * 72];
    __shared__ __align__(16) __nv_bfloat16 Vs[64 * 72];
    __shared__ __align__(16) float Sf[64 * 68];
    __shared__ float linv[64];
    __shared__ float rs[4], rss[4];

    int w = blockIdx.x, head = blockIdx.y, n = blockIdx.z;
    int tid = threadIdx.x, warp = tid >> 5;

    size_t base = (((size_t)(n * 3) * 4 + head) * 512 + w) * 4096;
    size_t step = (size_t)4 * 512 * 4096;
    const uint4* Qg = (const uint4*)(qkvB + base);
    const uint4* Kg = (const uint4*)(qkvB + base + step);
    const uint4* Vg = (const uint4*)(qkvB + base + 2 * step);

    #pragma unroll
    for (int i = 0; i < 4; i++) {
        int c = tid + i * 128;
        int r = c >> 3, q = c & 7;
        ((uint4*)(QP + r * 72))[q] = Qg[c];
        ((uint4*)(Ks + r * 72))[q] = Kg[c];
        ((uint4*)(Vs + r * 72))[q] = Vg[c];
    }
    __syncthreads();

    {
        int m = warp * 16;
        wmma::fragment<wmma::accumulator, 16, 16, 16, float> acc[4];
        #pragma unroll
        for (int j = 0; j < 4; j++) wmma::fill_fragment(acc[j], 0.f);
        #pragma unroll
        for (int kd = 0; kd < 4; kd++) {
            wmma::fragment<wmma::matrix_a, 16, 16, 16, __nv_bfloat16, wmma::row_major> af;
            wmma::load_matrix_sync(af, QP + m * 72 + kd * 16, 72);
            #pragma unroll
            for (int j = 0; j < 4; j++) {
                wmma::fragment<wmma::matrix_b, 16, 16, 16, __nv_bfloat16, wmma::col_major> bf;
                wmma::load_matrix_sync(bf, Ks + (j * 16) * 72 + kd * 16, 72);
                wmma::mma_sync(acc[j], af, bf, acc[j]);
            }
        }
        #pragma unroll
        for (int j = 0; j < 4; j++)
            wmma::store_matrix_sync(Sf + m * 68 + j * 16, acc[j], 68, wmma::mem_row_major);
    }
    __syncthreads();

    // softmax without max subtraction (scores tiny; shift-invariant)
    {
        int r = tid >> 1, hf = tid & 1;
        const float* srow = Sf + r * 68 + hf * 32;
        float ls = 0.f;
        __nv_bfloat16* prow = QP + r * 72 + hf * 32;
        #pragma unroll
        for (int j = 0; j < 32; j++) {
            float p = __expf(srow[j]);
            ls += p;
            prow[j] = __float2bfloat16(p);
        }
        ls += __shfl_xor_sync(0xffffffffu, ls, 1);
        if (hf == 0) linv[r] = 1.f / ls;
    }
    __syncthreads();

    {
        int m = warp * 16;
        wmma::fragment<wmma::accumulator, 16, 16, 16, float> acc[4];
        #pragma unroll
        for (int j = 0; j < 4; j++) wmma::fill_fragment(acc[j], 0.f);
        #pragma unroll
        for (int kk = 0; kk < 4; kk++) {
            wmma::fragment<wmma::matrix_a, 16, 16, 16, __nv_bfloat16, wmma::row_major> af;
            wmma::load_matrix_sync(af, QP + m * 72 + kk * 16, 72);
            #pragma unroll
            for (int j = 0; j < 4; j++) {
                wmma::fragment<wmma::matrix_b, 16, 16, 16, __nv_bfloat16, wmma::row_major> bf;
                wmma::load_matrix_sync(bf, Vs + (kk * 16) * 72 + j * 16, 72);
                wmma::mma_sync(acc[j], af, bf, acc[j]);
            }
        }
        #pragma unroll
        for (int j = 0; j < 4; j++)
            wmma::store_matrix_sync(Sf + m * 68 + j * 16, acc[j], 68, wmma::mem_row_major);
    }
    __syncthreads();

    int wh = w >> 6, ww = (w >> 3) & 7, wd = w & 7;
    int base_s = wh * 4096 + ww * 128 + wd * 4;
    int chb = n * 256 + head * 64;
    float s_acc = 0.f, ss_acc = 0.f;
    #pragma unroll
    for (int it = 0; it < 8; it++) {
        int idx = tid + it * 128;
        int d = idx >> 4, tg = idx & 15;
        int i_ = tg >> 2, j_ = tg & 3;
        int s = base_s + i_ * 1024 + j_ * 32;
        int t0 = tg * 4;
        size_t g = ((size_t)(chb + d)) * SV + s;
        float4 xv = *reinterpret_cast<const float4*>(x + g);
        float4 ov;
        ov.x = fmaf(Sf[(t0 + 0) * 68 + d], linv[t0 + 0], xv.x);
        ov.y = fmaf(Sf[(t0 + 1) * 68 + d], linv[t0 + 1], xv.y);
        ov.z = fmaf(Sf[(t0 + 2) * 68 + d], linv[t0 + 2], xv.z);
        ov.w = fmaf(Sf[(t0 + 3) * 68 + d], linv[t0 + 3], xv.w);
        *reinterpret_cast<float4*>(attn + g) = ov;
        float ps = ov.x + ov.y + ov.z + ov.w;
        s_acc  += ps;
        ss_acc += ov.x*ov.x + ov.y*ov.y + ov.z*ov.z + ov.w*ov.w;
        #pragma unroll
        for (int o = 8; o; o >>= 1) ps += __shfl_down_sync(0xffffffffu, ps, o);
        if ((tid & 15) == 0)
            praw[((size_t)(chb + d)) * 512 + w] = ps * (1.f / 64.f);
    }
    #pragma unroll
    for (int o = 16; o; o >>= 1) {
        s_acc  += __shfl_down_sync(0xffffffffu, s_acc, o);
        ss_acc += __shfl_down_sync(0xffffffffu, ss_acc, o);
    }
    if ((tid & 31) == 0) { rs[warp] = s_acc; rss[warp] = ss_acc; }
    __syncthreads();
    if (tid == 0) {
        size_t pi = (size_t)n * 2048 + head * 512 + w;
        part[pi * 2 + 0] = rs[0] + rs[1] + rs[2] + rs[3];
        part[pi * 2 + 1] = rss[0] + rss[1] + rss[2] + rss[3];
    }
}

// =========================================================================
// Global attention: no-max softmax, O persistent in accumulators,
// cp.async double-buffered K/V (3 syncs/chunk).
// =========================================================================
#define GA_SMEM 109056

__global__ void __launch_bounds__(256, 2) gattn_kernel(
    const __nv_bfloat16* __restrict__ q2T, const __nv_bfloat16* __restrict__ kvT,
    const float* __restrict__ attn,
    const float* __restrict__ A1, const float* __restrict__ D1,
    __nv_bfloat16* __restrict__ ghi, __nv_bfloat16* __restrict__ glo) {
    extern __shared__ __align__(16) char sm[];
    __nv_bfloat16* Qs = (__nv_bfloat16*)sm;          // [128][72]
    __nv_bfloat16* Ks = Qs + 128 * 72;               // 2 x [64][72]
    __nv_bfloat16* Vs = Ks + 2 * 64 * 72;            // 2 x [64][72]
    __nv_bfloat16* Ps = Vs + 2 * 64 * 72;            // [128][72]
    float* Sf   = (float*)(Ps + 128 * 72);           // [128][68]
    float* lrow = Sf + 128 * 68;                     // [128]

    int tid = threadIdx.x, warp = tid >> 5;
    int h = blockIdx.y, n = blockIdx.z;
    int s0 = blockIdx.x * 128;

    const uint4* Qg = (const uint4*)(q2T + ((size_t)(n * 4 + h) * SV + s0) * 64);
    const __nv_bfloat16* Kg = kvT + ((size_t)(n * 8 + h) * 512) * 64;
    const __nv_bfloat16* Vg = kvT + ((size_t)(n * 8 + 4 + h) * 512) * 64;

    auto prefetchKV = [&](int ch, int b) {
        #pragma unroll
        for (int i = 0; i < 2; i++) {
            int idx = tid + i * 256;
            int r = idx >> 3, c = (idx & 7) * 8;
            cp16(Ks + b * 4608 + r * 72 + c, Kg + (size_t)(ch * 64 + r) * 64 + c);
            cp16(Vs + b * 4608 + r * 72 + c, Vg + (size_t)(ch * 64 + r) * 64 + c);
        }
    };

    prefetchKV(0, 0); CP_COMMIT;

    #pragma unroll
    for (int i = 0; i < 4; i++) {
        int idx = tid + i * 256;
        int r = idx >> 3, c = idx & 7;
        ((uint4*)(Qs + r * 72))[c] = Qg[r * 8 + c];
    }
    if (tid < 128) lrow[tid] = 0.f;

    int pm = warp >> 1, pn = warp & 1;
    wmma::fragment<wmma::accumulator, 16, 16, 16, float> acc_o[2][2];
    #pragma unroll
    for (int i = 0; i < 2; i++)
        #pragma unroll
        for (int j = 0; j < 2; j++) wmma::fill_fragment(acc_o[i][j], 0.f);

    for (int ch = 0; ch < 8; ch++) {
        int b = ch & 1;
        CP_WAIT0;
        __syncthreads();   // KV[b] ready; prev PV done; Qs/lrow ready on ch=0

        // S = Q @ K^T : each warp 16 rows x 64 keys
        {
            int m = warp * 16;
            wmma::fragment<wmma::accumulator, 16, 16, 16, float> acc[4];
            #pragma unroll
            for (int j = 0; j < 4; j++) wmma::fill_fragment(acc[j], 0.f);
            #pragma unroll
            for (int kd = 0; kd < 4; kd++) {
                wmma::fragment<wmma::matrix_a, 16, 16, 16, __nv_bfloat16, wmma::row_major> af;
                wmma::load_matrix_sync(af, Qs + m * 72 + kd * 16, 72);
                #pragma unroll
                for (int j = 0; j < 4; j++) {
                    wmma::fragment<wmma::matrix_b, 16, 16, 16, __nv_bfloat16, wmma::col_major> bf;
                    wmma::load_matrix_sync(bf, Ks + b * 4608 + (j * 16) * 72 + kd * 16, 72);
                    wmma::mma_sync(acc[j], af, bf, acc[j]);
                }
            }
            #pragma unroll
            for (int j = 0; j < 4; j++)
                wmma::store_matrix_sync(Sf + m * 68 + j * 16, acc[j], 68, wmma::mem_row_major);
        }
        __syncthreads();

        // softmax-lite: p = exp(s), accumulate row sums
        {
            int r = tid >> 1, hf = tid & 1;
            const float* srow = Sf + r * 68 + hf * 32;
            float ls = 0.f;
            __nv_bfloat16* prow = Ps + r * 72 + hf * 32;
            #pragma unroll
            for (int j = 0; j < 32; j++) {
                float p = __expf(srow[j]);
                ls += p;
                prow[j] = __float2bfloat16(p);
            }
            ls += __shfl_xor_sync(0xffffffffu, ls, 1);
            if (hf == 0) lrow[r] += ls;
        }
        __syncthreads();

        // prefetch next chunk's K/V into the other buffer (safe: its last
        // readers finished before this chunk's top sync)
        if (ch + 1 < 8) {
            prefetchKV(ch + 1, b ^ 1);
            CP_COMMIT;
        }

        // O += P @ V (persistent accumulators)
        {
            #pragma unroll
            for (int kk = 0; kk < 4; kk++) {
                wmma::fragment<wmma::matrix_a, 16, 16, 16, __nv_bfloat16, wmma::row_major> af[2];
                #pragma unroll
                for (int i = 0; i < 2; i++)
                    wmma::load_matrix_sync(af[i], Ps + (pm * 32 + i * 16) * 72 + kk * 16, 72);
                wmma::fragment<wmma::matrix_b, 16, 16, 16, __nv_bfloat16, wmma::row_major> bf[2];
                #pragma unroll
                for (int j = 0; j < 2; j++)
                    wmma::load_matrix_sync(bf[j], Vs + b * 4608 + (kk * 16) * 72 + pn * 32 + j * 16, 72);
                #pragma unroll
                for (int i = 0; i < 2; i++)
                    #pragma unroll
                    for (int j = 0; j < 2; j++)
                        wmma::mma_sync(acc_o[i][j], af[i], bf[j], acc_o[i][j]);
            }
        }
    }

    __syncthreads();
    #pragma unroll
    for (int i = 0; i < 2; i++)
        #pragma unroll
        for (int j = 0; j < 2; j++)
            wmma::store_matrix_sync(Sf + (pm * 32 + i * 16) * 68 + pn * 32 + j * 16,
                                    acc_o[i][j], 68, wmma::mem_row_major);
    __syncthreads();

    #pragma unroll
    for (int i = 0; i < 32; i++) {
        int idx = tid + i * 256;
        int r = idx & 127, d = idx >> 7;
        int cch = n * 256 + h * 64 + d;
        float v = Sf[r * 68 + d] / lrow[r];
        size_t gi = ((size_t)cch) * SV + s0 + r;
        float t = v + fmaf(A1[cch], attn[gi], D1[cch]);
        __nv_bfloat16 hi = __float2bfloat16(t);
        ghi[gi] = hi;
        glo[gi] = __float2bfloat16(t - __bfloat162float(hi));
    }
}

// =========================================================================
// host launch
// =========================================================================
extern "C" void kernel_launch(void* const* d_in, const int* in_sizes, int n_in,
                              void* d_out, int out_size) {
    const float* x      = (const float*)d_in[0];
    const float* qkv_w  = (const float*)d_in[1];
    const float* qkv_b  = (const float*)d_in[2];
    const float* norm_w = (const float*)d_in[3];
    const float* norm_b = (const float*)d_in[4];
    const float* anorm_w= (const float*)d_in[5];
    const float* anorm_b= (const float*)d_in[6];
    const float* dnorm_w= (const float*)d_in[7];
    const float* dnorm_b= (const float*)d_in[8];
    const float* q_w    = (const float*)d_in[9];
    const float* q_b    = (const float*)d_in[10];
    const float* kv_w   = (const float*)d_in[11];
    const float* kv_b   = (const float*)d_in[12];
    const float* proj_w = (const float*)d_in[13];
    const float* proj_b = (const float*)d_in[14];
    float* out = (float*)d_out;

    float *attn, *praw, *pnorm, *part, *aff;
    __nv_bfloat16 *xnB, *qkvB, *attnB, *ghi, *glo, *pooledB, *q2T, *kvT;
    __nv_bfloat16 *WqkvB, *WqB, *WkvB, *WprojB;
    cudaGetSymbolAddress((void**)&attn,    g_attn);
    cudaGetSymbolAddress((void**)&praw,    g_praw);
    cudaGetSymbolAddress((void**)&pnorm,   g_pnorm);
    cudaGetSymbolAddress((void**)&xnB,     g_xnB);
    cudaGetSymbolAddress((void**)&qkvB,    g_qkvB);
    cudaGetSymbolAddress((void**)&attnB,   g_attnB);
    cudaGetSymbolAddress((void**)&ghi,     g_ghi);
    cudaGetSymbolAddress((void**)&glo,     g_glo);
    cudaGetSymbolAddress((void**)&pooledB, g_pooledB);
    cudaGetSymbolAddress((void**)&q2T,     g_q2T);
    cudaGetSymbolAddress((void**)&kvT,     g_kvT);
    cudaGetSymbolAddress((void**)&WqkvB,   g_WqkvB);
    cudaGetSymbolAddress((void**)&WqB,     g_WqB);
    cudaGetSymbolAddress((void**)&WkvB,    g_WkvB);
    cudaGetSymbolAddress((void**)&WprojB,  g_WprojB);
    cudaGetSymbolAddress((void**)&part,    g_part);
    cudaGetSymbolAddress((void**)&aff,     g_aff);

    static bool attr_set = false;
    if (!attr_set) {
        cudaFuncSetAttribute(gattn_kernel, cudaFuncAttributeMaxDynamicSharedMemorySize, GA_SMEM);
        cudaFuncSetAttribute(wgemm3_kernel<0>, cudaFuncAttributeMaxDynamicSharedMemorySize, WG_SMEM);
        cudaFuncSetAttribute(wgemm3_kernel<1>, cudaFuncAttributeMaxDynamicSharedMemorySize, WG_SMEM);
        cudaFuncSetAttribute(wgemm3_kernel<2>, cudaFuncAttributeMaxDynamicSharedMemorySize, WG_SMEM);
        attr_set = true;
    }

    float* A0 = aff;        float* D0 = aff + 512;
    float* A1 = aff + 1024; float* D1 = aff + 1536;
    float* A2 = aff + 2048; float* D2 = aff + 2560;

    convert_weights_kernel<<<2304, 256>>>(qkv_w, q_w, kv_w, proj_w,
                                          WqkvB, WqB, WkvB, WprojB);

    // GroupNorm(x) -> bf16 normed x
    reduce1_kernel<<<dim3(512, NB), 256>>>(x, 256L * SV, part);
    stats2affine_kernel<<<NB, 256>>>(part, 512, norm_w, norm_b, A0, D0, 1.f / (256.f * 32768.f));
    convert_x_kernel<<<16384, 256>>>(x, A0, D0, xnB);

    // qkv conv -> window-gathered bf16 (q pre-scaled 1/16)
    wgemm3_kernel<2><<<dim3(6, 256, NB), 256, WG_SMEM>>>(
        WqkvB, xnB, xnB, qkv_b, nullptr, qkvB, 768, (int)SV, 256, SCALE_INV);

    // local attention: attn(raw) + pooled sums + gn partials
    local_attn_w_kernel<<<dim3(512, NH, NB), 128>>>(qkvB, x, attn, praw, part);

    // anorm affine from fused partials
    stats2affine_kernel<<<NB, 256>>>(part, 2048, anorm_w, anorm_b, A1, D1, 1.f / (256.f * 32768.f));

    // attnB = bf16(anorm(attn))
    convert_x_kernel<<<16384, 256>>>(attn, A1, D1, attnB);

    // pooled: affine -> ds-norm stats -> bf16
    apply_pool_affine_kernel<<<256, 256>>>(praw, A1, D1, pnorm);
    reduce1_kernel<<<dim3(32, NB), 256>>>(pnorm, 256L * 512, part);
    stats2affine_kernel<<<NB, 256>>>(part, 32, dnorm_w, dnorm_b, A2, D2, 1.f / (256.f * 512.f));
    convert_pooled_kernel<<<256, 256>>>(pnorm, A2, D2, pooledB);

    // kv conv -> kvT, q conv -> q2T (scaled 1/16)
    wgemm3_kernel<1><<<dim3(4, 4, NB), 256, WG_SMEM>>>(
        WkvB, pooledB, pooledB, kv_b, nullptr, kvT, 512, 512, 256, 1.f);
    wgemm3_kernel<1><<<dim3(2, 256, NB), 256, WG_SMEM>>>(
        WqB, attnB, attnB, q_b, nullptr, q2T, 256, (int)SV, 256, SCALE_INV);

    // global attention + affine residual -> bf16 hi/lo
    gattn_kernel<<<dim3(256, NH, NB), 256, GA_SMEM>>>(q2T, kvT, attn, A1, D1, ghi, glo);

    // final projection (3-term bf16 split) -> out
    wgemm3_kernel<0><<<dim3(2, 256, NB), 256, WG_SMEM>>>(
        WprojB, ghi, glo, proj_b, out, nullptr, 256, (int)SV, 768, 1.f);
}

// round 10
// speedup vs baseline: 1.3172x; 1.0015x over previous
#include <cuda_runtime.h>
#include <cuda_bf16.h>
#include <mma.h>
#include <math.h>
#include <stdint.h>

using namespace nvcuda;

#define NB 2
#define CH 256
#define SV 32768L
#define NH 4
#define HD 64
#define SCALE_INV 0.0625f
#define EPS 1e-6f

__device__ __forceinline__ unsigned pack2(float a, float b) {
    __nv_bfloat162 t = __floats2bfloat162_rn(a, b);
    return *reinterpret_cast<unsigned*>(&t);
}

// ---------------- scratch ----------------
__device__ __align__(16) float g_attn   [NB * 256L * SV];   // x + local attn (raw)
__device__ __align__(16) float g_praw   [NB * 256 * 512];
__device__ __align__(16) float g_pnorm  [NB * 256 * 512];
__device__ __align__(16) __nv_bfloat16 g_xnB   [NB * 256L * SV];
__device__ __align__(16) __nv_bfloat16 g_qkvB  [NB * 768L * SV];
__device__ __align__(16) __nv_bfloat16 g_attnB [NB * 256L * SV];
__device__ __align__(16) __nv_bfloat16 g_ghi   [NB * 256L * SV];
__device__ __align__(16) __nv_bfloat16 g_glo   [NB * 256L * SV];
__device__ __align__(16) __nv_bfloat16 g_pooledB[NB * 256 * 512];
__device__ __align__(16) __nv_bfloat16 g_q2T   [NB * 4L * SV * 64];
__device__ __align__(16) __nv_bfloat16 g_kvT   [NB * 8L * 512 * 64];
__device__ __align__(16) __nv_bfloat16 g_WqkvB [768 * 256];
__device__ __align__(16) __nv_bfloat16 g_WqB   [256 * 256];
__device__ __align__(16) __nv_bfloat16 g_WkvB  [512 * 256];
__device__ __align__(16) __nv_bfloat16 g_WprojB[256 * 768];
__device__ float g_part [NB * 2048 * 2];
__device__ float g_part2[NB * 64 * 2];
__device__ float g_aff  [6 * NB * 256];

// ---------------- cp.async ----------------
__device__ __forceinline__ void cp16(void* dst, const void* src) {
    unsigned d = (unsigned)__cvta_generic_to_shared(dst);
    asm volatile("cp.async.cg.shared.global [%0], [%1], 16;\n" :: "r"(d), "l"(src));
}
#define CP_COMMIT asm volatile("cp.async.commit_group;\n" ::: "memory")
#define CP_WAIT1  asm volatile("cp.async.wait_group 1;\n" ::: "memory")
#define CP_WAIT0  asm volatile("cp.async.wait_group 0;\n" ::: "memory")

// =========================================================================
// reductions / affine / conversions
// =========================================================================
__global__ void reduce1_kernel(const float* __restrict__ buf, long per, float* __restrict__ part) {
    int n = blockIdx.y;
    const float* p = buf + (size_t)n * per;
    float s = 0.f, ss = 0.f;
    for (long i = (long)blockIdx.x * blockDim.x + threadIdx.x; i < per;
         i += (long)gridDim.x * blockDim.x) {
        float v = p[i];
        s += v; ss += v * v;
    }
    for (int o = 16; o; o >>= 1) {
        s  += __shfl_down_sync(0xffffffffu, s, o);
        ss += __shfl_down_sync(0xffffffffu, ss, o);
    }
    __shared__ float sh[64];
    int w = threadIdx.x >> 5;
    if ((threadIdx.x & 31) == 0) { sh[w] = s; sh[32 + w] = ss; }
    __syncthreads();
    if (threadIdx.x < 32) {
        int nw = blockDim.x >> 5;
        s  = (threadIdx.x < nw) ? sh[threadIdx.x]      : 0.f;
        ss = (threadIdx.x < nw) ? sh[32 + threadIdx.x] : 0.f;
        for (int o = 16; o; o >>= 1) {
            s  += __shfl_down_sync(0xffffffffu, s, o);
            ss += __shfl_down_sync(0xffffffffu, ss, o);
        }
        if (threadIdx.x == 0) {
            part[((size_t)n * gridDim.x + blockIdx.x) * 2 + 0] = s;
            part[((size_t)n * gridDim.x + blockIdx.x) * 2 + 1] = ss;
        }
    }
}

// merged reduce2 + make_affine: one block per sample, 256 threads
__global__ void stats2affine_kernel(const float* __restrict__ part, int nb,
                                    const float* __restrict__ w, const float* __restrict__ b,
                                    float* __restrict__ a, float* __restrict__ d,
                                    float inv_cnt) {
    int n = blockIdx.x, tid = threadIdx.x;
    float s = 0.f, ss = 0.f;
    for (int i = tid; i < nb; i += 256) {
        s  += part[((size_t)n * nb + i) * 2 + 0];
        ss += part[((size_t)n * nb + i) * 2 + 1];
    }
    for (int o = 16; o; o >>= 1) {
        s  += __shfl_down_sync(0xffffffffu, s, o);
        ss += __shfl_down_sync(0xffffffffu, ss, o);
    }
    __shared__ float sh[16];
    __shared__ float sm_mean, sm_rstd;
    int wp = tid >> 5;
    if ((tid & 31) == 0) { sh[wp] = s; sh[8 + wp] = ss; }
    __syncthreads();
    if (tid < 32) {
        s  = (tid < 8) ? sh[tid]     : 0.f;
        ss = (tid < 8) ? sh[8 + tid] : 0.f;
        for (int o = 4; o; o >>= 1) {
            s  += __shfl_down_sync(0xffffffffu, s, o);
            ss += __shfl_down_sync(0xffffffffu, ss, o);
        }
        if (tid == 0) {
            float mean = s * inv_cnt;
            float var  = ss * inv_cnt - mean * mean;
            sm_mean = mean;
            sm_rstd = rsqrtf(var + EPS);
        }
    }
    __syncthreads();
    float mean = sm_mean, rstd = sm_rstd;
    a[n * CH + tid] = w[tid] * rstd;
    d[n * CH + tid] = b[tid] - mean * rstd * w[tid];
}

__global__ void convert_x_kernel(const float* __restrict__ x,
                                 const float* __restrict__ a, const float* __restrict__ d,
                                 __nv_bfloat16* __restrict__ out) {
    size_t i4 = (size_t)blockIdx.x * blockDim.x + threadIdx.x;
    int c = (int)((i4 >> 13) & 255);
    int n = (int)(i4 >> 21);
    float aa = a[n * CH + c], dd = d[n * CH + c];
    float4 v = reinterpret_cast<const float4*>(x)[i4];
    uint2 r;
    r.x = pack2(fmaf(aa, v.x, dd), fmaf(aa, v.y, dd));
    r.y = pack2(fmaf(aa, v.z, dd), fmaf(aa, v.w, dd));
    reinterpret_cast<uint2*>(out)[i4] = r;
}

__global__ void apply_pool_affine_kernel(const float* __restrict__ praw,
                                         const float* __restrict__ a, const float* __restrict__ d,
                                         float* __restrict__ pnorm) {
    size_t i4 = (size_t)blockIdx.x * blockDim.x + threadIdx.x;
    int c = (int)((i4 >> 7) & 255);
    int n = (int)(i4 >> 15);
    float aa = a[n * CH + c], dd = d[n * CH + c];
    float4 v = reinterpret_cast<const float4*>(praw)[i4];
    v.x = fmaf(aa, v.x, dd); v.y = fmaf(aa, v.y, dd);
    v.z = fmaf(aa, v.z, dd); v.w = fmaf(aa, v.w, dd);
    reinterpret_cast<float4*>(pnorm)[i4] = v;
}

__global__ void convert_pooled_kernel(const float* __restrict__ pooled,
                                      const float* __restrict__ a, const float* __restrict__ d,
                                      __nv_bfloat16* __restrict__ out) {
    size_t i4 = (size_t)blockIdx.x * blockDim.x + threadIdx.x;
    int c = (int)((i4 >> 7) & 255);
    int n = (int)(i4 >> 15);
    float aa = a[n * CH + c], dd = d[n * CH + c];
    float4 v = reinterpret_cast<const float4*>(pooled)[i4];
    uint2 r;
    r.x = pack2(fmaf(aa, v.x, dd), fmaf(aa, v.y, dd));
    r.y = pack2(fmaf(aa, v.z, dd), fmaf(aa, v.w, dd));
    reinterpret_cast<uint2*>(out)[i4] = r;
}

__global__ void convert_weights_kernel(
    const float* __restrict__ qkv_w, const float* __restrict__ q_w,
    const float* __restrict__ kv_w, const float* __restrict__ proj_w,
    __nv_bfloat16* __restrict__ Wqkv, __nv_bfloat16* __restrict__ Wq,
    __nv_bfloat16* __restrict__ Wkv, __nv_bfloat16* __restrict__ Wproj) {
    int idx = blockIdx.x * blockDim.x + threadIdx.x;
    const int T1 = 768 * 256, T2 = T1 + 256 * 256, T3 = T2 + 512 * 256, T4 = T3 + 256 * 768;
    if (idx < T1) {
        Wqkv[idx] = __float2bfloat16(qkv_w[idx]);
    } else if (idx < T2) {
        int j = idx - T1; Wq[j] = __float2bfloat16(q_w[j]);
    } else if (idx < T3) {
        int j = idx - T2; Wkv[j] = __float2bfloat16(kv_w[j]);
    } else if (idx < T4) {
        int j = idx - T3;
        int m = j / 768, k = j % 768;
        float v = proj_w[m * 256 + (k & 255)];
        __nv_bfloat16 hi = __float2bfloat16(v);
        if (k >= 256 && k < 512) hi = __float2bfloat16(v - __bfloat162float(hi));
        Wproj[j] = hi;
    }
}

// =========================================================================
// wgemm3: BM=128, BN=128, BK=32, 3-stage cp.async, 256 threads.
// MODE 1/2 epilogue: col-major Cs staging + dim-major lane mapping for
// fully coalesced bf16 stores.
// =========================================================================
#define WG_SMEM 69632

template<int MODE>
__global__ void __launch_bounds__(256) wgemm3_kernel(
    const __nv_bfloat16* __restrict__ A,
    const __nv_bfloat16* __restrict__ B0, const __nv_bfloat16* __restrict__ B1,
    const float* __restrict__ bias,
    float* __restrict__ outF, __nv_bfloat16* __restrict__ outB,
    int M, int S, int KT, float qScale) {
    extern __shared__ __align__(16) char dsm[];
    __nv_bfloat16* As = (__nv_bfloat16*)dsm;
    __nv_bfloat16* Bs = (__nv_bfloat16*)(dsm + 30720);
    float* Cs = (float*)dsm;

    int tid = threadIdx.x, warp = tid >> 5;
    int wm = warp >> 2, wn = warp & 3;
    int m0 = blockIdx.x * 128;
    int s0 = blockIdx.y * 128;
    int z  = blockIdx.z;

    const __nv_bfloat16* Bb0 = B0 + (size_t)z * 256 * S;
    const __nv_bfloat16* Bb1 = B1 + (size_t)z * 256 * S;

    wmma::fragment<wmma::accumulator, 16, 16, 16, float> acc[4][2];
    #pragma unroll
    for (int i = 0; i < 4; i++)
        #pragma unroll
        for (int j = 0; j < 2; j++) wmma::fill_fragment(acc[i][j], 0.f);

    const int NIT = KT >> 5;

    auto prefetch = [&](int it, int buf) {
        int ktL = it * 32;
        #pragma unroll
        for (int i = 0; i < 2; i++) {
            int c = tid + i * 256;
            int r = c >> 2, q = (c & 3) * 8;
            cp16(As + buf * 5120 + r * 40 + q,
                 A + (size_t)(m0 + r) * KT + ktL + q);
        }
        const __nv_bfloat16* Bp = (ktL < 512) ? Bb0 : Bb1;
        int krow = ktL & 255;
        #pragma unroll
        for (int i = 0; i < 2; i++) {
            int c = tid + i * 256;
            int r = c >> 4, q = (c & 15) * 8;
            cp16(Bs + buf * 4352 + r * 136 + q,
                 Bp + (size_t)(krow + r) * S + s0 + q);
        }
    };

    prefetch(0, 0); CP_COMMIT;
    prefetch(1, 1); CP_COMMIT;

    int buf = 0;
    for (int it = 0; it < NIT; it++) {
        if (it + 1 < NIT) CP_WAIT1; else CP_WAIT0;
        __syncthreads();
        #pragma unroll
        for (int ks = 0; ks < 2; ks++) {
            wmma::fragment<wmma::matrix_a, 16, 16, 16, __nv_bfloat16, wmma::row_major> af[4];
            #pragma unroll
            for (int i = 0; i < 4; i++)
                wmma::load_matrix_sync(af[i], As + buf * 5120 + (wm * 64 + i * 16) * 40 + ks * 16, 40);
            wmma::fragment<wmma::matrix_b, 16, 16, 16, __nv_bfloat16, wmma::row_major> bf[2];
            #pragma unroll
            for (int j = 0; j < 2; j++)
                wmma::load_matrix_sync(bf[j], Bs + buf * 4352 + (ks * 16) * 136 + wn * 32 + j * 16, 136);
            #pragma unroll
            for (int i = 0; i < 4; i++)
                #pragma unroll
                for (int j = 0; j < 2; j++)
                    wmma::mma_sync(acc[i][j], af[i], bf[j], acc[i][j]);
        }
        if (it + 2 < NIT) {
            prefetch(it + 2, (buf + 2) % 3);
            CP_COMMIT;
        }
        buf = (buf + 1) % 3;
    }

    __syncthreads();

    if (MODE == 0) {
        #pragma unroll
        for (int i = 0; i < 4; i++)
            #pragma unroll
            for (int j = 0; j < 2; j++)
                wmma::store_matrix_sync(Cs + (wm * 64 + i * 16) * 132 + wn * 32 + j * 16,
                                        acc[i][j], 132, wmma::mem_row_major);
        __syncthreads();
        float* Ob = outF + ((size_t)z * M + m0) * S;
        #pragma unroll
        for (int it = 0; it < 16; it++) {
            int idx = tid + it * 256;
            int r = idx >> 5, c4 = idx & 31;
            float bv = bias[m0 + r];
            float4 v = *reinterpret_cast<const float4*>(&Cs[r * 132 + c4 * 4]);
            v.x += bv; v.y += bv; v.z += bv; v.w += bv;
            *reinterpret_cast<float4*>(&Ob[(size_t)r * S + s0 + c4 * 4]) = v;
        }
    } else {
        #pragma unroll
        for (int i = 0; i < 4; i++)
            #pragma unroll
            for (int j = 0; j < 2; j++)
                wmma::store_matrix_sync(Cs + (wn * 32 + j * 16) * 136 + wm * 64 + i * 16,
                                        acc[i][j], 136, wmma::mem_col_major);
        __syncthreads();

        int dg = tid & 15;
        int gmb = m0 + dg * 8;
        float bias8[8];
        #pragma unroll
        for (int e = 0; e < 8; e++) bias8[e] = bias[gmb + e];

        float sc;
        int db = gmb & 63;
        __nv_bfloat16* hbase;
        if (MODE == 1) {
            int hb = gmb >> 6;
            sc = qScale;
            hbase = outB + ((size_t)(z * (M >> 6) + hb) * S + s0) * 64 + db;
        } else {
            int sel = gmb >> 8, head = (gmb >> 6) & 3;
            sc = (sel == 0) ? qScale : 1.f;
            hbase = outB + (((size_t)(z * 3 + sel) * 4 + head) * 512) * 4096 + db;
        }

        #pragma unroll
        for (int it = 0; it < 8; it++) {
            int sl = it * 16 + (tid >> 4);
            float4 lo = *reinterpret_cast<const float4*>(&Cs[sl * 136 + dg * 8]);
            float4 hi = *reinterpret_cast<const float4*>(&Cs[sl * 136 + dg * 8 + 4]);
            float f[8] = {lo.x, lo.y, lo.z, lo.w, hi.x, hi.y, hi.z, hi.w};
            #pragma unroll
            for (int e = 0; e < 8; e++) f[e] = (f[e] + bias8[e]) * sc;
            uint4 u;
            u.x = pack2(f[0], f[1]);
            u.y = pack2(f[2], f[3]);
            u.z = pack2(f[4], f[5]);
            u.w = pack2(f[6], f[7]);
            size_t off;
            if (MODE == 1) {
                off = (size_t)sl * 64;
            } else {
                int s = s0 + sl;
                int d5 = s & 31, w5 = (s >> 5) & 31, h5 = s >> 10;
                int window = ((h5 >> 2) * 8 + (w5 >> 2)) * 8 + (d5 >> 2);
                int token  = (((h5 & 3) * 4 + (w5 & 3)) * 4 + (d5 & 3));
                off = (size_t)window * 4096 + token * 64;
            }
            *reinterpret_cast<uint4*>(hbase + off) = u;
        }
    }
}

// =========================================================================
// Local windowed attention (wmma, no-max softmax) + pool sums + gn partials
// =========================================================================
__global__ void __launch_bounds__(128) local_attn_w_kernel(
    const __nv_bfloat16* __restrict__ qkvB, const float* __restrict__ x,
    float* __restrict__ attn, float* __restrict__ praw, float* __restrict__ part) {
    __shared__ __align__(16) __nv_bfloat16 QP[64 * 72];
    __shared__ __align__(16) __nv_bfloat16 Ks[64 * 72];
    __shared__ __align__(16) __nv_bfloat16 Vs[64 * 72];
    __shared__ __align__(16) float Sf[64 * 68];
    __shared__ float linv[64];
    __shared__ float rs[4], rss[4];

    int w = blockIdx.x, head = blockIdx.y, n = blockIdx.z;
    int tid = threadIdx.x, warp = tid >> 5;

    size_t base = (((size_t)(n * 3) * 4 + head) * 512 + w) * 4096;
    size_t step = (size_t)4 * 512 * 4096;
    const uint4* Qg = (const uint4*)(qkvB + base);
    const uint4* Kg = (const uint4*)(qkvB + base + step);
    const uint4* Vg = (const uint4*)(qkvB + base + 2 * step);

    #pragma unroll
    for (int i = 0; i < 4; i++) {
        int c = tid + i * 128;
        int r = c >> 3, q = c & 7;
        ((uint4*)(QP + r * 72))[q] = Qg[c];
        ((uint4*)(Ks + r * 72))[q] = Kg[c];
        ((uint4*)(Vs + r * 72))[q] = Vg[c];
    }
    __syncthreads();

    {
        int m = warp * 16;
        wmma::fragment<wmma::accumulator, 16, 16, 16, float> acc[4];
        #pragma unroll
        for (int j = 0; j < 4; j++) wmma::fill_fragment(acc[j], 0.f);
        #pragma unroll
        for (int kd = 0; kd < 4; kd++) {
            wmma::fragment<wmma::matrix_a, 16, 16, 16, __nv_bfloat16, wmma::row_major> af;
            wmma::load_matrix_sync(af, QP + m * 72 + kd * 16, 72);
            #pragma unroll
            for (int j = 0; j < 4; j++) {
                wmma::fragment<wmma::matrix_b, 16, 16, 16, __nv_bfloat16, wmma::col_major> bf;
                wmma::load_matrix_sync(bf, Ks + (j * 16) * 72 + kd * 16, 72);
                wmma::mma_sync(acc[j], af, bf, acc[j]);
            }
        }
        #pragma unroll
        for (int j = 0; j < 4; j++)
            wmma::store_matrix_sync(Sf + m * 68 + j * 16, acc[j], 68, wmma::mem_row_major);
    }
    __syncthreads();

    // softmax without max subtraction (scores tiny; shift-invariant)
    {
        int r = tid >> 1, hf = tid & 1;
        const float* srow = Sf + r * 68 + hf * 32;
        float ls = 0.f;
        __nv_bfloat16* prow = QP + r * 72 + hf * 32;
        #pragma unroll
        for (int j = 0; j < 32; j++) {
            float p = __expf(srow[j]);
            ls += p;
            prow[j] = __float2bfloat16(p);
        }
        ls += __shfl_xor_sync(0xffffffffu, ls, 1);
        if (hf == 0) linv[r] = 1.f / ls;
    }
    __syncthreads();

    {
        int m = warp * 16;
        wmma::fragment<wmma::accumulator, 16, 16, 16, float> acc[4];
        #pragma unroll
        for (int j = 0; j < 4; j++) wmma::fill_fragment(acc[j], 0.f);
        #pragma unroll
        for (int kk = 0; kk < 4; kk++) {
            wmma::fragment<wmma::matrix_a, 16, 16, 16, __nv_bfloat16, wmma::row_major> af;
            wmma::load_matrix_sync(af, QP + m * 72 + kk * 16, 72);
            #pragma unroll
            for (int j = 0; j < 4; j++) {
                wmma::fragment<wmma::matrix_b, 16, 16, 16, __nv_bfloat16, wmma::row_major> bf;
                wmma::load_matrix_sync(bf, Vs + (kk * 16) * 72 + j * 16, 72);
                wmma::mma_sync(acc[j], af, bf, acc[j]);
            }
        }
        #pragma unroll
        for (int j = 0; j < 4; j++)
            wmma::store_matrix_sync(Sf + m * 68 + j * 16, acc[j], 68, wmma::mem_row_major);
    }
    __syncthreads();

    int wh = w >> 6, ww = (w >> 3) & 7, wd = w & 7;
    int base_s = wh * 4096 + ww * 128 + wd * 4;
    int chb = n * 256 + head * 64;
    float s_acc = 0.f, ss_acc = 0.f;
    #pragma unroll
    for (int it = 0; it < 8; it++) {
        int idx = tid + it * 128;
        int d = idx >> 4, tg = idx & 15;
        int i_ = tg >> 2, j_ = tg & 3;
        int s = base_s + i_ * 1024 + j_ * 32;
        int t0 = tg * 4;
        size_t g = ((size_t)(chb + d)) * SV + s;
        float4 xv = *reinterpret_cast<const float4*>(x + g);
        float4 ov;
        ov.x = fmaf(Sf[(t0 + 0) * 68 + d], linv[t0 + 0], xv.x);
        ov.y = fmaf(Sf[(t0 + 1) * 68 + d], linv[t0 + 1], xv.y);
        ov.z = fmaf(Sf[(t0 + 2) * 68 + d], linv[t0 + 2], xv.z);
        ov.w = fmaf(Sf[(t0 + 3) * 68 + d], linv[t0 + 3], xv.w);
        *reinterpret_cast<float4*>(attn + g) = ov;
        float ps = ov.x + ov.y + ov.z + ov.w;
        s_acc  += ps;
        ss_acc += ov.x*ov.x + ov.y*ov.y + ov.z*ov.z + ov.w*ov.w;
        #pragma unroll
        for (int o = 8; o; o >>= 1) ps += __shfl_down_sync(0xffffffffu, ps, o);
        if ((tid & 15) == 0)
            praw[((size_t)(chb + d)) * 512 + w] = ps * (1.f / 64.f);
    }
    #pragma unroll
    for (int o = 16; o; o >>= 1) {
        s_acc  += __shfl_down_sync(0xffffffffu, s_acc, o);
        ss_acc += __shfl_down_sync(0xffffffffu, ss_acc, o);
    }
    if ((tid & 31) == 0) { rs[warp] = s_acc; rss[warp] = ss_acc; }
    __syncthreads();
    if (tid == 0) {
        size_t pi = (size_t)n * 2048 + head * 512 + w;
        part[pi * 2 + 0] = rs[0] + rs[1] + rs[2] + rs[3];
        part[pi * 2 + 1] = rss[0] + rss[1] + rss[2] + rss[3];
    }
}

// =========================================================================
// Global attention: no-max softmax, O persistent in accumulators,
// cp.async double-buffered K/V (3 syncs/chunk).
// =========================================================================
#define GA_SMEM 109056

__global__ void __launch_bounds__(256, 2) gattn_kernel(
    const __nv_bfloat16* __restrict__ q2T, const __nv_bfloat16* __restrict__ kvT,
    const float* __restrict__ attn,
    const float* __restrict__ A1, const float* __restrict__ D1,
    __nv_bfloat16* __restrict__ ghi, __nv_bfloat16* __restrict__ glo) {
    extern __shared__ __align__(16) char sm[];
    __nv_bfloat16* Qs = (__nv_bfloat16*)sm;
    __nv_bfloat16* Ks = Qs + 128 * 72;
    __nv_bfloat16* Vs = Ks + 2 * 64 * 72;
    __nv_bfloat16* Ps = Vs + 2 * 64 * 72;
    float* Sf   = (float*)(Ps + 128 * 72);
    float* lrow = Sf + 128 * 68;

    int tid = threadIdx.x, warp = tid >> 5;
    int h = blockIdx.y, n = blockIdx.z;
    int s0 = blockIdx.x * 128;

    const uint4* Qg = (const uint4*)(q2T + ((size_t)(n * 4 + h) * SV + s0) * 64);
    const __nv_bfloat16* Kg = kvT + ((size_t)(n * 8 + h) * 512) * 64;
    const __nv_bfloat16* Vg = kvT + ((size_t)(n * 8 + 4 + h) * 512) * 64;

    auto prefetchKV = [&](int ch, int b) {
        #pragma unroll
        for (int i = 0; i < 2; i++) {
            int idx = tid + i * 256;
            int r = idx >> 3, c = (idx & 7) * 8;
            cp16(Ks + b * 4608 + r * 72 + c, Kg + (size_t)(ch * 64 + r) * 64 + c);
            cp16(Vs + b * 4608 + r * 72 + c, Vg + (size_t)(ch * 64 + r) * 64 + c);
        }
    };

    prefetchKV(0, 0); CP_COMMIT;

    #pragma unroll
    for (int i = 0; i < 4; i++) {
        int idx = tid + i * 256;
        int r = idx >> 3, c = idx & 7;
        ((uint4*)(Qs + r * 72))[c] = Qg[r * 8 + c];
    }
    if (tid < 128) lrow[tid] = 0.f;

    int pm = warp >> 1, pn = warp & 1;
    wmma::fragment<wmma::accumulator, 16, 16, 16, float> acc_o[2][2];
    #pragma unroll
    for (int i = 0; i < 2; i++)
        #pragma unroll
        for (int j = 0; j < 2; j++) wmma::fill_fragment(acc_o[i][j], 0.f);

    for (int ch = 0; ch < 8; ch++) {
        int b = ch & 1;
        CP_WAIT0;
        __syncthreads();

        {
            int m = warp * 16;
            wmma::fragment<wmma::accumulator, 16, 16, 16, float> acc[4];
            #pragma unroll
            for (int j = 0; j < 4; j++) wmma::fill_fragment(acc[j], 0.f);
            #pragma unroll
            for (int kd = 0; kd < 4; kd++) {
                wmma::fragment<wmma::matrix_a, 16, 16, 16, __nv_bfloat16, wmma::row_major> af;
                wmma::load_matrix_sync(af, Qs + m * 72 + kd * 16, 72);
                #pragma unroll
                for (int j = 0; j < 4; j++) {
                    wmma::fragment<wmma::matrix_b, 16, 16, 16, __nv_bfloat16, wmma::col_major> bf;
                    wmma::load_matrix_sync(bf, Ks + b * 4608 + (j * 16) * 72 + kd * 16, 72);
                    wmma::mma_sync(acc[j], af, bf, acc[j]);
                }
            }
            #pragma unroll
            for (int j = 0; j < 4; j++)
                wmma::store_matrix_sync(Sf + m * 68 + j * 16, acc[j], 68, wmma::mem_row_major);
        }
        __syncthreads();

        {
            int r = tid >> 1, hf = tid & 1;
            const float* srow = Sf + r * 68 + hf * 32;
            float ls = 0.f;
            __nv_bfloat16* prow = Ps + r * 72 + hf * 32;
            #pragma unroll
            for (int j = 0; j < 32; j++) {
                float p = __expf(srow[j]);
                ls += p;
                prow[j] = __float2bfloat16(p);
            }
            ls += __shfl_xor_sync(0xffffffffu, ls, 1);
            if (hf == 0) lrow[r] += ls;
        }
        __syncthreads();

        if (ch + 1 < 8) {
            prefetchKV(ch + 1, b ^ 1);
            CP_COMMIT;
        }

        {
            #pragma unroll
            for (int kk = 0; kk < 4; kk++) {
                wmma::fragment<wmma::matrix_a, 16, 16, 16, __nv_bfloat16, wmma::row_major> af[2];
                #pragma unroll
                for (int i = 0; i < 2; i++)
                    wmma::load_matrix_sync(af[i], Ps + (pm * 32 + i * 16) * 72 + kk * 16, 72);
                wmma::fragment<wmma::matrix_b, 16, 16, 16, __nv_bfloat16, wmma::row_major> bf[2];
                #pragma unroll
                for (int j = 0; j < 2; j++)
                    wmma::load_matrix_sync(bf[j], Vs + b * 4608 + (kk * 16) * 72 + pn * 32 + j * 16, 72);
                #pragma unroll
                for (int i = 0; i < 2; i++)
                    #pragma unroll
                    for (int j = 0; j < 2; j++)
                        wmma::mma_sync(acc_o[i][j], af[i], bf[j], acc_o[i][j]);
            }
        }
    }

    __syncthreads();
    #pragma unroll
    for (int i = 0; i < 2; i++)
        #pragma unroll
        for (int j = 0; j < 2; j++)
            wmma::store_matrix_sync(Sf + (pm * 32 + i * 16) * 68 + pn * 32 + j * 16,
                                    acc_o[i][j], 68, wmma::mem_row_major);
    __syncthreads();

    #pragma unroll
    for (int i = 0; i < 32; i++) {
        int idx = tid + i * 256;
        int r = idx & 127, d = idx >> 7;
        int cch = n * 256 + h * 64 + d;
        float v = Sf[r * 68 + d] / lrow[r];
        size_t gi = ((size_t)cch) * SV + s0 + r;
        float t = v + fmaf(A1[cch], attn[gi], D1[cch]);
        __nv_bfloat16 hi = __float2bfloat16(t);
        ghi[gi] = hi;
        glo[gi] = __float2bfloat16(t - __bfloat162float(hi));
    }
}

// =========================================================================
// host launch — event-forked side stream to overlap independent chains
// =========================================================================
extern "C" void kernel_launch(void* const* d_in, const int* in_sizes, int n_in,
                              void* d_out, int out_size) {
    const float* x      = (const float*)d_in[0];
    const float* qkv_w  = (const float*)d_in[1];
    const float* qkv_b  = (const float*)d_in[2];
    const float* norm_w = (const float*)d_in[3];
    const float* norm_b = (const float*)d_in[4];
    const float* anorm_w= (const float*)d_in[5];
    const float* anorm_b= (const float*)d_in[6];
    const float* dnorm_w= (const float*)d_in[7];
    const float* dnorm_b= (const float*)d_in[8];
    const float* q_w    = (const float*)d_in[9];
    const float* q_b    = (const float*)d_in[10];
    const float* kv_w   = (const float*)d_in[11];
    const float* kv_b   = (const float*)d_in[12];
    const float* proj_w = (const float*)d_in[13];
    const float* proj_b = (const float*)d_in[14];
    float* out = (float*)d_out;

    float *attn, *praw, *pnorm, *part, *part2, *aff;
    __nv_bfloat16 *xnB, *qkvB, *attnB, *ghi, *glo, *pooledB, *q2T, *kvT;
    __nv_bfloat16 *WqkvB, *WqB, *WkvB, *WprojB;
    cudaGetSymbolAddress((void**)&attn,    g_attn);
    cudaGetSymbolAddress((void**)&praw,    g_praw);
    cudaGetSymbolAddress((void**)&pnorm,   g_pnorm);
    cudaGetSymbolAddress((void**)&xnB,     g_xnB);
    cudaGetSymbolAddress((void**)&qkvB,    g_qkvB);
    cudaGetSymbolAddress((void**)&attnB,   g_attnB);
    cudaGetSymbolAddress((void**)&ghi,     g_ghi);
    cudaGetSymbolAddress((void**)&glo,     g_glo);
    cudaGetSymbolAddress((void**)&pooledB, g_pooledB);
    cudaGetSymbolAddress((void**)&q2T,     g_q2T);
    cudaGetSymbolAddress((void**)&kvT,     g_kvT);
    cudaGetSymbolAddress((void**)&WqkvB,   g_WqkvB);
    cudaGetSymbolAddress((void**)&WqB,     g_WqB);
    cudaGetSymbolAddress((void**)&WkvB,    g_WkvB);
    cudaGetSymbolAddress((void**)&WprojB,  g_WprojB);
    cudaGetSymbolAddress((void**)&part,    g_part);
    cudaGetSymbolAddress((void**)&part2,   g_part2);
    cudaGetSymbolAddress((void**)&aff,     g_aff);

    static cudaStream_t s1 = nullptr;
    static cudaEvent_t evF1, evJ1, evF2, evJ2;
    static bool init_done = false;
    if (!init_done) {
        cudaFuncSetAttribute(gattn_kernel, cudaFuncAttributeMaxDynamicSharedMemorySize, GA_SMEM);
        cudaFuncSetAttribute(wgemm3_kernel<0>, cudaFuncAttributeMaxDynamicSharedMemorySize, WG_SMEM);
        cudaFuncSetAttribute(wgemm3_kernel<1>, cudaFuncAttributeMaxDynamicSharedMemorySize, WG_SMEM);
        cudaFuncSetAttribute(wgemm3_kernel<2>, cudaFuncAttributeMaxDynamicSharedMemorySize, WG_SMEM);
        cudaStreamCreateWithFlags(&s1, cudaStreamNonBlocking);
        cudaEventCreateWithFlags(&evF1, cudaEventDisableTiming);
        cudaEventCreateWithFlags(&evJ1, cudaEventDisableTiming);
        cudaEventCreateWithFlags(&evF2, cudaEventDisableTiming);
        cudaEventCreateWithFlags(&evJ2, cudaEventDisableTiming);
        init_done = true;
    }

    float* A0 = aff;        float* D0 = aff + 512;
    float* A1 = aff + 1024; float* D1 = aff + 1536;
    float* A2 = aff + 2048; float* D2 = aff + 2560;

    // ---- fork 1: weight conversion ∥ x-norm chain ----
    cudaEventRecord(evF1, 0);
    cudaStreamWaitEvent(s1, evF1, 0);
    convert_weights_kernel<<<2304, 256, 0, s1>>>(qkv_w, q_w, kv_w, proj_w,
                                                 WqkvB, WqB, WkvB, WprojB);
    cudaEventRecord(evJ1, s1);

    reduce1_kernel<<<dim3(512, NB), 256>>>(x, 256L * SV, part);
    stats2affine_kernel<<<NB, 256>>>(part, 512, norm_w, norm_b, A0, D0, 1.f / (256.f * 32768.f));
    convert_x_kernel<<<16384, 256>>>(x, A0, D0, xnB);

    cudaStreamWaitEvent(0, evJ1, 0);   // qkv gemm needs weights + xnB

    // qkv conv -> window-gathered bf16 (q pre-scaled 1/16)
    wgemm3_kernel<2><<<dim3(6, 256, NB), 256, WG_SMEM>>>(
        WqkvB, xnB, xnB, qkv_b, nullptr, qkvB, 768, (int)SV, 256, SCALE_INV);

    // local attention: attn(raw) + pooled sums + gn partials
    local_attn_w_kernel<<<dim3(512, NH, NB), 128>>>(qkvB, x, attn, praw, part);

    // anorm affine from fused partials
    stats2affine_kernel<<<NB, 256>>>(part, 2048, anorm_w, anorm_b, A1, D1, 1.f / (256.f * 32768.f));

    // ---- fork 2: pooled/kv chain ∥ attnB + q gemm ----
    cudaEventRecord(evF2, 0);
    cudaStreamWaitEvent(s1, evF2, 0);
    apply_pool_affine_kernel<<<256, 256, 0, s1>>>(praw, A1, D1, pnorm);
    reduce1_kernel<<<dim3(32, NB), 256, 0, s1>>>(pnorm, 256L * 512, part2);
    stats2affine_kernel<<<NB, 256, 0, s1>>>(part2, 32, dnorm_w, dnorm_b, A2, D2, 1.f / (256.f * 512.f));
    convert_pooled_kernel<<<256, 256, 0, s1>>>(pnorm, A2, D2, pooledB);
    wgemm3_kernel<1><<<dim3(4, 4, NB), 256, WG_SMEM, s1>>>(
        WkvB, pooledB, pooledB, kv_b, nullptr, kvT, 512, 512, 256, 1.f);
    cudaEventRecord(evJ2, s1);

    // main: attnB = bf16(anorm(attn)), then q conv -> q2T (scaled 1/16)
    convert_x_kernel<<<16384, 256>>>(attn, A1, D1, attnB);
    wgemm3_kernel<1><<<dim3(2, 256, NB), 256, WG_SMEM>>>(
        WqB, attnB, attnB, q_b, nullptr, q2T, 256, (int)SV, 256, SCALE_INV);

    cudaStreamWaitEvent(0, evJ2, 0);   // gattn needs kvT + q2T

    // global attention + affine residual -> bf16 hi/lo
    gattn_kernel<<<dim3(256, NH, NB), 256, GA_SMEM>>>(q2T, kvT, attn, A1, D1, ghi, glo);

    // final projection (3-term bf16 split) -> out
    wgemm3_kernel<0><<<dim3(2, 256, NB), 256, WG_SMEM>>>(
        WprojB, ghi, glo, proj_b, out, nullptr, 256, (int)SV, 768, 1.f);
}

// round 11
// speedup vs baseline: 1.3377x; 1.0155x over previous
#include <cuda_runtime.h>
#include <cuda_bf16.h>
#include <mma.h>
#include <math.h>
#include <stdint.h>

using namespace nvcuda;

#define NB 2
#define CH 256
#define SV 32768L
#define NH 4
#define HD 64
#define SCALE_INV 0.0625f
#define EPS 1e-6f

__device__ __forceinline__ unsigned pack2(float a, float b) {
    __nv_bfloat162 t = __floats2bfloat162_rn(a, b);
    return *reinterpret_cast<unsigned*>(&t);
}

// ---------------- scratch ----------------
__device__ __align__(16) float g_attn   [NB * 256L * SV];
__device__ __align__(16) float g_praw   [NB * 256 * 512];
__device__ __align__(16) float g_pnorm  [NB * 256 * 512];
__device__ __align__(16) __nv_bfloat16 g_xB    [NB * 256L * SV];
__device__ __align__(16) __nv_bfloat16 g_qkvB  [NB * 768L * SV];
__device__ __align__(16) __nv_bfloat16 g_attnB [NB * 256L * SV];
__device__ __align__(16) __nv_bfloat16 g_ghi   [NB * 256L * SV];
__device__ __align__(16) __nv_bfloat16 g_glo   [NB * 256L * SV];
__device__ __align__(16) __nv_bfloat16 g_pooledB[NB * 256 * 512];
__device__ __align__(16) __nv_bfloat16 g_q2T   [NB * 4L * SV * 64];
__device__ __align__(16) __nv_bfloat16 g_kvT   [NB * 8L * 512 * 64];
__device__ __align__(16) __nv_bfloat16 g_Wqkv2B[NB * 768 * 256];
__device__ __align__(16) __nv_bfloat16 g_Wq2B  [NB * 256 * 256];
__device__ __align__(16) __nv_bfloat16 g_WkvB  [512 * 256];
__device__ __align__(16) __nv_bfloat16 g_WprojB[256 * 768];
__device__ float g_qkvb2[NB * 768];
__device__ float g_qb2  [NB * 256];
__device__ float g_part [NB * 2048 * 2];
__device__ float g_part2[NB * 64 * 2];
__device__ float g_aff  [6 * NB * 256];

// ---------------- cp.async ----------------
__device__ __forceinline__ void cp16(void* dst, const void* src) {
    unsigned d = (unsigned)__cvta_generic_to_shared(dst);
    asm volatile("cp.async.cg.shared.global [%0], [%1], 16;\n" :: "r"(d), "l"(src));
}
#define CP_COMMIT asm volatile("cp.async.commit_group;\n" ::: "memory")
#define CP_WAIT1  asm volatile("cp.async.wait_group 1;\n" ::: "memory")
#define CP_WAIT0  asm volatile("cp.async.wait_group 0;\n" ::: "memory")

// =========================================================================
// reductions / affine / conversions
// =========================================================================
// vectorized: per4 = number of float4 per sample
__global__ void reduce1_kernel(const float* __restrict__ buf, long per4, float* __restrict__ part) {
    int n = blockIdx.y;
    const float4* p = reinterpret_cast<const float4*>(buf) + (size_t)n * per4;
    float s = 0.f, ss = 0.f;
    for (long i = (long)blockIdx.x * blockDim.x + threadIdx.x; i < per4;
         i += (long)gridDim.x * blockDim.x) {
        float4 v = p[i];
        s  += v.x + v.y + v.z + v.w;
        ss += v.x*v.x + v.y*v.y + v.z*v.z + v.w*v.w;
    }
    for (int o = 16; o; o >>= 1) {
        s  += __shfl_down_sync(0xffffffffu, s, o);
        ss += __shfl_down_sync(0xffffffffu, ss, o);
    }
    __shared__ float sh[64];
    int w = threadIdx.x >> 5;
    if ((threadIdx.x & 31) == 0) { sh[w] = s; sh[32 + w] = ss; }
    __syncthreads();
    if (threadIdx.x < 32) {
        int nw = blockDim.x >> 5;
        s  = (threadIdx.x < nw) ? sh[threadIdx.x]      : 0.f;
        ss = (threadIdx.x < nw) ? sh[32 + threadIdx.x] : 0.f;
        for (int o = 16; o; o >>= 1) {
            s  += __shfl_down_sync(0xffffffffu, s, o);
            ss += __shfl_down_sync(0xffffffffu, ss, o);
        }
        if (threadIdx.x == 0) {
            part[((size_t)n * gridDim.x + blockIdx.x) * 2 + 0] = s;
            part[((size_t)n * gridDim.x + blockIdx.x) * 2 + 1] = ss;
        }
    }
}

__global__ void stats2affine_kernel(const float* __restrict__ part, int nb,
                                    const float* __restrict__ w, const float* __restrict__ b,
                                    float* __restrict__ a, float* __restrict__ d,
                                    float inv_cnt) {
    int n = blockIdx.x, tid = threadIdx.x;
    float s = 0.f, ss = 0.f;
    for (int i = tid; i < nb; i += 256) {
        s  += part[((size_t)n * nb + i) * 2 + 0];
        ss += part[((size_t)n * nb + i) * 2 + 1];
    }
    for (int o = 16; o; o >>= 1) {
        s  += __shfl_down_sync(0xffffffffu, s, o);
        ss += __shfl_down_sync(0xffffffffu, ss, o);
    }
    __shared__ float sh[16];
    __shared__ float sm_mean, sm_rstd;
    int wp = tid >> 5;
    if ((tid & 31) == 0) { sh[wp] = s; sh[8 + wp] = ss; }
    __syncthreads();
    if (tid < 32) {
        s  = (tid < 8) ? sh[tid]     : 0.f;
        ss = (tid < 8) ? sh[8 + tid] : 0.f;
        for (int o = 4; o; o >>= 1) {
            s  += __shfl_down_sync(0xffffffffu, s, o);
            ss += __shfl_down_sync(0xffffffffu, ss, o);
        }
        if (tid == 0) {
            float mean = s * inv_cnt;
            float var  = ss * inv_cnt - mean * mean;
            sm_mean = mean;
            sm_rstd = rsqrtf(var + EPS);
        }
    }
    __syncthreads();
    float mean = sm_mean, rstd = sm_rstd;
    a[n * CH + tid] = w[tid] * rstd;
    d[n * CH + tid] = b[tid] - mean * rstd * w[tid];
}

// plain fp32 -> bf16, 8 elems/thread (32B in, 16B out)
__global__ void convert_plain_kernel(const float* __restrict__ x, __nv_bfloat16* __restrict__ out) {
    size_t i8 = (size_t)blockIdx.x * blockDim.x + threadIdx.x;
    const float4* p = reinterpret_cast<const float4*>(x) + i8 * 2;
    float4 v0 = p[0], v1 = p[1];
    uint4 u;
    u.x = pack2(v0.x, v0.y);
    u.y = pack2(v0.z, v0.w);
    u.z = pack2(v1.x, v1.y);
    u.w = pack2(v1.z, v1.w);
    reinterpret_cast<uint4*>(out)[i8] = u;
}

// fold affine into weights: W2[n][m][k] = bf16(W[m][k]*A[n][k]),
// b2[n][m] = b[m] + sum_k W[m][k]*D[n][k]   (exact fp32 bias term)
__global__ void fold_kernel(const float* __restrict__ W, const float* __restrict__ bsrc,
                            const float* __restrict__ A, const float* __restrict__ D,
                            __nv_bfloat16* __restrict__ W2, float* __restrict__ b2, int Mrows) {
    int m = blockIdx.x, n = blockIdx.y, tid = threadIdx.x;
    float w = W[(size_t)m * 256 + tid];
    float aa = A[n * 256 + tid], dd = D[n * 256 + tid];
    W2[((size_t)n * Mrows + m) * 256 + tid] = __float2bfloat16(w * aa);
    float pr = w * dd;
    for (int o = 16; o; o >>= 1) pr += __shfl_down_sync(0xffffffffu, pr, o);
    __shared__ float sh[8];
    if ((tid & 31) == 0) sh[tid >> 5] = pr;
    __syncthreads();
    if (tid == 0) {
        float t = 0.f;
        #pragma unroll
        for (int i = 0; i < 8; i++) t += sh[i];
        b2[n * Mrows + m] = bsrc[m] + t;
    }
}

__global__ void apply_pool_affine_kernel(const float* __restrict__ praw,
                                         const float* __restrict__ a, const float* __restrict__ d,
                                         float* __restrict__ pnorm) {
    size_t i4 = (size_t)blockIdx.x * blockDim.x + threadIdx.x;
    int c = (int)((i4 >> 7) & 255);
    int n = (int)(i4 >> 15);
    float aa = a[n * CH + c], dd = d[n * CH + c];
    float4 v = reinterpret_cast<const float4*>(praw)[i4];
    v.x = fmaf(aa, v.x, dd); v.y = fmaf(aa, v.y, dd);
    v.z = fmaf(aa, v.z, dd); v.w = fmaf(aa, v.w, dd);
    reinterpret_cast<float4*>(pnorm)[i4] = v;
}

__global__ void convert_pooled_kernel(const float* __restrict__ pooled,
                                      const float* __restrict__ a, const float* __restrict__ d,
                                      __nv_bfloat16* __restrict__ out) {
    size_t i4 = (size_t)blockIdx.x * blockDim.x + threadIdx.x;
    int c = (int)((i4 >> 7) & 255);
    int n = (int)(i4 >> 15);
    float aa = a[n * CH + c], dd = d[n * CH + c];
    float4 v = reinterpret_cast<const float4*>(pooled)[i4];
    uint2 r;
    r.x = pack2(fmaf(aa, v.x, dd), fmaf(aa, v.y, dd));
    r.y = pack2(fmaf(aa, v.z, dd), fmaf(aa, v.w, dd));
    reinterpret_cast<uint2*>(out)[i4] = r;
}

// kv + proj weights only (qkv/q are folded per batch)
__global__ void convert_weights_kernel(
    const float* __restrict__ kv_w, const float* __restrict__ proj_w,
    __nv_bfloat16* __restrict__ Wkv, __nv_bfloat16* __restrict__ Wproj) {
    int idx = blockIdx.x * blockDim.x + threadIdx.x;
    const int T1 = 512 * 256, T2 = T1 + 256 * 768;
    if (idx < T1) {
        Wkv[idx] = __float2bfloat16(kv_w[idx]);
    } else if (idx < T2) {
        int j = idx - T1;
        int m = j / 768, k = j % 768;
        float v = proj_w[m * 256 + (k & 255)];
        __nv_bfloat16 hi = __float2bfloat16(v);
        if (k >= 256 && k < 512) hi = __float2bfloat16(v - __bfloat162float(hi));
        Wproj[j] = hi;
    }
}

// =========================================================================
// wgemm3: BM=128, BN=128, BK=32, 3-stage cp.async, 256 threads.
// aStride/biasStride: per-z element offsets for folded per-batch weights.
// =========================================================================
#define WG_SMEM 69632

template<int MODE>
__global__ void __launch_bounds__(256) wgemm3_kernel(
    const __nv_bfloat16* __restrict__ A,
    const __nv_bfloat16* __restrict__ B0, const __nv_bfloat16* __restrict__ B1,
    const float* __restrict__ bias,
    float* __restrict__ outF, __nv_bfloat16* __restrict__ outB,
    int M, int S, int KT, float qScale, long aStride, int biasStride) {
    extern __shared__ __align__(16) char dsm[];
    __nv_bfloat16* As = (__nv_bfloat16*)dsm;
    __nv_bfloat16* Bs = (__nv_bfloat16*)(dsm + 30720);
    float* Cs = (float*)dsm;

    int tid = threadIdx.x, warp = tid >> 5;
    int wm = warp >> 2, wn = warp & 3;
    int m0 = blockIdx.x * 128;
    int s0 = blockIdx.y * 128;
    int z  = blockIdx.z;

    const __nv_bfloat16* Az = A + (size_t)z * aStride;
    const float* biasz = bias + (size_t)z * biasStride;
    const __nv_bfloat16* Bb0 = B0 + (size_t)z * 256 * S;
    const __nv_bfloat16* Bb1 = B1 + (size_t)z * 256 * S;

    wmma::fragment<wmma::accumulator, 16, 16, 16, float> acc[4][2];
    #pragma unroll
    for (int i = 0; i < 4; i++)
        #pragma unroll
        for (int j = 0; j < 2; j++) wmma::fill_fragment(acc[i][j], 0.f);

    const int NIT = KT >> 5;

    auto prefetch = [&](int it, int buf) {
        int ktL = it * 32;
        #pragma unroll
        for (int i = 0; i < 2; i++) {
            int c = tid + i * 256;
            int r = c >> 2, q = (c & 3) * 8;
            cp16(As + buf * 5120 + r * 40 + q,
                 Az + (size_t)(m0 + r) * KT + ktL + q);
        }
        const __nv_bfloat16* Bp = (ktL < 512) ? Bb0 : Bb1;
        int krow = ktL & 255;
        #pragma unroll
        for (int i = 0; i < 2; i++) {
            int c = tid + i * 256;
            int r = c >> 4, q = (c & 15) * 8;
            cp16(Bs + buf * 4352 + r * 136 + q,
                 Bp + (size_t)(krow + r) * S + s0 + q);
        }
    };

    prefetch(0, 0); CP_COMMIT;
    prefetch(1, 1); CP_COMMIT;

    int buf = 0;
    for (int it = 0; it < NIT; it++) {
        if (it + 1 < NIT) CP_WAIT1; else CP_WAIT0;
        __syncthreads();
        #pragma unroll
        for (int ks = 0; ks < 2; ks++) {
            wmma::fragment<wmma::matrix_a, 16, 16, 16, __nv_bfloat16, wmma::row_major> af[4];
            #pragma unroll
            for (int i = 0; i < 4; i++)
                wmma::load_matrix_sync(af[i], As + buf * 5120 + (wm * 64 + i * 16) * 40 + ks * 16, 40);
            wmma::fragment<wmma::matrix_b, 16, 16, 16, __nv_bfloat16, wmma::row_major> bf[2];
            #pragma unroll
            for (int j = 0; j < 2; j++)
                wmma::load_matrix_sync(bf[j], Bs + buf * 4352 + (ks * 16) * 136 + wn * 32 + j * 16, 136);
            #pragma unroll
            for (int i = 0; i < 4; i++)
                #pragma unroll
                for (int j = 0; j < 2; j++)
                    wmma::mma_sync(acc[i][j], af[i], bf[j], acc[i][j]);
        }
        if (it + 2 < NIT) {
            prefetch(it + 2, (buf + 2) % 3);
            CP_COMMIT;
        }
        buf = (buf + 1) % 3;
    }

    __syncthreads();

    if (MODE == 0) {
        #pragma unroll
        for (int i = 0; i < 4; i++)
            #pragma unroll
            for (int j = 0; j < 2; j++)
                wmma::store_matrix_sync(Cs + (wm * 64 + i * 16) * 132 + wn * 32 + j * 16,
                                        acc[i][j], 132, wmma::mem_row_major);
        __syncthreads();
        float* Ob = outF + ((size_t)z * M + m0) * S;
        #pragma unroll
        for (int it = 0; it < 16; it++) {
            int idx = tid + it * 256;
            int r = idx >> 5, c4 = idx & 31;
            float bv = biasz[m0 + r];
            float4 v = *reinterpret_cast<const float4*>(&Cs[r * 132 + c4 * 4]);
            v.x += bv; v.y += bv; v.z += bv; v.w += bv;
            *reinterpret_cast<float4*>(&Ob[(size_t)r * S + s0 + c4 * 4]) = v;
        }
    } else {
        #pragma unroll
        for (int i = 0; i < 4; i++)
            #pragma unroll
            for (int j = 0; j < 2; j++)
                wmma::store_matrix_sync(Cs + (wn * 32 + j * 16) * 136 + wm * 64 + i * 16,
                                        acc[i][j], 136, wmma::mem_col_major);
        __syncthreads();

        int dg = tid & 15;
        int gmb = m0 + dg * 8;
        float bias8[8];
        #pragma unroll
        for (int e = 0; e < 8; e++) bias8[e] = biasz[gmb + e];

        float sc;
        int db = gmb & 63;
        __nv_bfloat16* hbase;
        if (MODE == 1) {
            int hb = gmb >> 6;
            sc = qScale;
            hbase = outB + ((size_t)(z * (M >> 6) + hb) * S + s0) * 64 + db;
        } else {
            int sel = gmb >> 8, head = (gmb >> 6) & 3;
            sc = (sel == 0) ? qScale : 1.f;
            hbase = outB + (((size_t)(z * 3 + sel) * 4 + head) * 512) * 4096 + db;
        }

        #pragma unroll
        for (int it = 0; it < 8; it++) {
            int sl = it * 16 + (tid >> 4);
            float4 lo = *reinterpret_cast<const float4*>(&Cs[sl * 136 + dg * 8]);
            float4 hi = *reinterpret_cast<const float4*>(&Cs[sl * 136 + dg * 8 + 4]);
            float f[8] = {lo.x, lo.y, lo.z, lo.w, hi.x, hi.y, hi.z, hi.w};
            #pragma unroll
            for (int e = 0; e < 8; e++) f[e] = (f[e] + bias8[e]) * sc;
            uint4 u;
            u.x = pack2(f[0], f[1]);
            u.y = pack2(f[2], f[3]);
            u.z = pack2(f[4], f[5]);
            u.w = pack2(f[6], f[7]);
            size_t off;
            if (MODE == 1) {
                off = (size_t)sl * 64;
            } else {
                int s = s0 + sl;
                int d5 = s & 31, w5 = (s >> 5) & 31, h5 = s >> 10;
                int window = ((h5 >> 2) * 8 + (w5 >> 2)) * 8 + (d5 >> 2);
                int token  = (((h5 & 3) * 4 + (w5 & 3)) * 4 + (d5 & 3));
                off = (size_t)window * 4096 + token * 64;
            }
            *reinterpret_cast<uint4*>(hbase + off) = u;
        }
    }
}

// =========================================================================
// Local windowed attention (wmma, no-max softmax) + pool sums + gn partials
// =========================================================================
__global__ void __launch_bounds__(128) local_attn_w_kernel(
    const __nv_bfloat16* __restrict__ qkvB, const float* __restrict__ x,
    float* __restrict__ attn, float* __restrict__ praw, float* __restrict__ part) {
    __shared__ __align__(16) __nv_bfloat16 QP[64 * 72];
    __shared__ __align__(16) __nv_bfloat16 Ks[64 * 72];
    __shared__ __align__(16) __nv_bfloat16 Vs[64 * 72];
    __shared__ __align__(16) float Sf[64 * 68];
    __shared__ float linv[64];
    __shared__ float rs[4], rss[4];

    int w = blockIdx.x, head = blockIdx.y, n = blockIdx.z;
    int tid = threadIdx.x, warp = tid >> 5;

    size_t base = (((size_t)(n * 3) * 4 + head) * 512 + w) * 4096;
    size_t step = (size_t)4 * 512 * 4096;
    const uint4* Qg = (const uint4*)(qkvB + base);
    const uint4* Kg = (const uint4*)(qkvB + base + step);
    const uint4* Vg = (const uint4*)(qkvB + base + 2 * step);

    #pragma unroll
    for (int i = 0; i < 4; i++) {
        int c = tid + i * 128;
        int r = c >> 3, q = c & 7;
        ((uint4*)(QP + r * 72))[q] = Qg[c];
        ((uint4*)(Ks + r * 72))[q] = Kg[c];
        ((uint4*)(Vs + r * 72))[q] = Vg[c];
    }
    __syncthreads();

    {
        int m = warp * 16;
        wmma::fragment<wmma::accumulator, 16, 16, 16, float> acc[4];
        #pragma unroll
        for (int j = 0; j < 4; j++) wmma::fill_fragment(acc[j], 0.f);
        #pragma unroll
        for (int kd = 0; kd < 4; kd++) {
            wmma::fragment<wmma::matrix_a, 16, 16, 16, __nv_bfloat16, wmma::row_major> af;
            wmma::load_matrix_sync(af, QP + m * 72 + kd * 16, 72);
            #pragma unroll
            for (int j = 0; j < 4; j++) {
                wmma::fragment<wmma::matrix_b, 16, 16, 16, __nv_bfloat16, wmma::col_major> bf;
                wmma::load_matrix_sync(bf, Ks + (j * 16) * 72 + kd * 16, 72);
                wmma::mma_sync(acc[j], af, bf, acc[j]);
            }
        }
        #pragma unroll
        for (int j = 0; j < 4; j++)
            wmma::store_matrix_sync(Sf + m * 68 + j * 16, acc[j], 68, wmma::mem_row_major);
    }
    __syncthreads();

    {
        int r = tid >> 1, hf = tid & 1;
        const float* srow = Sf + r * 68 + hf * 32;
        float ls = 0.f;
        __nv_bfloat16* prow = QP + r * 72 + hf * 32;
        #pragma unroll
        for (int j = 0; j < 32; j++) {
            float p = __expf(srow[j]);
            ls += p;
            prow[j] = __float2bfloat16(p);
        }
        ls += __shfl_xor_sync(0xffffffffu, ls, 1);
        if (hf == 0) linv[r] = 1.f / ls;
    }
    __syncthreads();

    {
        int m = warp * 16;
        wmma::fragment<wmma::accumulator, 16, 16, 16, float> acc[4];
        #pragma unroll
        for (int j = 0; j < 4; j++) wmma::fill_fragment(acc[j], 0.f);
        #pragma unroll
        for (int kk = 0; kk < 4; kk++) {
            wmma::fragment<wmma::matrix_a, 16, 16, 16, __nv_bfloat16, wmma::row_major> af;
            wmma::load_matrix_sync(af, QP + m * 72 + kk * 16, 72);
            #pragma unroll
            for (int j = 0; j < 4; j++) {
                wmma::fragment<wmma::matrix_b, 16, 16, 16, __nv_bfloat16, wmma::row_major> bf;
                wmma::load_matrix_sync(bf, Vs + (kk * 16) * 72 + j * 16, 72);
                wmma::mma_sync(acc[j], af, bf, acc[j]);
            }
        }
        #pragma unroll
        for (int j = 0; j < 4; j++)
            wmma::store_matrix_sync(Sf + m * 68 + j * 16, acc[j], 68, wmma::mem_row_major);
    }
    __syncthreads();

    int wh = w >> 6, ww = (w >> 3) & 7, wd = w & 7;
    int base_s = wh * 4096 + ww * 128 + wd * 4;
    int chb = n * 256 + head * 64;
    float s_acc = 0.f, ss_acc = 0.f;
    #pragma unroll
    for (int it = 0; it < 8; it++) {
        int idx = tid + it * 128;
        int d = idx >> 4, tg = idx & 15;
        int i_ = tg >> 2, j_ = tg & 3;
        int s = base_s + i_ * 1024 + j_ * 32;
        int t0 = tg * 4;
        size_t g = ((size_t)(chb + d)) * SV + s;
        float4 xv = *reinterpret_cast<const float4*>(x + g);
        float4 ov;
        ov.x = fmaf(Sf[(t0 + 0) * 68 + d], linv[t0 + 0], xv.x);
        ov.y = fmaf(Sf[(t0 + 1) * 68 + d], linv[t0 + 1], xv.y);
        ov.z = fmaf(Sf[(t0 + 2) * 68 + d], linv[t0 + 2], xv.z);
        ov.w = fmaf(Sf[(t0 + 3) * 68 + d], linv[t0 + 3], xv.w);
        *reinterpret_cast<float4*>(attn + g) = ov;
        float ps = ov.x + ov.y + ov.z + ov.w;
        s_acc  += ps;
        ss_acc += ov.x*ov.x + ov.y*ov.y + ov.z*ov.z + ov.w*ov.w;
        #pragma unroll
        for (int o = 8; o; o >>= 1) ps += __shfl_down_sync(0xffffffffu, ps, o);
        if ((tid & 15) == 0)
            praw[((size_t)(chb + d)) * 512 + w] = ps * (1.f / 64.f);
    }
    #pragma unroll
    for (int o = 16; o; o >>= 1) {
        s_acc  += __shfl_down_sync(0xffffffffu, s_acc, o);
        ss_acc += __shfl_down_sync(0xffffffffu, ss_acc, o);
    }
    if ((tid & 31) == 0) { rs[warp] = s_acc; rss[warp] = ss_acc; }
    __syncthreads();
    if (tid == 0) {
        size_t pi = (size_t)n * 2048 + head * 512 + w;
        part[pi * 2 + 0] = rs[0] + rs[1] + rs[2] + rs[3];
        part[pi * 2 + 1] = rss[0] + rss[1] + rss[2] + rss[3];
    }
}

// =========================================================================
// Global attention: no-max softmax, O persistent in accumulators,
// cp.async double-buffered K/V.
// =========================================================================
#define GA_SMEM 109056

__global__ void __launch_bounds__(256, 2) gattn_kernel(
    const __nv_bfloat16* __restrict__ q2T, const __nv_bfloat16* __restrict__ kvT,
    const float* __restrict__ attn,
    const float* __restrict__ A1, const float* __restrict__ D1,
    __nv_bfloat16* __restrict__ ghi, __nv_bfloat16* __restrict__ glo) {
    extern __shared__ __align__(16) char sm[];
    __nv_bfloat16* Qs = (__nv_bfloat16*)sm;
    __nv_bfloat16* Ks = Qs + 128 * 72;
    __nv_bfloat16* Vs = Ks + 2 * 64 * 72;
    __nv_bfloat16* Ps = Vs + 2 * 64 * 72;
    float* Sf   = (float*)(Ps + 128 * 72);
    float* lrow = Sf + 128 * 68;

    int tid = threadIdx.x, warp = tid >> 5;
    int h = blockIdx.y, n = blockIdx.z;
    int s0 = blockIdx.x * 128;

    const uint4* Qg = (const uint4*)(q2T + ((size_t)(n * 4 + h) * SV + s0) * 64);
    const __nv_bfloat16* Kg = kvT + ((size_t)(n * 8 + h) * 512) * 64;
    const __nv_bfloat16* Vg = kvT + ((size_t)(n * 8 + 4 + h) * 512) * 64;

    auto prefetchKV = [&](int ch, int b) {
        #pragma unroll
        for (int i = 0; i < 2; i++) {
            int idx = tid + i * 256;
            int r = idx >> 3, c = (idx & 7) * 8;
            cp16(Ks + b * 4608 + r * 72 + c, Kg + (size_t)(ch * 64 + r) * 64 + c);
            cp16(Vs + b * 4608 + r * 72 + c, Vg + (size_t)(ch * 64 + r) * 64 + c);
        }
    };

    prefetchKV(0, 0); CP_COMMIT;

    #pragma unroll
    for (int i = 0; i < 4; i++) {
        int idx = tid + i * 256;
        int r = idx >> 3, c = idx & 7;
        ((uint4*)(Qs + r * 72))[c] = Qg[r * 8 + c];
    }
    if (tid < 128) lrow[tid] = 0.f;

    int pm = warp >> 1, pn = warp & 1;
    wmma::fragment<wmma::accumulator, 16, 16, 16, float> acc_o[2][2];
    #pragma unroll
    for (int i = 0; i < 2; i++)
        #pragma unroll
        for (int j = 0; j < 2; j++) wmma::fill_fragment(acc_o[i][j], 0.f);

    for (int ch = 0; ch < 8; ch++) {
        int b = ch & 1;
        CP_WAIT0;
        __syncthreads();

        {
            int m = warp * 16;
            wmma::fragment<wmma::accumulator, 16, 16, 16, float> acc[4];
            #pragma unroll
            for (int j = 0; j < 4; j++) wmma::fill_fragment(acc[j], 0.f);
            #pragma unroll
            for (int kd = 0; kd < 4; kd++) {
                wmma::fragment<wmma::matrix_a, 16, 16, 16, __nv_bfloat16, wmma::row_major> af;
                wmma::load_matrix_sync(af, Qs + m * 72 + kd * 16, 72);
                #pragma unroll
                for (int j = 0; j < 4; j++) {
                    wmma::fragment<wmma::matrix_b, 16, 16, 16, __nv_bfloat16, wmma::col_major> bf;
                    wmma::load_matrix_sync(bf, Ks + b * 4608 + (j * 16) * 72 + kd * 16, 72);
                    wmma::mma_sync(acc[j], af, bf, acc[j]);
                }
            }
            #pragma unroll
            for (int j = 0; j < 4; j++)
                wmma::store_matrix_sync(Sf + m * 68 + j * 16, acc[j], 68, wmma::mem_row_major);
        }
        __syncthreads();

        {
            int r = tid >> 1, hf = tid & 1;
            const float* srow = Sf + r * 68 + hf * 32;
            float ls = 0.f;
            __nv_bfloat16* prow = Ps + r * 72 + hf * 32;
            #pragma unroll
            for (int j = 0; j < 32; j++) {
                float p = __expf(srow[j]);
                ls += p;
                prow[j] = __float2bfloat16(p);
            }
            ls += __shfl_xor_sync(0xffffffffu, ls, 1);
            if (hf == 0) lrow[r] += ls;
        }
        __syncthreads();

        if (ch + 1 < 8) {
            prefetchKV(ch + 1, b ^ 1);
            CP_COMMIT;
        }

        {
            #pragma unroll
            for (int kk = 0; kk < 4; kk++) {
                wmma::fragment<wmma::matrix_a, 16, 16, 16, __nv_bfloat16, wmma::row_major> af[2];
                #pragma unroll
                for (int i = 0; i < 2; i++)
                    wmma::load_matrix_sync(af[i], Ps + (pm * 32 + i * 16) * 72 + kk * 16, 72);
                wmma::fragment<wmma::matrix_b, 16, 16, 16, __nv_bfloat16, wmma::row_major> bf[2];
                #pragma unroll
                for (int j = 0; j < 2; j++)
                    wmma::load_matrix_sync(bf[j], Vs + b * 4608 + (kk * 16) * 72 + pn * 32 + j * 16, 72);
                #pragma unroll
                for (int i = 0; i < 2; i++)
                    #pragma unroll
                    for (int j = 0; j < 2; j++)
                        wmma::mma_sync(acc_o[i][j], af[i], bf[j], acc_o[i][j]);
            }
        }
    }

    __syncthreads();
    #pragma unroll
    for (int i = 0; i < 2; i++)
        #pragma unroll
        for (int j = 0; j < 2; j++)
            wmma::store_matrix_sync(Sf + (pm * 32 + i * 16) * 68 + pn * 32 + j * 16,
                                    acc_o[i][j], 68, wmma::mem_row_major);
    __syncthreads();

    #pragma unroll
    for (int i = 0; i < 32; i++) {
        int idx = tid + i * 256;
        int r = idx & 127, d = idx >> 7;
        int cch = n * 256 + h * 64 + d;
        float v = Sf[r * 68 + d] / lrow[r];
        size_t gi = ((size_t)cch) * SV + s0 + r;
        float t = v + fmaf(A1[cch], attn[gi], D1[cch]);
        __nv_bfloat16 hi = __float2bfloat16(t);
        ghi[gi] = hi;
        glo[gi] = __float2bfloat16(t - __bfloat162float(hi));
    }
}

// =========================================================================
// host launch
// =========================================================================
extern "C" void kernel_launch(void* const* d_in, const int* in_sizes, int n_in,
                              void* d_out, int out_size) {
    const float* x      = (const float*)d_in[0];
    const float* qkv_w  = (const float*)d_in[1];
    const float* qkv_b  = (const float*)d_in[2];
    const float* norm_w = (const float*)d_in[3];
    const float* norm_b = (const float*)d_in[4];
    const float* anorm_w= (const float*)d_in[5];
    const float* anorm_b= (const float*)d_in[6];
    const float* dnorm_w= (const float*)d_in[7];
    const float* dnorm_b= (const float*)d_in[8];
    const float* q_w    = (const float*)d_in[9];
    const float* q_b    = (const float*)d_in[10];
    const float* kv_w   = (const float*)d_in[11];
    const float* kv_b   = (const float*)d_in[12];
    const float* proj_w = (const float*)d_in[13];
    const float* proj_b = (const float*)d_in[14];
    float* out = (float*)d_out;

    float *attn, *praw, *pnorm, *part, *part2, *aff, *qkvb2, *qb2;
    __nv_bfloat16 *xB, *qkvB, *attnB, *ghi, *glo, *pooledB, *q2T, *kvT;
    __nv_bfloat16 *Wqkv2B, *Wq2B, *WkvB, *WprojB;
    cudaGetSymbolAddress((void**)&attn,    g_attn);
    cudaGetSymbolAddress((void**)&praw,    g_praw);
    cudaGetSymbolAddress((void**)&pnorm,   g_pnorm);
    cudaGetSymbolAddress((void**)&xB,      g_xB);
    cudaGetSymbolAddress((void**)&qkvB,    g_qkvB);
    cudaGetSymbolAddress((void**)&attnB,   g_attnB);
    cudaGetSymbolAddress((void**)&ghi,     g_ghi);
    cudaGetSymbolAddress((void**)&glo,     g_glo);
    cudaGetSymbolAddress((void**)&pooledB, g_pooledB);
    cudaGetSymbolAddress((void**)&q2T,     g_q2T);
    cudaGetSymbolAddress((void**)&kvT,     g_kvT);
    cudaGetSymbolAddress((void**)&Wqkv2B,  g_Wqkv2B);
    cudaGetSymbolAddress((void**)&Wq2B,    g_Wq2B);
    cudaGetSymbolAddress((void**)&WkvB,    g_WkvB);
    cudaGetSymbolAddress((void**)&WprojB,  g_WprojB);
    cudaGetSymbolAddress((void**)&qkvb2,   g_qkvb2);
    cudaGetSymbolAddress((void**)&qb2,     g_qb2);
    cudaGetSymbolAddress((void**)&part,    g_part);
    cudaGetSymbolAddress((void**)&part2,   g_part2);
    cudaGetSymbolAddress((void**)&aff,     g_aff);

    static cudaStream_t s1 = nullptr;
    static cudaEvent_t ev0, evS1a, evA, evB, evA1, evKV;
    static bool init_done = false;
    if (!init_done) {
        cudaFuncSetAttribute(gattn_kernel, cudaFuncAttributeMaxDynamicSharedMemorySize, GA_SMEM);
        cudaFuncSetAttribute(wgemm3_kernel<0>, cudaFuncAttributeMaxDynamicSharedMemorySize, WG_SMEM);
        cudaFuncSetAttribute(wgemm3_kernel<1>, cudaFuncAttributeMaxDynamicSharedMemorySize, WG_SMEM);
        cudaFuncSetAttribute(wgemm3_kernel<2>, cudaFuncAttributeMaxDynamicSharedMemorySize, WG_SMEM);
        cudaStreamCreateWithFlags(&s1, cudaStreamNonBlocking);
        cudaEventCreateWithFlags(&ev0,  cudaEventDisableTiming);
        cudaEventCreateWithFlags(&evS1a, cudaEventDisableTiming);
        cudaEventCreateWithFlags(&evA,  cudaEventDisableTiming);
        cudaEventCreateWithFlags(&evB,  cudaEventDisableTiming);
        cudaEventCreateWithFlags(&evA1, cudaEventDisableTiming);
        cudaEventCreateWithFlags(&evKV, cudaEventDisableTiming);
        init_done = true;
    }

    float* A0 = aff;        float* D0 = aff + 512;
    float* A1 = aff + 1024; float* D1 = aff + 1536;
    float* A2 = aff + 2048; float* D2 = aff + 2560;

    // ---- fork: side = plain x->bf16 + kv/proj weight convert; main = stats+fold ----
    cudaEventRecord(ev0, 0);
    cudaStreamWaitEvent(s1, ev0, 0);
    convert_plain_kernel<<<8192, 256, 0, s1>>>(x, xB);
    convert_weights_kernel<<<1280, 256, 0, s1>>>(kv_w, proj_w, WkvB, WprojB);
    cudaEventRecord(evS1a, s1);

    reduce1_kernel<<<dim3(512, NB), 256>>>(x, 256L * SV / 4, part);
    stats2affine_kernel<<<NB, 256>>>(part, 512, norm_w, norm_b, A0, D0, 1.f / (256.f * 32768.f));
    fold_kernel<<<dim3(768, NB), 256>>>(qkv_w, qkv_b, A0, D0, Wqkv2B, qkvb2, 768);

    cudaStreamWaitEvent(0, evS1a, 0);

    // qkv conv (folded per-batch weights) -> window-gathered bf16 (q * 1/16)
    wgemm3_kernel<2><<<dim3(6, 256, NB), 256, WG_SMEM>>>(
        Wqkv2B, xB, xB, qkvb2, nullptr, qkvB, 768, (int)SV, 256, SCALE_INV,
        768L * 256, 768);

    // local attention: attn(raw) + pooled sums + gn partials
    local_attn_w_kernel<<<dim3(512, NH, NB), 128>>>(qkvB, x, attn, praw, part);

    // ---- fork: side = attnB plain convert, then pooled/kv chain after A1 ----
    cudaEventRecord(evA, 0);
    cudaStreamWaitEvent(s1, evA, 0);
    convert_plain_kernel<<<8192, 256, 0, s1>>>(attn, attnB);
    cudaEventRecord(evB, s1);

    // main: anorm affine + fold q weights
    stats2affine_kernel<<<NB, 256>>>(part, 2048, anorm_w, anorm_b, A1, D1, 1.f / (256.f * 32768.f));
    cudaEventRecord(evA1, 0);
    fold_kernel<<<dim3(256, NB), 256>>>(q_w, q_b, A1, D1, Wq2B, qb2, 256);

    // side: pooled chain (needs A1) -> kv gemm
    cudaStreamWaitEvent(s1, evA1, 0);
    apply_pool_affine_kernel<<<256, 256, 0, s1>>>(praw, A1, D1, pnorm);
    reduce1_kernel<<<dim3(32, NB), 256, 0, s1>>>(pnorm, 256L * 512 / 4, part2);
    stats2affine_kernel<<<NB, 256, 0, s1>>>(part2, 32, dnorm_w, dnorm_b, A2, D2, 1.f / (256.f * 512.f));
    convert_pooled_kernel<<<256, 256, 0, s1>>>(pnorm, A2, D2, pooledB);
    wgemm3_kernel<1><<<dim3(4, 4, NB), 256, WG_SMEM, s1>>>(
        WkvB, pooledB, pooledB, kv_b, nullptr, kvT, 512, 512, 256, 1.f, 0, 0);
    cudaEventRecord(evKV, s1);

    // main: q gemm (folded weights on raw attnB) -> q2T (scaled 1/16)
    cudaStreamWaitEvent(0, evB, 0);
    wgemm3_kernel<1><<<dim3(2, 256, NB), 256, WG_SMEM>>>(
        Wq2B, attnB, attnB, qb2, nullptr, q2T, 256, (int)SV, 256, SCALE_INV,
        256L * 256, 256);

    cudaStreamWaitEvent(0, evKV, 0);

    // global attention + affine residual -> bf16 hi/lo
    gattn_kernel<<<dim3(256, NH, NB), 256, GA_SMEM>>>(q2T, kvT, attn, A1, D1, ghi, glo);

    // final projection (3-term bf16 split) -> out
    wgemm3_kernel<0><<<dim3(2, 256, NB), 256, WG_SMEM>>>(
        WprojB, ghi, glo, proj_b, out, nullptr, 256, (int)SV, 768, 1.f, 0, 0);
}

// round 12
// speedup vs baseline: 1.3391x; 1.0011x over previous
#include <cuda_runtime.h>
#include <cuda_bf16.h>
#include <mma.h>
#include <math.h>
#include <stdint.h>

using namespace nvcuda;

#define NB 2
#define CH 256
#define SV 32768L
#define NH 4
#define HD 64
#define SCALE_INV 0.0625f
#define EPS 1e-6f

__device__ __forceinline__ unsigned pack2(float a, float b) {
    __nv_bfloat162 t = __floats2bfloat162_rn(a, b);
    return *reinterpret_cast<unsigned*>(&t);
}

// ---------------- scratch ----------------
__device__ __align__(16) float g_attn   [NB * 256L * SV];
__device__ __align__(16) float g_praw   [NB * 256 * 512];
__device__ __align__(16) float g_pnorm  [NB * 256 * 512];
__device__ __align__(16) __nv_bfloat16 g_xB    [NB * 256L * SV];
__device__ __align__(16) __nv_bfloat16 g_qkvB  [NB * 768L * SV];
__device__ __align__(16) __nv_bfloat16 g_attnB [NB * 256L * SV];
__device__ __align__(16) __nv_bfloat16 g_ghi   [NB * 256L * SV];
__device__ __align__(16) __nv_bfloat16 g_glo   [NB * 256L * SV];
__device__ __align__(16) __nv_bfloat16 g_pooledB[NB * 256 * 512];
__device__ __align__(16) __nv_bfloat16 g_q2T   [NB * 4L * SV * 64];
__device__ __align__(16) __nv_bfloat16 g_kvT   [NB * 8L * 512 * 64];
__device__ __align__(16) __nv_bfloat16 g_Wqkv2B[NB * 768 * 256];
__device__ __align__(16) __nv_bfloat16 g_Wq2B  [NB * 256 * 256];
__device__ __align__(16) __nv_bfloat16 g_WkvB  [512 * 256];
__device__ __align__(16) __nv_bfloat16 g_WprojB[256 * 768];
__device__ float g_qkvb2[NB * 768];
__device__ float g_qb2  [NB * 256];
__device__ float g_part [NB * 2048 * 2];
__device__ float g_part2[NB * 64 * 2];
__device__ float g_aff  [6 * NB * 256];

// ---------------- cp.async ----------------
__device__ __forceinline__ void cp16(void* dst, const void* src) {
    unsigned d = (unsigned)__cvta_generic_to_shared(dst);
    asm volatile("cp.async.cg.shared.global [%0], [%1], 16;\n" :: "r"(d), "l"(src));
}
#define CP_COMMIT asm volatile("cp.async.commit_group;\n" ::: "memory")
#define CP_WAIT1  asm volatile("cp.async.wait_group 1;\n" ::: "memory")
#define CP_WAIT0  asm volatile("cp.async.wait_group 0;\n" ::: "memory")

// =========================================================================
// reductions / affine / conversions
// =========================================================================
__global__ void reduce1_kernel(const float* __restrict__ buf, long per4, float* __restrict__ part) {
    int n = blockIdx.y;
    const float4* p = reinterpret_cast<const float4*>(buf) + (size_t)n * per4;
    float s = 0.f, ss = 0.f;
    for (long i = (long)blockIdx.x * blockDim.x + threadIdx.x; i < per4;
         i += (long)gridDim.x * blockDim.x) {
        float4 v = p[i];
        s  += v.x + v.y + v.z + v.w;
        ss += v.x*v.x + v.y*v.y + v.z*v.z + v.w*v.w;
    }
    for (int o = 16; o; o >>= 1) {
        s  += __shfl_down_sync(0xffffffffu, s, o);
        ss += __shfl_down_sync(0xffffffffu, ss, o);
    }
    __shared__ float sh[64];
    int w = threadIdx.x >> 5;
    if ((threadIdx.x & 31) == 0) { sh[w] = s; sh[32 + w] = ss; }
    __syncthreads();
    if (threadIdx.x < 32) {
        int nw = blockDim.x >> 5;
        s  = (threadIdx.x < nw) ? sh[threadIdx.x]      : 0.f;
        ss = (threadIdx.x < nw) ? sh[32 + threadIdx.x] : 0.f;
        for (int o = 16; o; o >>= 1) {
            s  += __shfl_down_sync(0xffffffffu, s, o);
            ss += __shfl_down_sync(0xffffffffu, ss, o);
        }
        if (threadIdx.x == 0) {
            part[((size_t)n * gridDim.x + blockIdx.x) * 2 + 0] = s;
            part[((size_t)n * gridDim.x + blockIdx.x) * 2 + 1] = ss;
        }
    }
}

__global__ void stats2affine_kernel(const float* __restrict__ part, int nb,
                                    const float* __restrict__ w, const float* __restrict__ b,
                                    float* __restrict__ a, float* __restrict__ d,
                                    float inv_cnt) {
    int n = blockIdx.x, tid = threadIdx.x;
    float s = 0.f, ss = 0.f;
    for (int i = tid; i < nb; i += 256) {
        s  += part[((size_t)n * nb + i) * 2 + 0];
        ss += part[((size_t)n * nb + i) * 2 + 1];
    }
    for (int o = 16; o; o >>= 1) {
        s  += __shfl_down_sync(0xffffffffu, s, o);
        ss += __shfl_down_sync(0xffffffffu, ss, o);
    }
    __shared__ float sh[16];
    __shared__ float sm_mean, sm_rstd;
    int wp = tid >> 5;
    if ((tid & 31) == 0) { sh[wp] = s; sh[8 + wp] = ss; }
    __syncthreads();
    if (tid < 32) {
        s  = (tid < 8) ? sh[tid]     : 0.f;
        ss = (tid < 8) ? sh[8 + tid] : 0.f;
        for (int o = 4; o; o >>= 1) {
            s  += __shfl_down_sync(0xffffffffu, s, o);
            ss += __shfl_down_sync(0xffffffffu, ss, o);
        }
        if (tid == 0) {
            float mean = s * inv_cnt;
            float var  = ss * inv_cnt - mean * mean;
            sm_mean = mean;
            sm_rstd = rsqrtf(var + EPS);
        }
    }
    __syncthreads();
    float mean = sm_mean, rstd = sm_rstd;
    a[n * CH + tid] = w[tid] * rstd;
    d[n * CH + tid] = b[tid] - mean * rstd * w[tid];
}

__global__ void convert_plain_kernel(const float* __restrict__ x, __nv_bfloat16* __restrict__ out) {
    size_t i8 = (size_t)blockIdx.x * blockDim.x + threadIdx.x;
    const float4* p = reinterpret_cast<const float4*>(x) + i8 * 2;
    float4 v0 = p[0], v1 = p[1];
    uint4 u;
    u.x = pack2(v0.x, v0.y);
    u.y = pack2(v0.z, v0.w);
    u.z = pack2(v1.x, v1.y);
    u.w = pack2(v1.z, v1.w);
    reinterpret_cast<uint4*>(out)[i8] = u;
}

__global__ void fold_kernel(const float* __restrict__ W, const float* __restrict__ bsrc,
                            const float* __restrict__ A, const float* __restrict__ D,
                            __nv_bfloat16* __restrict__ W2, float* __restrict__ b2, int Mrows) {
    int m = blockIdx.x, n = blockIdx.y, tid = threadIdx.x;
    float w = W[(size_t)m * 256 + tid];
    float aa = A[n * 256 + tid], dd = D[n * 256 + tid];
    W2[((size_t)n * Mrows + m) * 256 + tid] = __float2bfloat16(w * aa);
    float pr = w * dd;
    for (int o = 16; o; o >>= 1) pr += __shfl_down_sync(0xffffffffu, pr, o);
    __shared__ float sh[8];
    if ((tid & 31) == 0) sh[tid >> 5] = pr;
    __syncthreads();
    if (tid == 0) {
        float t = 0.f;
        #pragma unroll
        for (int i = 0; i < 8; i++) t += sh[i];
        b2[n * Mrows + m] = bsrc[m] + t;
    }
}

__global__ void apply_pool_affine_kernel(const float* __restrict__ praw,
                                         const float* __restrict__ a, const float* __restrict__ d,
                                         float* __restrict__ pnorm) {
    size_t i4 = (size_t)blockIdx.x * blockDim.x + threadIdx.x;
    int c = (int)((i4 >> 7) & 255);
    int n = (int)(i4 >> 15);
    float aa = a[n * CH + c], dd = d[n * CH + c];
    float4 v = reinterpret_cast<const float4*>(praw)[i4];
    v.x = fmaf(aa, v.x, dd); v.y = fmaf(aa, v.y, dd);
    v.z = fmaf(aa, v.z, dd); v.w = fmaf(aa, v.w, dd);
    reinterpret_cast<float4*>(pnorm)[i4] = v;
}

__global__ void convert_pooled_kernel(const float* __restrict__ pooled,
                                      const float* __restrict__ a, const float* __restrict__ d,
                                      __nv_bfloat16* __restrict__ out) {
    size_t i4 = (size_t)blockIdx.x * blockDim.x + threadIdx.x;
    int c = (int)((i4 >> 7) & 255);
    int n = (int)(i4 >> 15);
    float aa = a[n * CH + c], dd = d[n * CH + c];
    float4 v = reinterpret_cast<const float4*>(pooled)[i4];
    uint2 r;
    r.x = pack2(fmaf(aa, v.x, dd), fmaf(aa, v.y, dd));
    r.y = pack2(fmaf(aa, v.z, dd), fmaf(aa, v.w, dd));
    reinterpret_cast<uint2*>(out)[i4] = r;
}

__global__ void convert_weights_kernel(
    const float* __restrict__ kv_w, const float* __restrict__ proj_w,
    __nv_bfloat16* __restrict__ Wkv, __nv_bfloat16* __restrict__ Wproj) {
    int idx = blockIdx.x * blockDim.x + threadIdx.x;
    const int T1 = 512 * 256, T2 = T1 + 256 * 768;
    if (idx < T1) {
        Wkv[idx] = __float2bfloat16(kv_w[idx]);
    } else if (idx < T2) {
        int j = idx - T1;
        int m = j / 768, k = j % 768;
        float v = proj_w[m * 256 + (k & 255)];
        __nv_bfloat16 hi = __float2bfloat16(v);
        if (k >= 256 && k < 512) hi = __float2bfloat16(v - __bfloat162float(hi));
        Wproj[j] = hi;
    }
}

// =========================================================================
// wgemm3: BM=128, BN=128, BK=32, 3-stage cp.async, 256 threads, 2 blocks/SM.
// =========================================================================
#define WG_SMEM 69632

template<int MODE>
__global__ void __launch_bounds__(256, 2) wgemm3_kernel(
    const __nv_bfloat16* __restrict__ A,
    const __nv_bfloat16* __restrict__ B0, const __nv_bfloat16* __restrict__ B1,
    const float* __restrict__ bias,
    float* __restrict__ outF, __nv_bfloat16* __restrict__ outB,
    int M, int S, int KT, float qScale, long aStride, int biasStride) {
    extern __shared__ __align__(16) char dsm[];
    __nv_bfloat16* As = (__nv_bfloat16*)dsm;
    __nv_bfloat16* Bs = (__nv_bfloat16*)(dsm + 30720);
    float* Cs = (float*)dsm;

    int tid = threadIdx.x, warp = tid >> 5;
    int wm = warp >> 2, wn = warp & 3;
    int m0 = blockIdx.x * 128;
    int s0 = blockIdx.y * 128;
    int z  = blockIdx.z;

    const __nv_bfloat16* Az = A + (size_t)z * aStride;
    const float* biasz = bias + (size_t)z * biasStride;
    const __nv_bfloat16* Bb0 = B0 + (size_t)z * 256 * S;
    const __nv_bfloat16* Bb1 = B1 + (size_t)z * 256 * S;

    wmma::fragment<wmma::accumulator, 16, 16, 16, float> acc[4][2];
    #pragma unroll
    for (int i = 0; i < 4; i++)
        #pragma unroll
        for (int j = 0; j < 2; j++) wmma::fill_fragment(acc[i][j], 0.f);

    const int NIT = KT >> 5;

    auto prefetch = [&](int it, int buf) {
        int ktL = it * 32;
        #pragma unroll
        for (int i = 0; i < 2; i++) {
            int c = tid + i * 256;
            int r = c >> 2, q = (c & 3) * 8;
            cp16(As + buf * 5120 + r * 40 + q,
                 Az + (size_t)(m0 + r) * KT + ktL + q);
        }
        const __nv_bfloat16* Bp = (ktL < 512) ? Bb0 : Bb1;
        int krow = ktL & 255;
        #pragma unroll
        for (int i = 0; i < 2; i++) {
            int c = tid + i * 256;
            int r = c >> 4, q = (c & 15) * 8;
            cp16(Bs + buf * 4352 + r * 136 + q,
                 Bp + (size_t)(krow + r) * S + s0 + q);
        }
    };

    prefetch(0, 0); CP_COMMIT;
    prefetch(1, 1); CP_COMMIT;

    int buf = 0;
    for (int it = 0; it < NIT; it++) {
        if (it + 1 < NIT) CP_WAIT1; else CP_WAIT0;
        __syncthreads();
        #pragma unroll
        for (int ks = 0; ks < 2; ks++) {
            wmma::fragment<wmma::matrix_a, 16, 16, 16, __nv_bfloat16, wmma::row_major> af[4];
            #pragma unroll
            for (int i = 0; i < 4; i++)
                wmma::load_matrix_sync(af[i], As + buf * 5120 + (wm * 64 + i * 16) * 40 + ks * 16, 40);
            wmma::fragment<wmma::matrix_b, 16, 16, 16, __nv_bfloat16, wmma::row_major> bf[2];
            #pragma unroll
            for (int j = 0; j < 2; j++)
                wmma::load_matrix_sync(bf[j], Bs + buf * 4352 + (ks * 16) * 136 + wn * 32 + j * 16, 136);
            #pragma unroll
            for (int i = 0; i < 4; i++)
                #pragma unroll
                for (int j = 0; j < 2; j++)
                    wmma::mma_sync(acc[i][j], af[i], bf[j], acc[i][j]);
        }
        if (it + 2 < NIT) {
            prefetch(it + 2, (buf + 2) % 3);
            CP_COMMIT;
        }
        buf = (buf + 1) % 3;
    }

    __syncthreads();

    if (MODE == 0) {
        #pragma unroll
        for (int i = 0; i < 4; i++)
            #pragma unroll
            for (int j = 0; j < 2; j++)
                wmma::store_matrix_sync(Cs + (wm * 64 + i * 16) * 132 + wn * 32 + j * 16,
                                        acc[i][j], 132, wmma::mem_row_major);
        __syncthreads();
        float* Ob = outF + ((size_t)z * M + m0) * S;
        #pragma unroll
        for (int it = 0; it < 16; it++) {
            int idx = tid + it * 256;
            int r = idx >> 5, c4 = idx & 31;
            float bv = biasz[m0 + r];
            float4 v = *reinterpret_cast<const float4*>(&Cs[r * 132 + c4 * 4]);
            v.x += bv; v.y += bv; v.z += bv; v.w += bv;
            *reinterpret_cast<float4*>(&Ob[(size_t)r * S + s0 + c4 * 4]) = v;
        }
    } else {
        #pragma unroll
        for (int i = 0; i < 4; i++)
            #pragma unroll
            for (int j = 0; j < 2; j++)
                wmma::store_matrix_sync(Cs + (wn * 32 + j * 16) * 136 + wm * 64 + i * 16,
                                        acc[i][j], 136, wmma::mem_col_major);
        __syncthreads();

        int dg = tid & 15;
        int gmb = m0 + dg * 8;
        float bias8[8];
        #pragma unroll
        for (int e = 0; e < 8; e++) bias8[e] = biasz[gmb + e];

        float sc;
        int db = gmb & 63;
        __nv_bfloat16* hbase;
        if (MODE == 1) {
            int hb = gmb >> 6;
            sc = qScale;
            hbase = outB + ((size_t)(z * (M >> 6) + hb) * S + s0) * 64 + db;
        } else {
            int sel = gmb >> 8, head = (gmb >> 6) & 3;
            sc = (sel == 0) ? qScale : 1.f;
            hbase = outB + (((size_t)(z * 3 + sel) * 4 + head) * 512) * 4096 + db;
        }

        #pragma unroll
        for (int it = 0; it < 8; it++) {
            int sl = it * 16 + (tid >> 4);
            float4 lo = *reinterpret_cast<const float4*>(&Cs[sl * 136 + dg * 8]);
            float4 hi = *reinterpret_cast<const float4*>(&Cs[sl * 136 + dg * 8 + 4]);
            float f[8] = {lo.x, lo.y, lo.z, lo.w, hi.x, hi.y, hi.z, hi.w};
            #pragma unroll
            for (int e = 0; e < 8; e++) f[e] = (f[e] + bias8[e]) * sc;
            uint4 u;
            u.x = pack2(f[0], f[1]);
            u.y = pack2(f[2], f[3]);
            u.z = pack2(f[4], f[5]);
            u.w = pack2(f[6], f[7]);
            size_t off;
            if (MODE == 1) {
                off = (size_t)sl * 64;
            } else {
                int s = s0 + sl;
                int d5 = s & 31, w5 = (s >> 5) & 31, h5 = s >> 10;
                int window = ((h5 >> 2) * 8 + (w5 >> 2)) * 8 + (d5 >> 2);
                int token  = (((h5 & 3) * 4 + (w5 & 3)) * 4 + (d5 & 3));
                off = (size_t)window * 4096 + token * 64;
            }
            *reinterpret_cast<uint4*>(hbase + off) = u;
        }
    }
}

// =========================================================================
// Local windowed attention (wmma, no-max softmax) + pool sums + gn partials
// =========================================================================
__global__ void __launch_bounds__(128) local_attn_w_kernel(
    const __nv_bfloat16* __restrict__ qkvB, const float* __restrict__ x,
    float* __restrict__ attn, float* __restrict__ praw, float* __restrict__ part) {
    __shared__ __align__(16) __nv_bfloat16 QP[64 * 72];
    __shared__ __align__(16) __nv_bfloat16 Ks[64 * 72];
    __shared__ __align__(16) __nv_bfloat16 Vs[64 * 72];
    __shared__ __align__(16) float Sf[64 * 68];
    __shared__ float linv[64];
    __shared__ float rs[4], rss[4];

    int w = blockIdx.x, head = blockIdx.y, n = blockIdx.z;
    int tid = threadIdx.x, warp = tid >> 5;

    size_t base = (((size_t)(n * 3) * 4 + head) * 512 + w) * 4096;
    size_t step = (size_t)4 * 512 * 4096;
    const uint4* Qg = (const uint4*)(qkvB + base);
    const uint4* Kg = (const uint4*)(qkvB + base + step);
    const uint4* Vg = (const uint4*)(qkvB + base + 2 * step);

    #pragma unroll
    for (int i = 0; i < 4; i++) {
        int c = tid + i * 128;
        int r = c >> 3, q = c & 7;
        ((uint4*)(QP + r * 72))[q] = Qg[c];
        ((uint4*)(Ks + r * 72))[q] = Kg[c];
        ((uint4*)(Vs + r * 72))[q] = Vg[c];
    }
    __syncthreads();

    {
        int m = warp * 16;
        wmma::fragment<wmma::accumulator, 16, 16, 16, float> acc[4];
        #pragma unroll
        for (int j = 0; j < 4; j++) wmma::fill_fragment(acc[j], 0.f);
        #pragma unroll
        for (int kd = 0; kd < 4; kd++) {
            wmma::fragment<wmma::matrix_a, 16, 16, 16, __nv_bfloat16, wmma::row_major> af;
            wmma::load_matrix_sync(af, QP + m * 72 + kd * 16, 72);
            #pragma unroll
            for (int j = 0; j < 4; j++) {
                wmma::fragment<wmma::matrix_b, 16, 16, 16, __nv_bfloat16, wmma::col_major> bf;
                wmma::load_matrix_sync(bf, Ks + (j * 16) * 72 + kd * 16, 72);
                wmma::mma_sync(acc[j], af, bf, acc[j]);
            }
        }
        #pragma unroll
        for (int j = 0; j < 4; j++)
            wmma::store_matrix_sync(Sf + m * 68 + j * 16, acc[j], 68, wmma::mem_row_major);
    }
    __syncthreads();

    {
        int r = tid >> 1, hf = tid & 1;
        const float* srow = Sf + r * 68 + hf * 32;
        float ls = 0.f;
        __nv_bfloat16* prow = QP + r * 72 + hf * 32;
        #pragma unroll
        for (int j = 0; j < 32; j++) {
            float p = __expf(srow[j]);
            ls += p;
            prow[j] = __float2bfloat16(p);
        }
        ls += __shfl_xor_sync(0xffffffffu, ls, 1);
        if (hf == 0) linv[r] = 1.f / ls;
    }
    __syncthreads();

    {
        int m = warp * 16;
        wmma::fragment<wmma::accumulator, 16, 16, 16, float> acc[4];
        #pragma unroll
        for (int j = 0; j < 4; j++) wmma::fill_fragment(acc[j], 0.f);
        #pragma unroll
        for (int kk = 0; kk < 4; kk++) {
            wmma::fragment<wmma::matrix_a, 16, 16, 16, __nv_bfloat16, wmma::row_major> af;
            wmma::load_matrix_sync(af, QP + m * 72 + kk * 16, 72);
            #pragma unroll
            for (int j = 0; j < 4; j++) {
                wmma::fragment<wmma::matrix_b, 16, 16, 16, __nv_bfloat16, wmma::row_major> bf;
                wmma::load_matrix_sync(bf, Vs + (kk * 16) * 72 + j * 16, 72);
                wmma::mma_sync(acc[j], af, bf, acc[j]);
            }
        }
        #pragma unroll
        for (int j = 0; j < 4; j++)
            wmma::store_matrix_sync(Sf + m * 68 + j * 16, acc[j], 68, wmma::mem_row_major);
    }
    __syncthreads();

    int wh = w >> 6, ww = (w >> 3) & 7, wd = w & 7;
    int base_s = wh * 4096 + ww * 128 + wd * 4;
    int chb = n * 256 + head * 64;
    float s_acc = 0.f, ss_acc = 0.f;
    #pragma unroll
    for (int it = 0; it < 8; it++) {
        int idx = tid + it * 128;
        int d = idx >> 4, tg = idx & 15;
        int i_ = tg >> 2, j_ = tg & 3;
        int s = base_s + i_ * 1024 + j_ * 32;
        int t0 = tg * 4;
        size_t g = ((size_t)(chb + d)) * SV + s;
        float4 xv = *reinterpret_cast<const float4*>(x + g);
        float4 ov;
        ov.x = fmaf(Sf[(t0 + 0) * 68 + d], linv[t0 + 0], xv.x);
        ov.y = fmaf(Sf[(t0 + 1) * 68 + d], linv[t0 + 1], xv.y);
        ov.z = fmaf(Sf[(t0 + 2) * 68 + d], linv[t0 + 2], xv.z);
        ov.w = fmaf(Sf[(t0 + 3) * 68 + d], linv[t0 + 3], xv.w);
        *reinterpret_cast<float4*>(attn + g) = ov;
        float ps = ov.x + ov.y + ov.z + ov.w;
        s_acc  += ps;
        ss_acc += ov.x*ov.x + ov.y*ov.y + ov.z*ov.z + ov.w*ov.w;
        #pragma unroll
        for (int o = 8; o; o >>= 1) ps += __shfl_down_sync(0xffffffffu, ps, o);
        if ((tid & 15) == 0)
            praw[((size_t)(chb + d)) * 512 + w] = ps * (1.f / 64.f);
    }
    #pragma unroll
    for (int o = 16; o; o >>= 1) {
        s_acc  += __shfl_down_sync(0xffffffffu, s_acc, o);
        ss_acc += __shfl_down_sync(0xffffffffu, ss_acc, o);
    }
    if ((tid & 31) == 0) { rs[warp] = s_acc; rss[warp] = ss_acc; }
    __syncthreads();
    if (tid == 0) {
        size_t pi = (size_t)n * 2048 + head * 512 + w;
        part[pi * 2 + 0] = rs[0] + rs[1] + rs[2] + rs[3];
        part[pi * 2 + 1] = rss[0] + rss[1] + rss[2] + rss[3];
    }
}

// =========================================================================
// Global attention: no-max softmax, O persistent in accumulators,
// cp.async double-buffered K/V.
// =========================================================================
#define GA_SMEM 109056

__global__ void __launch_bounds__(256, 2) gattn_kernel(
    const __nv_bfloat16* __restrict__ q2T, const __nv_bfloat16* __restrict__ kvT,
    const float* __restrict__ attn,
    const float* __restrict__ A1, const float* __restrict__ D1,
    __nv_bfloat16* __restrict__ ghi, __nv_bfloat16* __restrict__ glo) {
    extern __shared__ __align__(16) char sm[];
    __nv_bfloat16* Qs = (__nv_bfloat16*)sm;
    __nv_bfloat16* Ks = Qs + 128 * 72;
    __nv_bfloat16* Vs = Ks + 2 * 64 * 72;
    __nv_bfloat16* Ps = Vs + 2 * 64 * 72;
    float* Sf   = (float*)(Ps + 128 * 72);
    float* lrow = Sf + 128 * 68;

    int tid = threadIdx.x, warp = tid >> 5;
    int h = blockIdx.y, n = blockIdx.z;
    int s0 = blockIdx.x * 128;

    const uint4* Qg = (const uint4*)(q2T + ((size_t)(n * 4 + h) * SV + s0) * 64);
    const __nv_bfloat16* Kg = kvT + ((size_t)(n * 8 + h) * 512) * 64;
    const __nv_bfloat16* Vg = kvT + ((size_t)(n * 8 + 4 + h) * 512) * 64;

    auto prefetchKV = [&](int ch, int b) {
        #pragma unroll
        for (int i = 0; i < 2; i++) {
            int idx = tid + i * 256;
            int r = idx >> 3, c = (idx & 7) * 8;
            cp16(Ks + b * 4608 + r * 72 + c, Kg + (size_t)(ch * 64 + r) * 64 + c);
            cp16(Vs + b * 4608 + r * 72 + c, Vg + (size_t)(ch * 64 + r) * 64 + c);
        }
    };

    prefetchKV(0, 0); CP_COMMIT;

    #pragma unroll
    for (int i = 0; i < 4; i++) {
        int idx = tid + i * 256;
        int r = idx >> 3, c = idx & 7;
        ((uint4*)(Qs + r * 72))[c] = Qg[r * 8 + c];
    }
    if (tid < 128) lrow[tid] = 0.f;

    int pm = warp >> 1, pn = warp & 1;
    wmma::fragment<wmma::accumulator, 16, 16, 16, float> acc_o[2][2];
    #pragma unroll
    for (int i = 0; i < 2; i++)
        #pragma unroll
        for (int j = 0; j < 2; j++) wmma::fill_fragment(acc_o[i][j], 0.f);

    for (int ch = 0; ch < 8; ch++) {
        int b = ch & 1;
        CP_WAIT0;
        __syncthreads();

        {
            int m = warp * 16;
            wmma::fragment<wmma::accumulator, 16, 16, 16, float> acc[4];
            #pragma unroll
            for (int j = 0; j < 4; j++) wmma::fill_fragment(acc[j], 0.f);
            #pragma unroll
            for (int kd = 0; kd < 4; kd++) {
                wmma::fragment<wmma::matrix_a, 16, 16, 16, __nv_bfloat16, wmma::row_major> af;
                wmma::load_matrix_sync(af, Qs + m * 72 + kd * 16, 72);
                #pragma unroll
                for (int j = 0; j < 4; j++) {
                    wmma::fragment<wmma::matrix_b, 16, 16, 16, __nv_bfloat16, wmma::col_major> bf;
                    wmma::load_matrix_sync(bf, Ks + b * 4608 + (j * 16) * 72 + kd * 16, 72);
                    wmma::mma_sync(acc[j], af, bf, acc[j]);
                }
            }
            #pragma unroll
            for (int j = 0; j < 4; j++)
                wmma::store_matrix_sync(Sf + m * 68 + j * 16, acc[j], 68, wmma::mem_row_major);
        }
        __syncthreads();

        {
            int r = tid >> 1, hf = tid & 1;
            const float* srow = Sf + r * 68 + hf * 32;
            float ls = 0.f;
            __nv_bfloat16* prow = Ps + r * 72 + hf * 32;
            #pragma unroll
            for (int j = 0; j < 32; j++) {
                float p = __expf(srow[j]);
                ls += p;
                prow[j] = __float2bfloat16(p);
            }
            ls += __shfl_xor_sync(0xffffffffu, ls, 1);
            if (hf == 0) lrow[r] += ls;
        }
        __syncthreads();

        if (ch + 1 < 8) {
            prefetchKV(ch + 1, b ^ 1);
            CP_COMMIT;
        }

        {
            #pragma unroll
            for (int kk = 0; kk < 4; kk++) {
                wmma::fragment<wmma::matrix_a, 16, 16, 16, __nv_bfloat16, wmma::row_major> af[2];
                #pragma unroll
                for (int i = 0; i < 2; i++)
                    wmma::load_matrix_sync(af[i], Ps + (pm * 32 + i * 16) * 72 + kk * 16, 72);
                wmma::fragment<wmma::matrix_b, 16, 16, 16, __nv_bfloat16, wmma::row_major> bf[2];
                #pragma unroll
                for (int j = 0; j < 2; j++)
                    wmma::load_matrix_sync(bf[j], Vs + b * 4608 + (kk * 16) * 72 + pn * 32 + j * 16, 72);
                #pragma unroll
                for (int i = 0; i < 2; i++)
                    #pragma unroll
                    for (int j = 0; j < 2; j++)
                        wmma::mma_sync(acc_o[i][j], af[i], bf[j], acc_o[i][j]);
            }
        }
    }

    __syncthreads();
    #pragma unroll
    for (int i = 0; i < 2; i++)
        #pragma unroll
        for (int j = 0; j < 2; j++)
            wmma::store_matrix_sync(Sf + (pm * 32 + i * 16) * 68 + pn * 32 + j * 16,
                                    acc_o[i][j], 68, wmma::mem_row_major);
    __syncthreads();

    #pragma unroll
    for (int i = 0; i < 32; i++) {
        int idx = tid + i * 256;
        int r = idx & 127, d = idx >> 7;
        int cch = n * 256 + h * 64 + d;
        float v = Sf[r * 68 + d] / lrow[r];
        size_t gi = ((size_t)cch) * SV + s0 + r;
        float t = v + fmaf(A1[cch], attn[gi], D1[cch]);
        __nv_bfloat16 hi = __float2bfloat16(t);
        ghi[gi] = hi;
        glo[gi] = __float2bfloat16(t - __bfloat162float(hi));
    }
}

// =========================================================================
// host launch
// =========================================================================
extern "C" void kernel_launch(void* const* d_in, const int* in_sizes, int n_in,
                              void* d_out, int out_size) {
    const float* x      = (const float*)d_in[0];
    const float* qkv_w  = (const float*)d_in[1];
    const float* qkv_b  = (const float*)d_in[2];
    const float* norm_w = (const float*)d_in[3];
    const float* norm_b = (const float*)d_in[4];
    const float* anorm_w= (const float*)d_in[5];
    const float* anorm_b= (const float*)d_in[6];
    const float* dnorm_w= (const float*)d_in[7];
    const float* dnorm_b= (const float*)d_in[8];
    const float* q_w    = (const float*)d_in[9];
    const float* q_b    = (const float*)d_in[10];
    const float* kv_w   = (const float*)d_in[11];
    const float* kv_b   = (const float*)d_in[12];
    const float* proj_w = (const float*)d_in[13];
    const float* proj_b = (const float*)d_in[14];
    float* out = (float*)d_out;

    float *attn, *praw, *pnorm, *part, *part2, *aff, *qkvb2, *qb2;
    __nv_bfloat16 *xB, *qkvB, *attnB, *ghi, *glo, *pooledB, *q2T, *kvT;
    __nv_bfloat16 *Wqkv2B, *Wq2B, *WkvB, *WprojB;
    cudaGetSymbolAddress((void**)&attn,    g_attn);
    cudaGetSymbolAddress((void**)&praw,    g_praw);
    cudaGetSymbolAddress((void**)&pnorm,   g_pnorm);
    cudaGetSymbolAddress((void**)&xB,      g_xB);
    cudaGetSymbolAddress((void**)&qkvB,    g_qkvB);
    cudaGetSymbolAddress((void**)&attnB,   g_attnB);
    cudaGetSymbolAddress((void**)&ghi,     g_ghi);
    cudaGetSymbolAddress((void**)&glo,     g_glo);
    cudaGetSymbolAddress((void**)&pooledB, g_pooledB);
    cudaGetSymbolAddress((void**)&q2T,     g_q2T);
    cudaGetSymbolAddress((void**)&kvT,     g_kvT);
    cudaGetSymbolAddress((void**)&Wqkv2B,  g_Wqkv2B);
    cudaGetSymbolAddress((void**)&Wq2B,    g_Wq2B);
    cudaGetSymbolAddress((void**)&WkvB,    g_WkvB);
    cudaGetSymbolAddress((void**)&WprojB,  g_WprojB);
    cudaGetSymbolAddress((void**)&qkvb2,   g_qkvb2);
    cudaGetSymbolAddress((void**)&qb2,     g_qb2);
    cudaGetSymbolAddress((void**)&part,    g_part);
    cudaGetSymbolAddress((void**)&part2,   g_part2);
    cudaGetSymbolAddress((void**)&aff,     g_aff);

    static cudaStream_t s1 = nullptr;
    static cudaEvent_t ev0, evS1a, evA, evB, evA1, evKV;
    static bool init_done = false;
    if (!init_done) {
        cudaFuncSetAttribute(gattn_kernel, cudaFuncAttributeMaxDynamicSharedMemorySize, GA_SMEM);
        cudaFuncSetAttribute(wgemm3_kernel<0>, cudaFuncAttributeMaxDynamicSharedMemorySize, WG_SMEM);
        cudaFuncSetAttribute(wgemm3_kernel<1>, cudaFuncAttributeMaxDynamicSharedMemorySize, WG_SMEM);
        cudaFuncSetAttribute(wgemm3_kernel<2>, cudaFuncAttributeMaxDynamicSharedMemorySize, WG_SMEM);
        cudaStreamCreateWithFlags(&s1, cudaStreamNonBlocking);
        cudaEventCreateWithFlags(&ev0,  cudaEventDisableTiming);
        cudaEventCreateWithFlags(&evS1a, cudaEventDisableTiming);
        cudaEventCreateWithFlags(&evA,  cudaEventDisableTiming);
        cudaEventCreateWithFlags(&evB,  cudaEventDisableTiming);
        cudaEventCreateWithFlags(&evA1, cudaEventDisableTiming);
        cudaEventCreateWithFlags(&evKV, cudaEventDisableTiming);
        init_done = true;
    }

    float* A0 = aff;        float* D0 = aff + 512;
    float* A1 = aff + 1024; float* D1 = aff + 1536;
    float* A2 = aff + 2048; float* D2 = aff + 2560;

    // ---- fork: side = plain x->bf16 + kv/proj weight convert; main = stats+fold ----
    cudaEventRecord(ev0, 0);
    cudaStreamWaitEvent(s1, ev0, 0);
    convert_plain_kernel<<<8192, 256, 0, s1>>>(x, xB);
    convert_weights_kernel<<<1280, 256, 0, s1>>>(kv_w, proj_w, WkvB, WprojB);
    cudaEventRecord(evS1a, s1);

    reduce1_kernel<<<dim3(512, NB), 256>>>(x, 256L * SV / 4, part);
    stats2affine_kernel<<<NB, 256>>>(part, 512, norm_w, norm_b, A0, D0, 1.f / (256.f * 32768.f));
    fold_kernel<<<dim3(768, NB), 256>>>(qkv_w, qkv_b, A0, D0, Wqkv2B, qkvb2, 768);

    cudaStreamWaitEvent(0, evS1a, 0);

    // qkv conv (folded per-batch weights) -> window-gathered bf16 (q * 1/16)
    wgemm3_kernel<2><<<dim3(6, 256, NB), 256, WG_SMEM>>>(
        Wqkv2B, xB, xB, qkvb2, nullptr, qkvB, 768, (int)SV, 256, SCALE_INV,
        768L * 256, 768);

    // local attention: attn(raw) + pooled sums + gn partials
    local_attn_w_kernel<<<dim3(512, NH, NB), 128>>>(qkvB, x, attn, praw, part);

    // ---- fork: side = attnB plain convert, then pooled/kv chain after A1 ----
    cudaEventRecord(evA, 0);
    cudaStreamWaitEvent(s1, evA, 0);
    convert_plain_kernel<<<8192, 256, 0, s1>>>(attn, attnB);
    cudaEventRecord(evB, s1);

    // main: anorm affine + fold q weights
    stats2affine_kernel<<<NB, 256>>>(part, 2048, anorm_w, anorm_b, A1, D1, 1.f / (256.f * 32768.f));
    cudaEventRecord(evA1, 0);
    fold_kernel<<<dim3(256, NB), 256>>>(q_w, q_b, A1, D1, Wq2B, qb2, 256);

    // side: pooled chain (needs A1) -> kv gemm
    cudaStreamWaitEvent(s1, evA1, 0);
    apply_pool_affine_kernel<<<256, 256, 0, s1>>>(praw, A1, D1, pnorm);
    reduce1_kernel<<<dim3(32, NB), 256, 0, s1>>>(pnorm, 256L * 512 / 4, part2);
    stats2affine_kernel<<<NB, 256, 0, s1>>>(part2, 32, dnorm_w, dnorm_b, A2, D2, 1.f / (256.f * 512.f));
    convert_pooled_kernel<<<256, 256, 0, s1>>>(pnorm, A2, D2, pooledB);
    wgemm3_kernel<1><<<dim3(4, 4, NB), 256, WG_SMEM, s1>>>(
        WkvB, pooledB, pooledB, kv_b, nullptr, kvT, 512, 512, 256, 1.f, 0, 0);
    cudaEventRecord(evKV, s1);

    // main: q gemm (folded weights on raw attnB) -> q2T (scaled 1/16)
    cudaStreamWaitEvent(0, evB, 0);
    wgemm3_kernel<1><<<dim3(2, 256, NB), 256, WG_SMEM>>>(
        Wq2B, attnB, attnB, qb2, nullptr, q2T, 256, (int)SV, 256, SCALE_INV,
        256L * 256, 256);

    cudaStreamWaitEvent(0, evKV, 0);

    // global attention + affine residual -> bf16 hi/lo
    gattn_kernel<<<dim3(256, NH, NB), 256, GA_SMEM>>>(q2T, kvT, attn, A1, D1, ghi, glo);

    // final projection (3-term bf16 split) -> out
    wgemm3_kernel<0><<<dim3(2, 256, NB), 256, WG_SMEM>>>(
        WprojB, ghi, glo, proj_b, out, nullptr, 256, (int)SV, 768, 1.f, 0, 0);
}

// round 13
// speedup vs baseline: 1.3548x; 1.0117x over previous
#include <cuda_runtime.h>
#include <cuda_bf16.h>
#include <mma.h>
#include <math.h>
#include <stdint.h>

using namespace nvcuda;

#define NB 2
#define CH 256
#define SV 32768L
#define NH 4
#define HD 64
#define SCALE_INV 0.0625f
#define EPS 1e-6f

__device__ __forceinline__ unsigned pack2(float a, float b) {
    __nv_bfloat162 t = __floats2bfloat162_rn(a, b);
    return *reinterpret_cast<unsigned*>(&t);
}

// ---------------- scratch ----------------
__device__ __align__(16) float g_attn   [NB * 256L * SV];
__device__ __align__(16) float g_praw   [NB * 256 * 512];
__device__ __align__(16) float g_pnorm  [NB * 256 * 512];
__device__ __align__(16) __nv_bfloat16 g_xB    [NB * 256L * SV];
__device__ __align__(16) __nv_bfloat16 g_qkvB  [NB * 768L * SV];
__device__ __align__(16) __nv_bfloat16 g_attnB [NB * 256L * SV];
__device__ __align__(16) __nv_bfloat16 g_ghi   [NB * 256L * SV];
__device__ __align__(16) __nv_bfloat16 g_glo   [NB * 256L * SV];
__device__ __align__(16) __nv_bfloat16 g_pooledB[NB * 256 * 512];
__device__ __align__(16) __nv_bfloat16 g_q2T   [NB * 4L * SV * 64];
__device__ __align__(16) __nv_bfloat16 g_kvT   [NB * 8L * 512 * 64];
__device__ __align__(16) __nv_bfloat16 g_Wqkv2B[NB * 768 * 256];
__device__ __align__(16) __nv_bfloat16 g_Wq2B  [NB * 256 * 256];
__device__ __align__(16) __nv_bfloat16 g_WkvB  [512 * 256];
__device__ __align__(16) __nv_bfloat16 g_WprojB[256 * 768];
__device__ float g_qkvb2[NB * 768];
__device__ float g_qb2  [NB * 256];
__device__ float g_part [NB * 2048 * 2];
__device__ float g_part2[NB * 64 * 2];
__device__ float g_aff  [6 * NB * 256];

// ---------------- cp.async ----------------
__device__ __forceinline__ void cp16(void* dst, const void* src) {
    unsigned d = (unsigned)__cvta_generic_to_shared(dst);
    asm volatile("cp.async.cg.shared.global [%0], [%1], 16;\n" :: "r"(d), "l"(src));
}
#define CP_COMMIT asm volatile("cp.async.commit_group;\n" ::: "memory")
#define CP_WAIT1  asm volatile("cp.async.wait_group 1;\n" ::: "memory")
#define CP_WAIT0  asm volatile("cp.async.wait_group 0;\n" ::: "memory")

// =========================================================================
// reductions / affine / conversions
// =========================================================================
// fused: stats partials over x AND raw bf16 conversion in one pass
__global__ void reduce1x_kernel(const float* __restrict__ buf, long per4,
                                float* __restrict__ part, __nv_bfloat16* __restrict__ outB) {
    int n = blockIdx.y;
    const float4* p = reinterpret_cast<const float4*>(buf) + (size_t)n * per4;
    uint2* ob = reinterpret_cast<uint2*>(outB) + (size_t)n * per4;
    float s = 0.f, ss = 0.f;
    for (long i = (long)blockIdx.x * blockDim.x + threadIdx.x; i < per4;
         i += (long)gridDim.x * blockDim.x) {
        float4 v = p[i];
        s  += v.x + v.y + v.z + v.w;
        ss += v.x*v.x + v.y*v.y + v.z*v.z + v.w*v.w;
        uint2 r;
        r.x = pack2(v.x, v.y);
        r.y = pack2(v.z, v.w);
        ob[i] = r;
    }
    for (int o = 16; o; o >>= 1) {
        s  += __shfl_down_sync(0xffffffffu, s, o);
        ss += __shfl_down_sync(0xffffffffu, ss, o);
    }
    __shared__ float sh[64];
    int w = threadIdx.x >> 5;
    if ((threadIdx.x & 31) == 0) { sh[w] = s; sh[32 + w] = ss; }
    __syncthreads();
    if (threadIdx.x < 32) {
        int nw = blockDim.x >> 5;
        s  = (threadIdx.x < nw) ? sh[threadIdx.x]      : 0.f;
        ss = (threadIdx.x < nw) ? sh[32 + threadIdx.x] : 0.f;
        for (int o = 16; o; o >>= 1) {
            s  += __shfl_down_sync(0xffffffffu, s, o);
            ss += __shfl_down_sync(0xffffffffu, ss, o);
        }
        if (threadIdx.x == 0) {
            part[((size_t)n * gridDim.x + blockIdx.x) * 2 + 0] = s;
            part[((size_t)n * gridDim.x + blockIdx.x) * 2 + 1] = ss;
        }
    }
}

__global__ void reduce1_kernel(const float* __restrict__ buf, long per4, float* __restrict__ part) {
    int n = blockIdx.y;
    const float4* p = reinterpret_cast<const float4*>(buf) + (size_t)n * per4;
    float s = 0.f, ss = 0.f;
    for (long i = (long)blockIdx.x * blockDim.x + threadIdx.x; i < per4;
         i += (long)gridDim.x * blockDim.x) {
        float4 v = p[i];
        s  += v.x + v.y + v.z + v.w;
        ss += v.x*v.x + v.y*v.y + v.z*v.z + v.w*v.w;
    }
    for (int o = 16; o; o >>= 1) {
        s  += __shfl_down_sync(0xffffffffu, s, o);
        ss += __shfl_down_sync(0xffffffffu, ss, o);
    }
    __shared__ float sh[64];
    int w = threadIdx.x >> 5;
    if ((threadIdx.x & 31) == 0) { sh[w] = s; sh[32 + w] = ss; }
    __syncthreads();
    if (threadIdx.x < 32) {
        int nw = blockDim.x >> 5;
        s  = (threadIdx.x < nw) ? sh[threadIdx.x]      : 0.f;
        ss = (threadIdx.x < nw) ? sh[32 + threadIdx.x] : 0.f;
        for (int o = 16; o; o >>= 1) {
            s  += __shfl_down_sync(0xffffffffu, s, o);
            ss += __shfl_down_sync(0xffffffffu, ss, o);
        }
        if (threadIdx.x == 0) {
            part[((size_t)n * gridDim.x + blockIdx.x) * 2 + 0] = s;
            part[((size_t)n * gridDim.x + blockIdx.x) * 2 + 1] = ss;
        }
    }
}

__global__ void stats2affine_kernel(const float* __restrict__ part, int nb,
                                    const float* __restrict__ w, const float* __restrict__ b,
                                    float* __restrict__ a, float* __restrict__ d,
                                    float inv_cnt) {
    int n = blockIdx.x, tid = threadIdx.x;
    float s = 0.f, ss = 0.f;
    for (int i = tid; i < nb; i += 256) {
        s  += part[((size_t)n * nb + i) * 2 + 0];
        ss += part[((size_t)n * nb + i) * 2 + 1];
    }
    for (int o = 16; o; o >>= 1) {
        s  += __shfl_down_sync(0xffffffffu, s, o);
        ss += __shfl_down_sync(0xffffffffu, ss, o);
    }
    __shared__ float sh[16];
    __shared__ float sm_mean, sm_rstd;
    int wp = tid >> 5;
    if ((tid & 31) == 0) { sh[wp] = s; sh[8 + wp] = ss; }
    __syncthreads();
    if (tid < 32) {
        s  = (tid < 8) ? sh[tid]     : 0.f;
        ss = (tid < 8) ? sh[8 + tid] : 0.f;
        for (int o = 4; o; o >>= 1) {
            s  += __shfl_down_sync(0xffffffffu, s, o);
            ss += __shfl_down_sync(0xffffffffu, ss, o);
        }
        if (tid == 0) {
            float mean = s * inv_cnt;
            float var  = ss * inv_cnt - mean * mean;
            sm_mean = mean;
            sm_rstd = rsqrtf(var + EPS);
        }
    }
    __syncthreads();
    float mean = sm_mean, rstd = sm_rstd;
    a[n * CH + tid] = w[tid] * rstd;
    d[n * CH + tid] = b[tid] - mean * rstd * w[tid];
}

__global__ void convert_plain_kernel(const float* __restrict__ x, __nv_bfloat16* __restrict__ out) {
    size_t i8 = (size_t)blockIdx.x * blockDim.x + threadIdx.x;
    const float4* p = reinterpret_cast<const float4*>(x) + i8 * 2;
    float4 v0 = p[0], v1 = p[1];
    uint4 u;
    u.x = pack2(v0.x, v0.y);
    u.y = pack2(v0.z, v0.w);
    u.z = pack2(v1.x, v1.y);
    u.w = pack2(v1.z, v1.w);
    reinterpret_cast<uint4*>(out)[i8] = u;
}

__global__ void fold_kernel(const float* __restrict__ W, const float* __restrict__ bsrc,
                            const float* __restrict__ A, const float* __restrict__ D,
                            __nv_bfloat16* __restrict__ W2, float* __restrict__ b2, int Mrows) {
    int m = blockIdx.x, n = blockIdx.y, tid = threadIdx.x;
    float w = W[(size_t)m * 256 + tid];
    float aa = A[n * 256 + tid], dd = D[n * 256 + tid];
    W2[((size_t)n * Mrows + m) * 256 + tid] = __float2bfloat16(w * aa);
    float pr = w * dd;
    for (int o = 16; o; o >>= 1) pr += __shfl_down_sync(0xffffffffu, pr, o);
    __shared__ float sh[8];
    if ((tid & 31) == 0) sh[tid >> 5] = pr;
    __syncthreads();
    if (tid == 0) {
        float t = 0.f;
        #pragma unroll
        for (int i = 0; i < 8; i++) t += sh[i];
        b2[n * Mrows + m] = bsrc[m] + t;
    }
}

__global__ void apply_pool_affine_kernel(const float* __restrict__ praw,
                                         const float* __restrict__ a, const float* __restrict__ d,
                                         float* __restrict__ pnorm) {
    size_t i4 = (size_t)blockIdx.x * blockDim.x + threadIdx.x;
    int c = (int)((i4 >> 7) & 255);
    int n = (int)(i4 >> 15);
    float aa = a[n * CH + c], dd = d[n * CH + c];
    float4 v = reinterpret_cast<const float4*>(praw)[i4];
    v.x = fmaf(aa, v.x, dd); v.y = fmaf(aa, v.y, dd);
    v.z = fmaf(aa, v.z, dd); v.w = fmaf(aa, v.w, dd);
    reinterpret_cast<float4*>(pnorm)[i4] = v;
}

__global__ void convert_pooled_kernel(const float* __restrict__ pooled,
                                      const float* __restrict__ a, const float* __restrict__ d,
                                      __nv_bfloat16* __restrict__ out) {
    size_t i4 = (size_t)blockIdx.x * blockDim.x + threadIdx.x;
    int c = (int)((i4 >> 7) & 255);
    int n = (int)(i4 >> 15);
    float aa = a[n * CH + c], dd = d[n * CH + c];
    float4 v = reinterpret_cast<const float4*>(pooled)[i4];
    uint2 r;
    r.x = pack2(fmaf(aa, v.x, dd), fmaf(aa, v.y, dd));
    r.y = pack2(fmaf(aa, v.z, dd), fmaf(aa, v.w, dd));
    reinterpret_cast<uint2*>(out)[i4] = r;
}

__global__ void convert_weights_kernel(
    const float* __restrict__ kv_w, const float* __restrict__ proj_w,
    __nv_bfloat16* __restrict__ Wkv, __nv_bfloat16* __restrict__ Wproj) {
    int idx = blockIdx.x * blockDim.x + threadIdx.x;
    const int T1 = 512 * 256, T2 = T1 + 256 * 768;
    if (idx < T1) {
        Wkv[idx] = __float2bfloat16(kv_w[idx]);
    } else if (idx < T2) {
        int j = idx - T1;
        int m = j / 768, k = j % 768;
        float v = proj_w[m * 256 + (k & 255)];
        __nv_bfloat16 hi = __float2bfloat16(v);
        if (k >= 256 && k < 512) hi = __float2bfloat16(v - __bfloat162float(hi));
        Wproj[j] = hi;
    }
}

// =========================================================================
// wgemm3: BM=128, BN=128, BK=32, 3-stage cp.async, 256 threads, 2 blocks/SM.
// =========================================================================
#define WG_SMEM 69632

template<int MODE>
__global__ void __launch_bounds__(256, 2) wgemm3_kernel(
    const __nv_bfloat16* __restrict__ A,
    const __nv_bfloat16* __restrict__ B0, const __nv_bfloat16* __restrict__ B1,
    const float* __restrict__ bias,
    float* __restrict__ outF, __nv_bfloat16* __restrict__ outB,
    int M, int S, int KT, float qScale, long aStride, int biasStride) {
    extern __shared__ __align__(16) char dsm[];
    __nv_bfloat16* As = (__nv_bfloat16*)dsm;
    __nv_bfloat16* Bs = (__nv_bfloat16*)(dsm + 30720);
    float* Cs = (float*)dsm;

    int tid = threadIdx.x, warp = tid >> 5;
    int wm = warp >> 2, wn = warp & 3;
    int m0 = blockIdx.x * 128;
    int s0 = blockIdx.y * 128;
    int z  = blockIdx.z;

    const __nv_bfloat16* Az = A + (size_t)z * aStride;
    const float* biasz = bias + (size_t)z * biasStride;
    const __nv_bfloat16* Bb0 = B0 + (size_t)z * 256 * S;
    const __nv_bfloat16* Bb1 = B1 + (size_t)z * 256 * S;

    wmma::fragment<wmma::accumulator, 16, 16, 16, float> acc[4][2];
    #pragma unroll
    for (int i = 0; i < 4; i++)
        #pragma unroll
        for (int j = 0; j < 2; j++) wmma::fill_fragment(acc[i][j], 0.f);

    const int NIT = KT >> 5;

    auto prefetch = [&](int it, int buf) {
        int ktL = it * 32;
        #pragma unroll
        for (int i = 0; i < 2; i++) {
            int c = tid + i * 256;
            int r = c >> 2, q = (c & 3) * 8;
            cp16(As + buf * 5120 + r * 40 + q,
                 Az + (size_t)(m0 + r) * KT + ktL + q);
        }
        const __nv_bfloat16* Bp = (ktL < 512) ? Bb0 : Bb1;
        int krow = ktL & 255;
        #pragma unroll
        for (int i = 0; i < 2; i++) {
            int c = tid + i * 256;
            int r = c >> 4, q = (c & 15) * 8;
            cp16(Bs + buf * 4352 + r * 136 + q,
                 Bp + (size_t)(krow + r) * S + s0 + q);
        }
    };

    prefetch(0, 0); CP_COMMIT;
    prefetch(1, 1); CP_COMMIT;

    int buf = 0;
    for (int it = 0; it < NIT; it++) {
        if (it + 1 < NIT) CP_WAIT1; else CP_WAIT0;
        __syncthreads();
        #pragma unroll
        for (int ks = 0; ks < 2; ks++) {
            wmma::fragment<wmma::matrix_a, 16, 16, 16, __nv_bfloat16, wmma::row_major> af[4];
            #pragma unroll
            for (int i = 0; i < 4; i++)
                wmma::load_matrix_sync(af[i], As + buf * 5120 + (wm * 64 + i * 16) * 40 + ks * 16, 40);
            wmma::fragment<wmma::matrix_b, 16, 16, 16, __nv_bfloat16, wmma::row_major> bf[2];
            #pragma unroll
            for (int j = 0; j < 2; j++)
                wmma::load_matrix_sync(bf[j], Bs + buf * 4352 + (ks * 16) * 136 + wn * 32 + j * 16, 136);
            #pragma unroll
            for (int i = 0; i < 4; i++)
                #pragma unroll
                for (int j = 0; j < 2; j++)
                    wmma::mma_sync(acc[i][j], af[i], bf[j], acc[i][j]);
        }
        if (it + 2 < NIT) {
            prefetch(it + 2, (buf + 2) % 3);
            CP_COMMIT;
        }
        buf = (buf + 1) % 3;
    }

    __syncthreads();

    if (MODE == 0) {
        #pragma unroll
        for (int i = 0; i < 4; i++)
            #pragma unroll
            for (int j = 0; j < 2; j++)
                wmma::store_matrix_sync(Cs + (wm * 64 + i * 16) * 132 + wn * 32 + j * 16,
                                        acc[i][j], 132, wmma::mem_row_major);
        __syncthreads();
        float* Ob = outF + ((size_t)z * M + m0) * S;
        #pragma unroll
        for (int it = 0; it < 16; it++) {
            int idx = tid + it * 256;
            int r = idx >> 5, c4 = idx & 31;
            float bv = biasz[m0 + r];
            float4 v = *reinterpret_cast<const float4*>(&Cs[r * 132 + c4 * 4]);
            v.x += bv; v.y += bv; v.z += bv; v.w += bv;
            *reinterpret_cast<float4*>(&Ob[(size_t)r * S + s0 + c4 * 4]) = v;
        }
    } else {
        #pragma unroll
        for (int i = 0; i < 4; i++)
            #pragma unroll
            for (int j = 0; j < 2; j++)
                wmma::store_matrix_sync(Cs + (wn * 32 + j * 16) * 136 + wm * 64 + i * 16,
                                        acc[i][j], 136, wmma::mem_col_major);
        __syncthreads();

        int dg = tid & 15;
        int gmb = m0 + dg * 8;
        float bias8[8];
        #pragma unroll
        for (int e = 0; e < 8; e++) bias8[e] = biasz[gmb + e];

        float sc;
        int db = gmb & 63;
        __nv_bfloat16* hbase;
        if (MODE == 1) {
            int hb = gmb >> 6;
            sc = qScale;
            hbase = outB + ((size_t)(z * (M >> 6) + hb) * S + s0) * 64 + db;
        } else {
            int sel = gmb >> 8, head = (gmb >> 6) & 3;
            sc = (sel == 0) ? qScale : 1.f;
            hbase = outB + (((size_t)(z * 3 + sel) * 4 + head) * 512) * 4096 + db;
        }

        #pragma unroll
        for (int it = 0; it < 8; it++) {
            int sl = it * 16 + (tid >> 4);
            float4 lo = *reinterpret_cast<const float4*>(&Cs[sl * 136 + dg * 8]);
            float4 hi = *reinterpret_cast<const float4*>(&Cs[sl * 136 + dg * 8 + 4]);
            float f[8] = {lo.x, lo.y, lo.z, lo.w, hi.x, hi.y, hi.z, hi.w};
            #pragma unroll
            for (int e = 0; e < 8; e++) f[e] = (f[e] + bias8[e]) * sc;
            uint4 u;
            u.x = pack2(f[0], f[1]);
            u.y = pack2(f[2], f[3]);
            u.z = pack2(f[4], f[5]);
            u.w = pack2(f[6], f[7]);
            size_t off;
            if (MODE == 1) {
                off = (size_t)sl * 64;
            } else {
                int s = s0 + sl;
                int d5 = s & 31, w5 = (s >> 5) & 31, h5 = s >> 10;
                int window = ((h5 >> 2) * 8 + (w5 >> 2)) * 8 + (d5 >> 2);
                int token  = (((h5 & 3) * 4 + (w5 & 3)) * 4 + (d5 & 3));
                off = (size_t)window * 4096 + token * 64;
            }
            *reinterpret_cast<uint4*>(hbase + off) = u;
        }
    }
}

// =========================================================================
// Local windowed attention (wmma, no-max softmax) + pool sums + gn partials
// =========================================================================
__global__ void __launch_bounds__(128) local_attn_w_kernel(
    const __nv_bfloat16* __restrict__ qkvB, const float* __restrict__ x,
    float* __restrict__ attn, float* __restrict__ praw, float* __restrict__ part) {
    __shared__ __align__(16) __nv_bfloat16 QP[64 * 72];
    __shared__ __align__(16) __nv_bfloat16 Ks[64 * 72];
    __shared__ __align__(16) __nv_bfloat16 Vs[64 * 72];
    __shared__ __align__(16) float Sf[64 * 68];
    __shared__ float linv[64];
    __shared__ float rs[4], rss[4];

    int w = blockIdx.x, head = blockIdx.y, n = blockIdx.z;
    int tid = threadIdx.x, warp = tid >> 5;

    size_t base = (((size_t)(n * 3) * 4 + head) * 512 + w) * 4096;
    size_t step = (size_t)4 * 512 * 4096;
    const uint4* Qg = (const uint4*)(qkvB + base);
    const uint4* Kg = (const uint4*)(qkvB + base + step);
    const uint4* Vg = (const uint4*)(qkvB + base + 2 * step);

    #pragma unroll
    for (int i = 0; i < 4; i++) {
        int c = tid + i * 128;
        int r = c >> 3, q = c & 7;
        ((uint4*)(QP + r * 72))[q] = Qg[c];
        ((uint4*)(Ks + r * 72))[q] = Kg[c];
        ((uint4*)(Vs + r * 72))[q] = Vg[c];
    }
    __syncthreads();

    {
        int m = warp * 16;
        wmma::fragment<wmma::accumulator, 16, 16, 16, float> acc[4];
        #pragma unroll
        for (int j = 0; j < 4; j++) wmma::fill_fragment(acc[j], 0.f);
        #pragma unroll
        for (int kd = 0; kd < 4; kd++) {
            wmma::fragment<wmma::matrix_a, 16, 16, 16, __nv_bfloat16, wmma::row_major> af;
            wmma::load_matrix_sync(af, QP + m * 72 + kd * 16, 72);
            #pragma unroll
            for (int j = 0; j < 4; j++) {
                wmma::fragment<wmma::matrix_b, 16, 16, 16, __nv_bfloat16, wmma::col_major> bf;
                wmma::load_matrix_sync(bf, Ks + (j * 16) * 72 + kd * 16, 72);
                wmma::mma_sync(acc[j], af, bf, acc[j]);
            }
        }
        #pragma unroll
        for (int j = 0; j < 4; j++)
            wmma::store_matrix_sync(Sf + m * 68 + j * 16, acc[j], 68, wmma::mem_row_major);
    }
    __syncthreads();

    {
        int r = tid >> 1, hf = tid & 1;
        const float* srow = Sf + r * 68 + hf * 32;
        float ls = 0.f;
        __nv_bfloat16* prow = QP + r * 72 + hf * 32;
        #pragma unroll
        for (int j = 0; j < 32; j++) {
            float p = __expf(srow[j]);
            ls += p;
            prow[j] = __float2bfloat16(p);
        }
        ls += __shfl_xor_sync(0xffffffffu, ls, 1);
        if (hf == 0) linv[r] = 1.f / ls;
    }
    __syncthreads();

    {
        int m = warp * 16;
        wmma::fragment<wmma::accumulator, 16, 16, 16, float> acc[4];
        #pragma unroll
        for (int j = 0; j < 4; j++) wmma::fill_fragment(acc[j], 0.f);
        #pragma unroll
        for (int kk = 0; kk < 4; kk++) {
            wmma::fragment<wmma::matrix_a, 16, 16, 16, __nv_bfloat16, wmma::row_major> af;
            wmma::load_matrix_sync(af, QP + m * 72 + kk * 16, 72);
            #pragma unroll
            for (int j = 0; j < 4; j++) {
                wmma::fragment<wmma::matrix_b, 16, 16, 16, __nv_bfloat16, wmma::row_major> bf;
                wmma::load_matrix_sync(bf, Vs + (kk * 16) * 72 + j * 16, 72);
                wmma::mma_sync(acc[j], af, bf, acc[j]);
            }
        }
        #pragma unroll
        for (int j = 0; j < 4; j++)
            wmma::store_matrix_sync(Sf + m * 68 + j * 16, acc[j], 68, wmma::mem_row_major);
    }
    __syncthreads();

    int wh = w >> 6, ww = (w >> 3) & 7, wd = w & 7;
    int base_s = wh * 4096 + ww * 128 + wd * 4;
    int chb = n * 256 + head * 64;
    float s_acc = 0.f, ss_acc = 0.f;
    #pragma unroll
    for (int it = 0; it < 8; it++) {
        int idx = tid + it * 128;
        int d = idx >> 4, tg = idx & 15;
        int i_ = tg >> 2, j_ = tg & 3;
        int s = base_s + i_ * 1024 + j_ * 32;
        int t0 = tg * 4;
        size_t g = ((size_t)(chb + d)) * SV + s;
        float4 xv = *reinterpret_cast<const float4*>(x + g);
        float4 ov;
        ov.x = fmaf(Sf[(t0 + 0) * 68 + d], linv[t0 + 0], xv.x);
        ov.y = fmaf(Sf[(t0 + 1) * 68 + d], linv[t0 + 1], xv.y);
        ov.z = fmaf(Sf[(t0 + 2) * 68 + d], linv[t0 + 2], xv.z);
        ov.w = fmaf(Sf[(t0 + 3) * 68 + d], linv[t0 + 3], xv.w);
        *reinterpret_cast<float4*>(attn + g) = ov;
        float ps = ov.x + ov.y + ov.z + ov.w;
        s_acc  += ps;
        ss_acc += ov.x*ov.x + ov.y*ov.y + ov.z*ov.z + ov.w*ov.w;
        #pragma unroll
        for (int o = 8; o; o >>= 1) ps += __shfl_down_sync(0xffffffffu, ps, o);
        if ((tid & 15) == 0)
            praw[((size_t)(chb + d)) * 512 + w] = ps * (1.f / 64.f);
    }
    #pragma unroll
    for (int o = 16; o; o >>= 1) {
        s_acc  += __shfl_down_sync(0xffffffffu, s_acc, o);
        ss_acc += __shfl_down_sync(0xffffffffu, ss_acc, o);
    }
    if ((tid & 31) == 0) { rs[warp] = s_acc; rss[warp] = ss_acc; }
    __syncthreads();
    if (tid == 0) {
        size_t pi = (size_t)n * 2048 + head * 512 + w;
        part[pi * 2 + 0] = rs[0] + rs[1] + rs[2] + rs[3];
        part[pi * 2 + 1] = rss[0] + rss[1] + rss[2] + rss[3];
    }
}

// =========================================================================
// Global attention: no-max softmax, O persistent in accumulators,
// cp.async double-buffered K/V.
// =========================================================================
#define GA_SMEM 109056

__global__ void __launch_bounds__(256, 2) gattn_kernel(
    const __nv_bfloat16* __restrict__ q2T, const __nv_bfloat16* __restrict__ kvT,
    const float* __restrict__ attn,
    const float* __restrict__ A1, const float* __restrict__ D1,
    __nv_bfloat16* __restrict__ ghi, __nv_bfloat16* __restrict__ glo) {
    extern __shared__ __align__(16) char sm[];
    __nv_bfloat16* Qs = (__nv_bfloat16*)sm;
    __nv_bfloat16* Ks = Qs + 128 * 72;
    __nv_bfloat16* Vs = Ks + 2 * 64 * 72;
    __nv_bfloat16* Ps = Vs + 2 * 64 * 72;
    float* Sf   = (float*)(Ps + 128 * 72);
    float* lrow = Sf + 128 * 68;

    int tid = threadIdx.x, warp = tid >> 5;
    int h = blockIdx.y, n = blockIdx.z;
    int s0 = blockIdx.x * 128;

    const uint4* Qg = (const uint4*)(q2T + ((size_t)(n * 4 + h) * SV + s0) * 64);
    const __nv_bfloat16* Kg = kvT + ((size_t)(n * 8 + h) * 512) * 64;
    const __nv_bfloat16* Vg = kvT + ((size_t)(n * 8 + 4 + h) * 512) * 64;

    auto prefetchKV = [&](int ch, int b) {
        #pragma unroll
        for (int i = 0; i < 2; i++) {
            int idx = tid + i * 256;
            int r = idx >> 3, c = (idx & 7) * 8;
            cp16(Ks + b * 4608 + r * 72 + c, Kg + (size_t)(ch * 64 + r) * 64 + c);
            cp16(Vs + b * 4608 + r * 72 + c, Vg + (size_t)(ch * 64 + r) * 64 + c);
        }
    };

    prefetchKV(0, 0); CP_COMMIT;

    #pragma unroll
    for (int i = 0; i < 4; i++) {
        int idx = tid + i * 256;
        int r = idx >> 3, c = idx & 7;
        ((uint4*)(Qs + r * 72))[c] = Qg[r * 8 + c];
    }
    if (tid < 128) lrow[tid] = 0.f;

    int pm = warp >> 1, pn = warp & 1;
    wmma::fragment<wmma::accumulator, 16, 16, 16, float> acc_o[2][2];
    #pragma unroll
    for (int i = 0; i < 2; i++)
        #pragma unroll
        for (int j = 0; j < 2; j++) wmma::fill_fragment(acc_o[i][j], 0.f);

    for (int ch = 0; ch < 8; ch++) {
        int b = ch & 1;
        CP_WAIT0;
        __syncthreads();

        {
            int m = warp * 16;
            wmma::fragment<wmma::accumulator, 16, 16, 16, float> acc[4];
            #pragma unroll
            for (int j = 0; j < 4; j++) wmma::fill_fragment(acc[j], 0.f);
            #pragma unroll
            for (int kd = 0; kd < 4; kd++) {
                wmma::fragment<wmma::matrix_a, 16, 16, 16, __nv_bfloat16, wmma::row_major> af;
                wmma::load_matrix_sync(af, Qs + m * 72 + kd * 16, 72);
                #pragma unroll
                for (int j = 0; j < 4; j++) {
                    wmma::fragment<wmma::matrix_b, 16, 16, 16, __nv_bfloat16, wmma::col_major> bf;
                    wmma::load_matrix_sync(bf, Ks + b * 4608 + (j * 16) * 72 + kd * 16, 72);
                    wmma::mma_sync(acc[j], af, bf, acc[j]);
                }
            }
            #pragma unroll
            for (int j = 0; j < 4; j++)
                wmma::store_matrix_sync(Sf + m * 68 + j * 16, acc[j], 68, wmma::mem_row_major);
        }
        __syncthreads();

        {
            int r = tid >> 1, hf = tid & 1;
            const float* srow = Sf + r * 68 + hf * 32;
            float ls = 0.f;
            __nv_bfloat16* prow = Ps + r * 72 + hf * 32;
            #pragma unroll
            for (int j = 0; j < 32; j++) {
                float p = __expf(srow[j]);
                ls += p;
                prow[j] = __float2bfloat16(p);
            }
            ls += __shfl_xor_sync(0xffffffffu, ls, 1);
            if (hf == 0) lrow[r] += ls;
        }
        __syncthreads();

        if (ch + 1 < 8) {
            prefetchKV(ch + 1, b ^ 1);
            CP_COMMIT;
        }

        {
            #pragma unroll
            for (int kk = 0; kk < 4; kk++) {
                wmma::fragment<wmma::matrix_a, 16, 16, 16, __nv_bfloat16, wmma::row_major> af[2];
                #pragma unroll
                for (int i = 0; i < 2; i++)
                    wmma::load_matrix_sync(af[i], Ps + (pm * 32 + i * 16) * 72 + kk * 16, 72);
                wmma::fragment<wmma::matrix_b, 16, 16, 16, __nv_bfloat16, wmma::row_major> bf[2];
                #pragma unroll
                for (int j = 0; j < 2; j++)
                    wmma::load_matrix_sync(bf[j], Vs + b * 4608 + (kk * 16) * 72 + pn * 32 + j * 16, 72);
                #pragma unroll
                for (int i = 0; i < 2; i++)
                    #pragma unroll
                    for (int j = 0; j < 2; j++)
                        wmma::mma_sync(acc_o[i][j], af[i], bf[j], acc_o[i][j]);
            }
        }
    }

    __syncthreads();
    #pragma unroll
    for (int i = 0; i < 2; i++)
        #pragma unroll
        for (int j = 0; j < 2; j++)
            wmma::store_matrix_sync(Sf + (pm * 32 + i * 16) * 68 + pn * 32 + j * 16,
                                    acc_o[i][j], 68, wmma::mem_row_major);
    __syncthreads();

    #pragma unroll
    for (int i = 0; i < 32; i++) {
        int idx = tid + i * 256;
        int r = idx & 127, d = idx >> 7;
        int cch = n * 256 + h * 64 + d;
        float v = Sf[r * 68 + d] / lrow[r];
        size_t gi = ((size_t)cch) * SV + s0 + r;
        float t = v + fmaf(A1[cch], attn[gi], D1[cch]);
        __nv_bfloat16 hi = __float2bfloat16(t);
        ghi[gi] = hi;
        glo[gi] = __float2bfloat16(t - __bfloat162float(hi));
    }
}

// =========================================================================
// host launch
// =========================================================================
extern "C" void kernel_launch(void* const* d_in, const int* in_sizes, int n_in,
                              void* d_out, int out_size) {
    const float* x      = (const float*)d_in[0];
    const float* qkv_w  = (const float*)d_in[1];
    const float* qkv_b  = (const float*)d_in[2];
    const float* norm_w = (const float*)d_in[3];
    const float* norm_b = (const float*)d_in[4];
    const float* anorm_w= (const float*)d_in[5];
    const float* anorm_b= (const float*)d_in[6];
    const float* dnorm_w= (const float*)d_in[7];
    const float* dnorm_b= (const float*)d_in[8];
    const float* q_w    = (const float*)d_in[9];
    const float* q_b    = (const float*)d_in[10];
    const float* kv_w   = (const float*)d_in[11];
    const float* kv_b   = (const float*)d_in[12];
    const float* proj_w = (const float*)d_in[13];
    const float* proj_b = (const float*)d_in[14];
    float* out = (float*)d_out;

    float *attn, *praw, *pnorm, *part, *part2, *aff, *qkvb2, *qb2;
    __nv_bfloat16 *xB, *qkvB, *attnB, *ghi, *glo, *pooledB, *q2T, *kvT;
    __nv_bfloat16 *Wqkv2B, *Wq2B, *WkvB, *WprojB;
    cudaGetSymbolAddress((void**)&attn,    g_attn);
    cudaGetSymbolAddress((void**)&praw,    g_praw);
    cudaGetSymbolAddress((void**)&pnorm,   g_pnorm);
    cudaGetSymbolAddress((void**)&xB,      g_xB);
    cudaGetSymbolAddress((void**)&qkvB,    g_qkvB);
    cudaGetSymbolAddress((void**)&attnB,   g_attnB);
    cudaGetSymbolAddress((void**)&ghi,     g_ghi);
    cudaGetSymbolAddress((void**)&glo,     g_glo);
    cudaGetSymbolAddress((void**)&pooledB, g_pooledB);
    cudaGetSymbolAddress((void**)&q2T,     g_q2T);
    cudaGetSymbolAddress((void**)&kvT,     g_kvT);
    cudaGetSymbolAddress((void**)&Wqkv2B,  g_Wqkv2B);
    cudaGetSymbolAddress((void**)&Wq2B,    g_Wq2B);
    cudaGetSymbolAddress((void**)&WkvB,    g_WkvB);
    cudaGetSymbolAddress((void**)&WprojB,  g_WprojB);
    cudaGetSymbolAddress((void**)&qkvb2,   g_qkvb2);
    cudaGetSymbolAddress((void**)&qb2,     g_qb2);
    cudaGetSymbolAddress((void**)&part,    g_part);
    cudaGetSymbolAddress((void**)&part2,   g_part2);
    cudaGetSymbolAddress((void**)&aff,     g_aff);

    static cudaStream_t s1 = nullptr;
    static cudaEvent_t ev0, evS1a, evA, evB, evA1, evKV;
    static bool init_done = false;
    if (!init_done) {
        cudaFuncSetAttribute(gattn_kernel, cudaFuncAttributeMaxDynamicSharedMemorySize, GA_SMEM);
        cudaFuncSetAttribute(wgemm3_kernel<0>, cudaFuncAttributeMaxDynamicSharedMemorySize, WG_SMEM);
        cudaFuncSetAttribute(wgemm3_kernel<1>, cudaFuncAttributeMaxDynamicSharedMemorySize, WG_SMEM);
        cudaFuncSetAttribute(wgemm3_kernel<2>, cudaFuncAttributeMaxDynamicSharedMemorySize, WG_SMEM);
        cudaStreamCreateWithFlags(&s1, cudaStreamNonBlocking);
        cudaEventCreateWithFlags(&ev0,  cudaEventDisableTiming);
        cudaEventCreateWithFlags(&evS1a, cudaEventDisableTiming);
        cudaEventCreateWithFlags(&evA,  cudaEventDisableTiming);
        cudaEventCreateWithFlags(&evB,  cudaEventDisableTiming);
        cudaEventCreateWithFlags(&evA1, cudaEventDisableTiming);
        cudaEventCreateWithFlags(&evKV, cudaEventDisableTiming);
        init_done = true;
    }

    float* A0 = aff;        float* D0 = aff + 512;
    float* A1 = aff + 1024; float* D1 = aff + 1536;
    float* A2 = aff + 2048; float* D2 = aff + 2560;

    // ---- fork: side = kv/proj weight convert; main = fused stats + xB ----
    cudaEventRecord(ev0, 0);
    cudaStreamWaitEvent(s1, ev0, 0);
    convert_weights_kernel<<<1280, 256, 0, s1>>>(kv_w, proj_w, WkvB, WprojB);
    cudaEventRecord(evS1a, s1);

    // fused: stats partials over x AND xB = bf16(x) in one pass
    reduce1x_kernel<<<dim3(512, NB), 256>>>(x, 256L * SV / 4, part, xB);
    stats2affine_kernel<<<NB, 256>>>(part, 512, norm_w, norm_b, A0, D0, 1.f / (256.f * 32768.f));
    fold_kernel<<<dim3(768, NB), 256>>>(qkv_w, qkv_b, A0, D0, Wqkv2B, qkvb2, 768);

    cudaStreamWaitEvent(0, evS1a, 0);

    // qkv conv (folded per-batch weights) -> window-gathered bf16 (q * 1/16)
    wgemm3_kernel<2><<<dim3(6, 256, NB), 256, WG_SMEM>>>(
        Wqkv2B, xB, xB, qkvb2, nullptr, qkvB, 768, (int)SV, 256, SCALE_INV,
        768L * 256, 768);

    // local attention: attn(raw) + pooled sums + gn partials
    local_attn_w_kernel<<<dim3(512, NH, NB), 128>>>(qkvB, x, attn, praw, part);

    // ---- fork: side = attnB plain convert, then pooled/kv chain after A1 ----
    cudaEventRecord(evA, 0);
    cudaStreamWaitEvent(s1, evA, 0);
    convert_plain_kernel<<<8192, 256, 0, s1>>>(attn, attnB);
    cudaEventRecord(evB, s1);

    // main: anorm affine + fold q weights
    stats2affine_kernel<<<NB, 256>>>(part, 2048, anorm_w, anorm_b, A1, D1, 1.f / (256.f * 32768.f));
    cudaEventRecord(evA1, 0);
    fold_kernel<<<dim3(256, NB), 256>>>(q_w, q_b, A1, D1, Wq2B, qb2, 256);

    // side: pooled chain (needs A1) -> kv gemm
    cudaStreamWaitEvent(s1, evA1, 0);
    apply_pool_affine_kernel<<<256, 256, 0, s1>>>(praw, A1, D1, pnorm);
    reduce1_kernel<<<dim3(32, NB), 256, 0, s1>>>(pnorm, 256L * 512 / 4, part2);
    stats2affine_kernel<<<NB, 256, 0, s1>>>(part2, 32, dnorm_w, dnorm_b, A2, D2, 1.f / (256.f * 512.f));
    convert_pooled_kernel<<<256, 256, 0, s1>>>(pnorm, A2, D2, pooledB);
    wgemm3_kernel<1><<<dim3(4, 4, NB), 256, WG_SMEM, s1>>>(
        WkvB, pooledB, pooledB, kv_b, nullptr, kvT, 512, 512, 256, 1.f, 0, 0);
    cudaEventRecord(evKV, s1);

    // main: q gemm (folded weights on raw attnB) -> q2T (scaled 1/16)
    cudaStreamWaitEvent(0, evB, 0);
    wgemm3_kernel<1><<<dim3(2, 256, NB), 256, WG_SMEM>>>(
        Wq2B, attnB, attnB, qb2, nullptr, q2T, 256, (int)SV, 256, SCALE_INV,
        256L * 256, 256);

    cudaStreamWaitEvent(0, evKV, 0);

    // global attention + affine residual -> bf16 hi/lo
    gattn_kernel<<<dim3(256, NH, NB), 256, GA_SMEM>>>(q2T, kvT, attn, A1, D1, ghi, glo);

    // final projection (3-term bf16 split) -> out
    wgemm3_kernel<0><<<dim3(2, 256, NB), 256, WG_SMEM>>>(
        WprojB, ghi, glo, proj_b, out, nullptr, 256, (int)SV, 768, 1.f, 0, 0);
}